// round 6
// baseline (speedup 1.0000x reference)
#include <cuda_runtime.h>
#include <cuda_bf16.h>
#include <cuda_fp16.h>

typedef unsigned long long u64;
typedef unsigned int u32;

#define NPTS   65536
#define CCH    64
#define NSMP   16
#define CSW    8
#define EPSV   1e-5f
#define NBW    4   // points (warps) per block in fused kernel

// ---------------- f32x2 helpers ----------------
__device__ __forceinline__ u64 pk2(float a, float b) {
    u64 r; asm("mov.b64 %0, {%1, %2};" : "=l"(r) : "f"(a), "f"(b)); return r;
}
__device__ __forceinline__ void upk2(u64 v, float& a, float& b) {
    asm("mov.b64 {%0, %1}, %2;" : "=f"(a), "=f"(b) : "l"(v));
}
__device__ __forceinline__ u64 ffma2(u64 a, u64 b, u64 c) {
    u64 d; asm("fma.rn.f32x2 %0, %1, %2, %3;" : "=l"(d) : "l"(a), "l"(b), "l"(c)); return d;
}
__device__ __forceinline__ u64 fadd2(u64 a, u64 b) {
    u64 d; asm("add.rn.f32x2 %0, %1, %2;" : "=l"(d) : "l"(a), "l"(b)); return d;
}
__device__ __forceinline__ u64 neg2(u64 v) { return v ^ 0x8000000080000000ULL; }
__device__ __forceinline__ u32 f22h(float a, float b) {
    __half2 h = __floats2half2_rn(a, b);
    return *reinterpret_cast<u32*>(&h);
}
__device__ __forceinline__ u32 smem_u32(const void* p) {
    return (u32)__cvta_generic_to_shared(p);
}

// ---------------- scratch tables (L2-resident: 3 x 16MB) ----------------
__device__ float g_xq[NPTS * CCH];
__device__ float g_xk[NPTS * CCH];
__device__ float g_xv[NPTS * CCH];

// =====================================================================
// Kernel 1: xq/xk/xv = x @ W^T + b
// 256 thr; thread = (tx 0..7 -> 8 cols, ty 0..31 -> 2 rows).
// x stored duplicated {v,v} in smem -> no MOV dups; col-pair packed acc.
// =====================================================================
__global__ __launch_bounds__(256) void gemm_qkv(
    const float* __restrict__ x,
    const float* __restrict__ Wq, const float* __restrict__ bq,
    const float* __restrict__ Wk, const float* __restrict__ bk,
    const float* __restrict__ Wv, const float* __restrict__ bv)
{
    __shared__ __align__(16) float2 sXd[64][64];  // {v,v} ; sXd[k][r]
    __shared__ __align__(16) float  sW[64][64];   // sW[k][j] = W[j][k]
    __shared__ float sB[64];

    const int tid = threadIdx.x;
    const int mat = blockIdx.y;
    const float* W = (mat == 0) ? Wq : (mat == 1) ? Wk : Wv;
    const float* B = (mat == 0) ? bq : (mat == 1) ? bk : bv;
    float* outp    = (mat == 0) ? g_xq : (mat == 1) ? g_xk : g_xv;
    const int row0 = blockIdx.x * 64;

    const int r  = tid & 63;
    const int kb = (tid >> 6) << 4;
    #pragma unroll
    for (int e = 0; e < 4; ++e) {
        float4 vx = *(const float4*)&x[(row0 + r) * 64 + kb + 4 * e];
        sXd[kb + 4 * e + 0][r] = make_float2(vx.x, vx.x);
        sXd[kb + 4 * e + 1][r] = make_float2(vx.y, vx.y);
        sXd[kb + 4 * e + 2][r] = make_float2(vx.z, vx.z);
        sXd[kb + 4 * e + 3][r] = make_float2(vx.w, vx.w);
        float4 vw = *(const float4*)&W[r * 64 + kb + 4 * e];
        sW[kb + 4 * e + 0][r] = vw.x; sW[kb + 4 * e + 1][r] = vw.y;
        sW[kb + 4 * e + 2][r] = vw.z; sW[kb + 4 * e + 3][r] = vw.w;
    }
    if (tid < 64) sB[tid] = B[tid];
    __syncthreads();

    const int tx = tid & 7;    // cols 8*tx .. 8*tx+7
    const int ty = tid >> 3;   // rows 2*ty, 2*ty+1
    const int c0 = 8 * tx;
    const int r0 = 2 * ty;

    u64 acc[2][4];
    #pragma unroll
    for (int cp = 0; cp < 4; ++cp) {
        u64 bp = *(const u64*)&sB[c0 + 2 * cp];
        acc[0][cp] = bp; acc[1][cp] = bp;
    }

    #pragma unroll
    for (int k = 0; k < 64; ++k) {
        ulonglong2 ad = *(const ulonglong2*)&sXd[k][r0];   // {a0,a0},{a1,a1}
        ulonglong2 b01 = *(const ulonglong2*)&sW[k][c0];
        ulonglong2 b23 = *(const ulonglong2*)&sW[k][c0 + 4];
        acc[0][0] = ffma2(ad.x, b01.x, acc[0][0]);
        acc[0][1] = ffma2(ad.x, b01.y, acc[0][1]);
        acc[0][2] = ffma2(ad.x, b23.x, acc[0][2]);
        acc[0][3] = ffma2(ad.x, b23.y, acc[0][3]);
        acc[1][0] = ffma2(ad.y, b01.x, acc[1][0]);
        acc[1][1] = ffma2(ad.y, b01.y, acc[1][1]);
        acc[1][2] = ffma2(ad.y, b23.x, acc[1][2]);
        acc[1][3] = ffma2(ad.y, b23.y, acc[1][3]);
    }

    #pragma unroll
    for (int rr = 0; rr < 2; ++rr) {
        const int row = row0 + r0 + rr;
        *(ulonglong2*)&outp[row * 64 + c0]     = make_ulonglong2(acc[rr][0], acc[rr][1]);
        *(ulonglong2*)&outp[row * 64 + c0 + 4] = make_ulonglong2(acc[rr][2], acc[rr][3]);
    }
}

// =====================================================================
// Kernel 2: fused point-transformer. One warp per point.
// All per-lane constants precomputed ONCE per block into smem.
// =====================================================================
__global__ void __launch_bounds__(128, 8) fused_pt(
    const float* __restrict__ p,   const int*   __restrict__ idx,
    const float* __restrict__ Wp1, const float* __restrict__ bp1,
    const float* __restrict__ pg,  const float* __restrict__ pb,
    const float* __restrict__ pm,  const float* __restrict__ pv,
    const float* __restrict__ Wp2, const float* __restrict__ bp2,
    const float* __restrict__ wg1, const float* __restrict__ wb1,
    const float* __restrict__ wm1, const float* __restrict__ wv1,
    const float* __restrict__ Ww1, const float* __restrict__ bw1,
    const float* __restrict__ wg2, const float* __restrict__ wb2,
    const float* __restrict__ wm2, const float* __restrict__ wv2,
    const float* __restrict__ Ww2, const float* __restrict__ bw2,
    float* __restrict__ out)
{
    __shared__ float  sWp1[9], sbp1v[3], spa[3], spbv[3];
    // block-constant packed tables
    __shared__ __align__(16) u64    sQC[16][8];   // per q: wpA0,wpA1,wpA2,bpA,wpB0,wpB1,wpB2,bpB
    __shared__ __align__(16) float  sA1f[64], sB1f[64];  // folded BN1 per channel
    __shared__ __align__(16) u32    sBf[32][8];   // Ww1 fp16 B-fragments per lane
    __shared__ __align__(16) float4 sM0[32], sM1[32];    // BN2/bias meta per lane
    __shared__ u32    sBW2[32];                   // Ww2 fp16 frag per lane
    // per-warp (per point)
    __shared__ __align__(16) __half  ssw16[NBW][16][72];  // w[k][c] fp16
    __shared__ __align__(16) float4  stv4 [NBW][16];      // {t0,t1,t2,bits(j)}
    __shared__ __align__(16) float   swl  [NBW][16][8];   // softmax weights

    const int tid = threadIdx.x;

    // ---- one-shot block constant build ----
    if (tid < 9) sWp1[tid] = Wp1[tid];
    if (tid < 3) {
        sbp1v[tid] = bp1[tid];
        float a = pg[tid] * rsqrtf(pv[tid] + EPSV);
        spa[tid] = a; spbv[tid] = pb[tid] - pm[tid] * a;
    }
    {   // sQC: 128 slots
        const int qq = tid >> 3, e = tid & 7;
        u64 v;
        if (e < 3)       v = pk2(Wp2[(4*qq+0)*3 + e], Wp2[(4*qq+1)*3 + e]);
        else if (e == 3) v = pk2(bp2[4*qq],           bp2[4*qq+1]);
        else if (e < 7)  v = pk2(Wp2[(4*qq+2)*3 + (e-4)], Wp2[(4*qq+3)*3 + (e-4)]);
        else             v = pk2(bp2[4*qq+2],         bp2[4*qq+3]);
        sQC[qq][e] = v;
    }
    if (tid < 64) {
        float a = wg1[tid] * rsqrtf(wv1[tid] + EPSV);
        sA1f[tid] = a;
        sB1f[tid] = wb1[tid] - wm1[tid] * a;
    }
    {   // sBf: 256 slots
        for (int i = tid; i < 256; i += 128) {
            const int ln = i >> 3, e = i & 7, ch = e >> 1, rr = e & 1;
            const int nfr = ln >> 2, kfr = 2 * (ln & 3);
            const float* wr = &Ww1[nfr * 64 + ch * 16 + kfr + rr * 8];
            sBf[ln][e] = f22h(wr[0], wr[1]);
        }
    }
    if (tid < 32) {
        const int nfr = tid >> 2, kfr = 2 * (tid & 3);
        float tA = wg2[kfr]     * rsqrtf(wv2[kfr]     + EPSV);
        float tB = wg2[kfr + 1] * rsqrtf(wv2[kfr + 1] + EPSV);
        sM0[tid] = make_float4(bw1[kfr], bw1[kfr + 1], tA, tB);
        sM1[tid] = make_float4(wb2[kfr]     - wm2[kfr]     * tA,
                               wb2[kfr + 1] - wm2[kfr + 1] * tB,
                               bw2[kfr], bw2[kfr + 1]);
        sBW2[tid] = f22h(Ww2[nfr * 8 + kfr], Ww2[nfr * 8 + kfr + 1]);
    }
    __syncthreads();

    const int w    = tid >> 5;
    const int lane = tid & 31;
    const int n    = blockIdx.x * NBW + w;
    const int q    = lane & 15;
    const int sub  = lane >> 4;
    const int c0   = 4 * q;

    // ---- Phase 0: neighbor t values + index ----
    if (lane < 16) {
        int j = idx[n * 16 + lane];
        float pnx = p[n * 3 + 0], pny = p[n * 3 + 1], pnz = p[n * 3 + 2];
        float prx = p[j * 3 + 0] - pnx;
        float pry = p[j * 3 + 1] - pny;
        float prz = p[j * 3 + 2] - pnz;
        float u0 = prx * sWp1[0] + pry * sWp1[1] + prz * sWp1[2] + sbp1v[0];
        float u1 = prx * sWp1[3] + pry * sWp1[4] + prz * sWp1[5] + sbp1v[1];
        float u2 = prx * sWp1[6] + pry * sWp1[7] + prz * sWp1[8] + sbp1v[2];
        float t0 = fmaxf(0.f, fmaf(u0, spa[0], spbv[0]));
        float t1 = fmaxf(0.f, fmaf(u1, spa[1], spbv[1]));
        float t2 = fmaxf(0.f, fmaf(u2, spa[2], spbv[2]));
        stv4[w][lane] = make_float4(t0, t1, t2, __int_as_float(j));
    }
    __syncwarp();

    // ---- Phase A: gather xk, relation + pos-enc -> ssw16 (fp16) ----
    {
        ulonglong2 qcA  = *(const ulonglong2*)&sQC[q][0];  // wpA0, wpA1
        ulonglong2 qcA2 = *(const ulonglong2*)&sQC[q][2];  // wpA2, bpA
        ulonglong2 qcB  = *(const ulonglong2*)&sQC[q][4];  // wpB0, wpB1
        ulonglong2 qcB2 = *(const ulonglong2*)&sQC[q][6];  // wpB2, bpB
        float4 a1v = *(const float4*)&sA1f[c0];
        float4 b1v = *(const float4*)&sB1f[c0];
        const u64 nxqA = neg2(*(const u64*)&g_xq[n * 64 + c0]);
        const u64 nxqB = neg2(*(const u64*)&g_xq[n * 64 + c0 + 2]);

        #pragma unroll
        for (int it = 0; it < 8; ++it) {
            const int kk = 2 * it + sub;
            float4 tv = stv4[w][kk];
            int j = __float_as_int(tv.w);
            u64 t0d = pk2(tv.x, tv.x), t1d = pk2(tv.y, tv.y), t2d = pk2(tv.z, tv.z);
            ulonglong2 xkp = *(const ulonglong2*)&g_xk[j * 64 + c0];  // LDG.128
            u64 peA = ffma2(qcA.x, t0d, ffma2(qcA.y, t1d, ffma2(qcA2.x, t2d, qcA2.y)));
            u64 peB = ffma2(qcB.x, t0d, ffma2(qcB.y, t1d, ffma2(qcB2.x, t2d, qcB2.y)));
            u64 rA  = fadd2(fadd2(xkp.x, nxqA), peA);
            u64 rB  = fadd2(fadd2(xkp.y, nxqB), peB);
            float r0, r1, r2, r3;
            upk2(rA, r0, r1); upk2(rB, r2, r3);
            float w0  = fmaxf(0.f, fmaf(r0, a1v.x, b1v.x));
            float w1  = fmaxf(0.f, fmaf(r1, a1v.y, b1v.y));
            float w2_ = fmaxf(0.f, fmaf(r2, a1v.z, b1v.z));
            float w3  = fmaxf(0.f, fmaf(r3, a1v.w, b1v.w));
            u32 hlo = f22h(w0, w1), hhi = f22h(w2_, w3);
            *(u64*)&ssw16[w][kk][c0] = (u64)hlo | ((u64)hhi << 32);  // STS.64
        }
    }
    __syncwarp();

    // ---- Phase B: mma (w @ Ww1^T) -> bn2/relu -> mma (Ww2) -> softmax ----
    {
        const int nfr = lane >> 2;       // 0..7
        const int kfr = 2 * (lane & 3);  // 0,2,4,6

        uint4 bfa = *(const uint4*)&sBf[lane][0];
        uint4 bfb = *(const uint4*)&sBf[lane][4];
        u32 bfr[8] = {bfa.x, bfa.y, bfa.z, bfa.w, bfb.x, bfb.y, bfb.z, bfb.w};
        float4 m0 = sM0[lane];   // {cbw1A, cbw1B, ca2A, ca2B}
        float4 m1 = sM1[lane];   // {cb2A, cb2B, cbw2A, cbw2B}
        u32 bW2f = sBW2[lane];

        u32 afr[4][4];
        const int arow = lane & 15;
        const int acol = (lane >> 4) << 3;
        #pragma unroll
        for (int ch = 0; ch < 4; ++ch) {
            u32 ad = smem_u32(&ssw16[w][arow][ch * 16 + acol]);
            asm volatile("ldmatrix.sync.aligned.m8n8.x4.shared.b16 {%0,%1,%2,%3}, [%4];"
                : "=r"(afr[ch][0]), "=r"(afr[ch][1]), "=r"(afr[ch][2]), "=r"(afr[ch][3])
                : "r"(ad));
        }
        float d0 = 0.f, d1 = 0.f, d2 = 0.f, d3 = 0.f;
        #pragma unroll
        for (int ch = 0; ch < 4; ++ch) {
            asm volatile("mma.sync.aligned.m16n8k16.row.col.f32.f16.f16.f32 "
                "{%0,%1,%2,%3}, {%4,%5,%6,%7}, {%8,%9}, {%0,%1,%2,%3};"
                : "+f"(d0), "+f"(d1), "+f"(d2), "+f"(d3)
                : "r"(afr[ch][0]), "r"(afr[ch][1]), "r"(afr[ch][2]), "r"(afr[ch][3]),
                  "r"(bfr[2 * ch]), "r"(bfr[2 * ch + 1]));
        }
        float h0 = fmaxf(0.f, fmaf(d0 + m0.x, m0.z, m1.x));
        float h1 = fmaxf(0.f, fmaf(d1 + m0.y, m0.w, m1.y));
        float h2 = fmaxf(0.f, fmaf(d2 + m0.x, m0.z, m1.x));
        float h3 = fmaxf(0.f, fmaf(d3 + m0.y, m0.w, m1.y));
        u32 ha0 = f22h(h0, h1), ha1 = f22h(h2, h3);
        float l0 = 0.f, l1 = 0.f, l2 = 0.f, l3 = 0.f;
        asm volatile("mma.sync.aligned.m16n8k8.row.col.f32.f16.f16.f32 "
            "{%0,%1,%2,%3}, {%4,%5}, {%6}, {%0,%1,%2,%3};"
            : "+f"(l0), "+f"(l1), "+f"(l2), "+f"(l3)
            : "r"(ha0), "r"(ha1), "r"(bW2f));
        l0 += m1.z; l1 += m1.w; l2 += m1.z; l3 += m1.w;

        float mA = fmaxf(l0, l2), mB = fmaxf(l1, l3);
        #pragma unroll
        for (int dlt = 4; dlt <= 16; dlt <<= 1) {
            mA = fmaxf(mA, __shfl_xor_sync(0xffffffffu, mA, dlt));
            mB = fmaxf(mB, __shfl_xor_sync(0xffffffffu, mB, dlt));
        }
        float e0 = __expf(l0 - mA), e1 = __expf(l1 - mB);
        float e2 = __expf(l2 - mA), e3 = __expf(l3 - mB);
        float sA = e0 + e2, sB = e1 + e3;
        #pragma unroll
        for (int dlt = 4; dlt <= 16; dlt <<= 1) {
            sA += __shfl_xor_sync(0xffffffffu, sA, dlt);
            sB += __shfl_xor_sync(0xffffffffu, sB, dlt);
        }
        float iA = 1.f / sA, iB = 1.f / sB;
        *(u64*)&swl[w][nfr][kfr]     = pk2(e0 * iA, e1 * iB);
        *(u64*)&swl[w][nfr + 8][kfr] = pk2(e2 * iA, e3 * iB);
    }
    __syncwarp();

    // ---- Phase C: re-gather xv, recompute pe, weighted sum ----
    {
        ulonglong2 qcA  = *(const ulonglong2*)&sQC[q][0];
        ulonglong2 qcA2 = *(const ulonglong2*)&sQC[q][2];
        ulonglong2 qcB  = *(const ulonglong2*)&sQC[q][4];
        ulonglong2 qcB2 = *(const ulonglong2*)&sQC[q][6];
        const int csq = c0 & 7;   // 0 or 4

        u64 acc0 = 0ull, acc1 = 0ull;
        #pragma unroll
        for (int it = 0; it < 8; ++it) {
            const int kk = 2 * it + sub;
            float4 tv = stv4[w][kk];
            int j = __float_as_int(tv.w);
            u64 t0d = pk2(tv.x, tv.x), t1d = pk2(tv.y, tv.y), t2d = pk2(tv.z, tv.z);
            ulonglong2 xvp = *(const ulonglong2*)&g_xv[j * 64 + c0];  // LDG.128
            u64 peA = ffma2(qcA.x, t0d, ffma2(qcA.y, t1d, ffma2(qcA2.x, t2d, qcA2.y)));
            u64 peB = ffma2(qcB.x, t0d, ffma2(qcB.y, t1d, ffma2(qcB2.x, t2d, qcB2.y)));
            ulonglong2 g2 = *(const ulonglong2*)&swl[w][kk][csq];     // LDS.128
            acc0 = ffma2(fadd2(xvp.x, peA), g2.x, acc0);
            acc1 = ffma2(fadd2(xvp.y, peB), g2.y, acc1);
        }
        float o0, o1, o2, o3;
        upk2(acc0, o0, o1); upk2(acc1, o2, o3);
        o0 += __shfl_xor_sync(0xffffffffu, o0, 16);
        o1 += __shfl_xor_sync(0xffffffffu, o1, 16);
        o2 += __shfl_xor_sync(0xffffffffu, o2, 16);
        o3 += __shfl_xor_sync(0xffffffffu, o3, 16);
        if (sub == 0)
            *(float4*)&out[n * 64 + c0] = make_float4(o0, o1, o2, o3);
    }
}

// =====================================================================
extern "C" void kernel_launch(void* const* d_in, const int* in_sizes, int n_in,
                              void* d_out, int out_size)
{
    const float* p   = (const float*)d_in[0];
    const float* x   = (const float*)d_in[1];
    const int*   idx = (const int*)  d_in[2];
    const float* Wq  = (const float*)d_in[3];
    const float* bq  = (const float*)d_in[4];
    const float* Wk  = (const float*)d_in[5];
    const float* bk  = (const float*)d_in[6];
    const float* Wv  = (const float*)d_in[7];
    const float* bv  = (const float*)d_in[8];
    const float* Wp1 = (const float*)d_in[9];
    const float* bp1 = (const float*)d_in[10];
    const float* pg  = (const float*)d_in[11];
    const float* pb  = (const float*)d_in[12];
    const float* pm  = (const float*)d_in[13];
    const float* pv  = (const float*)d_in[14];
    const float* Wp2 = (const float*)d_in[15];
    const float* bp2 = (const float*)d_in[16];
    const float* wg1 = (const float*)d_in[17];
    const float* wb1 = (const float*)d_in[18];
    const float* wm1 = (const float*)d_in[19];
    const float* wv1 = (const float*)d_in[20];
    const float* Ww1 = (const float*)d_in[21];
    const float* bw1 = (const float*)d_in[22];
    const float* wg2 = (const float*)d_in[23];
    const float* wb2 = (const float*)d_in[24];
    const float* wm2 = (const float*)d_in[25];
    const float* wv2 = (const float*)d_in[26];
    const float* Ww2 = (const float*)d_in[27];
    const float* bw2 = (const float*)d_in[28];
    float* out = (float*)d_out;

    gemm_qkv<<<dim3(NPTS / 64, 3, 1), 256>>>(x, Wq, bq, Wk, bk, Wv, bv);
    fused_pt<<<NPTS / NBW, 128>>>(p, idx, Wp1, bp1, pg, pb, pm, pv, Wp2, bp2,
                                  wg1, wb1, wm1, wv1, Ww1, bw1,
                                  wg2, wb2, wm2, wv2, Ww2, bw2, out);
}

// round 7
// speedup vs baseline: 1.5122x; 1.5122x over previous
#include <cuda_runtime.h>
#include <cuda_bf16.h>
#include <cuda_fp16.h>

typedef unsigned long long u64;
typedef unsigned int u32;

#define NPTS   65536
#define CCH    64
#define NSMP   16
#define CSW    8
#define EPSV   1e-5f
#define NBW    4   // points (warps) per block in fused kernel

// ---------------- f32x2 helpers ----------------
__device__ __forceinline__ u64 pk2(float a, float b) {
    u64 r; asm("mov.b64 %0, {%1, %2};" : "=l"(r) : "f"(a), "f"(b)); return r;
}
__device__ __forceinline__ void upk2(u64 v, float& a, float& b) {
    asm("mov.b64 {%0, %1}, %2;" : "=f"(a), "=f"(b) : "l"(v));
}
__device__ __forceinline__ u64 ffma2(u64 a, u64 b, u64 c) {
    u64 d; asm("fma.rn.f32x2 %0, %1, %2, %3;" : "=l"(d) : "l"(a), "l"(b), "l"(c)); return d;
}
__device__ __forceinline__ u64 fadd2(u64 a, u64 b) {
    u64 d; asm("add.rn.f32x2 %0, %1, %2;" : "=l"(d) : "l"(a), "l"(b)); return d;
}
__device__ __forceinline__ u64 neg2(u64 v) { return v ^ 0x8000000080000000ULL; }
__device__ __forceinline__ u32 f22h(float a, float b) {
    __half2 h = __floats2half2_rn(a, b);
    return *reinterpret_cast<u32*>(&h);
}
__device__ __forceinline__ u32 smem_u32(const void* p) {
    return (u32)__cvta_generic_to_shared(p);
}

// ---------------- scratch tables (L2-resident: 3 x 16MB) ----------------
__device__ float g_xq[NPTS * CCH];
__device__ float g_xk[NPTS * CCH];
__device__ float g_xv[NPTS * CCH];

// =====================================================================
// Kernel 1: xq/xk/xv = x @ W^T + b   ([65536,64] x [64,64], 3 matrices)
// XOR-swizzled smem (stride 64): col' = col ^ ((k&3)<<4).
// Transpose STS conflict-free; u64/float4 loads stay aligned+conflict-free.
// =====================================================================
#define SWZ(k, c) ((c) ^ (((k) & 3) << 4))

__global__ __launch_bounds__(256) void gemm_qkv(
    const float* __restrict__ x,
    const float* __restrict__ Wq, const float* __restrict__ bq,
    const float* __restrict__ Wk, const float* __restrict__ bk,
    const float* __restrict__ Wv, const float* __restrict__ bv)
{
    __shared__ __align__(16) float sXf[64 * 64];  // sXf[k*64 + c'] = x[row0+c][k]
    __shared__ __align__(16) float sWf[64 * 64];  // sWf[k*64 + c'] = W[c][k]
    __shared__ float sB[64];

    const int tid = threadIdx.x;
    const int mat = blockIdx.y;
    const float* W = (mat == 0) ? Wq : (mat == 1) ? Wk : Wv;
    const float* B = (mat == 0) ? bq : (mat == 1) ? bk : bv;
    float* outp    = (mat == 0) ? g_xq : (mat == 1) ? g_xk : g_xv;
    const int row0 = blockIdx.x * 64;

    // transpose-load x tile and W into swizzled smem
    const int r  = tid & 63;
    const int kb = (tid >> 6) << 4;   // 0,16,32,48 (multiple of 4)
    #pragma unroll
    for (int e = 0; e < 4; ++e) {
        float4 vx = *(const float4*)&x[(row0 + r) * 64 + kb + 4 * e];
        sXf[(kb + 4 * e + 0) * 64 + (r ^ 0) ] = vx.x;
        sXf[(kb + 4 * e + 1) * 64 + (r ^ 16)] = vx.y;
        sXf[(kb + 4 * e + 2) * 64 + (r ^ 32)] = vx.z;
        sXf[(kb + 4 * e + 3) * 64 + (r ^ 48)] = vx.w;
        float4 vw = *(const float4*)&W[r * 64 + kb + 4 * e];
        sWf[(kb + 4 * e + 0) * 64 + (r ^ 0) ] = vw.x;
        sWf[(kb + 4 * e + 1) * 64 + (r ^ 16)] = vw.y;
        sWf[(kb + 4 * e + 2) * 64 + (r ^ 32)] = vw.z;
        sWf[(kb + 4 * e + 3) * 64 + (r ^ 48)] = vw.w;
    }
    if (tid < 64) sB[tid] = B[tid];
    __syncthreads();

    const int tx = tid & 15;   // col group: cols 4*tx..4*tx+3 (of W -> output cols)
    const int ty = tid >> 4;   // row group: rows 4*ty..4*ty+3  (x rows)

    u64 acc[2][4];
    #pragma unroll
    for (int c = 0; c < 4; ++c) {
        float bb = sB[4 * tx + c];
        u64 bd = pk2(bb, bb);
        acc[0][c] = bd; acc[1][c] = bd;
    }

    #pragma unroll
    for (int k = 0; k < 64; ++k) {
        u64 a0 = *(const u64*)&sXf[k * 64 + SWZ(k, 4 * ty)];       // rows 4ty,4ty+1
        u64 a1 = *(const u64*)&sXf[k * 64 + SWZ(k, 4 * ty) + 2];   // rows 4ty+2,4ty+3
        float4 b4 = *(const float4*)&sWf[k * 64 + SWZ(k, 4 * tx)];
        u64 b0 = pk2(b4.x, b4.x), b1 = pk2(b4.y, b4.y);
        u64 b2 = pk2(b4.z, b4.z), b3 = pk2(b4.w, b4.w);
        acc[0][0] = ffma2(a0, b0, acc[0][0]);  acc[1][0] = ffma2(a1, b0, acc[1][0]);
        acc[0][1] = ffma2(a0, b1, acc[0][1]);  acc[1][1] = ffma2(a1, b1, acc[1][1]);
        acc[0][2] = ffma2(a0, b2, acc[0][2]);  acc[1][2] = ffma2(a1, b2, acc[1][2]);
        acc[0][3] = ffma2(a0, b3, acc[0][3]);  acc[1][3] = ffma2(a1, b3, acc[1][3]);
    }

    #pragma unroll
    for (int rp = 0; rp < 2; ++rp) {
        float lo0, hi0, lo1, hi1, lo2, hi2, lo3, hi3;
        upk2(acc[rp][0], lo0, hi0); upk2(acc[rp][1], lo1, hi1);
        upk2(acc[rp][2], lo2, hi2); upk2(acc[rp][3], lo3, hi3);
        const int row = row0 + 4 * ty + 2 * rp;
        *(float4*)&outp[(row + 0) * 64 + 4 * tx] = make_float4(lo0, lo1, lo2, lo3);
        *(float4*)&outp[(row + 1) * 64 + 4 * tx] = make_float4(hi0, hi1, hi2, hi3);
    }
}

// =====================================================================
// Kernel 2: fused point-transformer. One warp per point. (round-5 best)
// =====================================================================
__global__ void __launch_bounds__(128, 8) fused_pt(
    const float* __restrict__ p,   const int*   __restrict__ idx,
    const float* __restrict__ Wp1, const float* __restrict__ bp1,
    const float* __restrict__ pg,  const float* __restrict__ pb,
    const float* __restrict__ pm,  const float* __restrict__ pv,
    const float* __restrict__ Wp2, const float* __restrict__ bp2,
    const float* __restrict__ wg1, const float* __restrict__ wb1,
    const float* __restrict__ wm1, const float* __restrict__ wv1,
    const float* __restrict__ Ww1, const float* __restrict__ bw1,
    const float* __restrict__ wg2, const float* __restrict__ wb2,
    const float* __restrict__ wm2, const float* __restrict__ wv2,
    const float* __restrict__ Ww2, const float* __restrict__ bw2,
    float* __restrict__ out)
{
    __shared__ float  sWp1[9], sbp1v[3], spa[3], spbv[3];
    // per-warp (per point)
    __shared__ __align__(16) __half  ssw16[NBW][16][72];  // w[k][c] fp16, row 144B
    __shared__ __align__(16) float4  stv4 [NBW][16];      // {t0,t1,t2,bits(j)}
    __shared__ __align__(16) float   swl  [NBW][16][8];   // softmax weights

    const int tid = threadIdx.x;
    if (tid < 9) sWp1[tid] = Wp1[tid];
    if (tid < 3) {
        sbp1v[tid] = bp1[tid];
        float a = pg[tid] * rsqrtf(pv[tid] + EPSV);
        spa[tid] = a; spbv[tid] = pb[tid] - pm[tid] * a;
    }
    __syncthreads();

    const int w    = tid >> 5;
    const int lane = tid & 31;
    const int n    = blockIdx.x * NBW + w;
    const int q    = lane & 15;
    const int sub  = lane >> 4;
    const int c0   = 4 * q;      // channel quad owned in phases A & C

    // ---- Phase 0: neighbor t values + index, packed per neighbor ----
    if (lane < 16) {
        int j = idx[n * 16 + lane];
        float pnx = p[n * 3 + 0], pny = p[n * 3 + 1], pnz = p[n * 3 + 2];
        float prx = p[j * 3 + 0] - pnx;
        float pry = p[j * 3 + 1] - pny;
        float prz = p[j * 3 + 2] - pnz;
        float u0 = prx * sWp1[0] + pry * sWp1[1] + prz * sWp1[2] + sbp1v[0];
        float u1 = prx * sWp1[3] + pry * sWp1[4] + prz * sWp1[5] + sbp1v[1];
        float u2 = prx * sWp1[6] + pry * sWp1[7] + prz * sWp1[8] + sbp1v[2];
        float t0 = fmaxf(0.f, fmaf(u0, spa[0], spbv[0]));
        float t1 = fmaxf(0.f, fmaf(u1, spa[1], spbv[1]));
        float t2 = fmaxf(0.f, fmaf(u2, spa[2], spbv[2]));
        stv4[w][lane] = make_float4(t0, t1, t2, __int_as_float(j));
    }
    __syncwarp();

    // ---- Phase A: gather xk (LDG.128), relation + pos-enc -> ssw16 (fp16) ----
    {
        const u64 nxqA = neg2(*(const u64*)&g_xq[n * 64 + c0]);
        const u64 nxqB = neg2(*(const u64*)&g_xq[n * 64 + c0 + 2]);
        const u64 wpA0 = pk2(Wp2[(c0+0)*3+0], Wp2[(c0+1)*3+0]);
        const u64 wpA1 = pk2(Wp2[(c0+0)*3+1], Wp2[(c0+1)*3+1]);
        const u64 wpA2 = pk2(Wp2[(c0+0)*3+2], Wp2[(c0+1)*3+2]);
        const u64 wpB0 = pk2(Wp2[(c0+2)*3+0], Wp2[(c0+3)*3+0]);
        const u64 wpB1 = pk2(Wp2[(c0+2)*3+1], Wp2[(c0+3)*3+1]);
        const u64 wpB2 = pk2(Wp2[(c0+2)*3+2], Wp2[(c0+3)*3+2]);
        const u64 bpA  = pk2(bp2[c0],     bp2[c0 + 1]);
        const u64 bpB  = pk2(bp2[c0 + 2], bp2[c0 + 3]);
        float a1v[4], b1v[4];
        #pragma unroll
        for (int e = 0; e < 4; ++e) {
            float a = wg1[c0 + e] * rsqrtf(wv1[c0 + e] + EPSV);
            a1v[e] = a; b1v[e] = wb1[c0 + e] - wm1[c0 + e] * a;
        }

        #pragma unroll
        for (int it = 0; it < 8; ++it) {
            const int kk = 2 * it + sub;
            float4 tv = stv4[w][kk];
            int j = __float_as_int(tv.w);
            u64 t0d = pk2(tv.x, tv.x), t1d = pk2(tv.y, tv.y), t2d = pk2(tv.z, tv.z);
            ulonglong2 xkp = *(const ulonglong2*)&g_xk[j * 64 + c0];  // LDG.128
            u64 peA = ffma2(wpA0, t0d, ffma2(wpA1, t1d, ffma2(wpA2, t2d, bpA)));
            u64 peB = ffma2(wpB0, t0d, ffma2(wpB1, t1d, ffma2(wpB2, t2d, bpB)));
            u64 rA  = fadd2(fadd2(xkp.x, nxqA), peA);
            u64 rB  = fadd2(fadd2(xkp.y, nxqB), peB);
            float r0, r1, r2, r3;
            upk2(rA, r0, r1); upk2(rB, r2, r3);
            float w0 = fmaxf(0.f, fmaf(r0, a1v[0], b1v[0]));
            float w1 = fmaxf(0.f, fmaf(r1, a1v[1], b1v[1]));
            float w2_ = fmaxf(0.f, fmaf(r2, a1v[2], b1v[2]));
            float w3 = fmaxf(0.f, fmaf(r3, a1v[3], b1v[3]));
            u32 hlo = f22h(w0, w1), hhi = f22h(w2_, w3);
            *(u64*)&ssw16[w][kk][c0] = (u64)hlo | ((u64)hhi << 32);  // STS.64
        }
    }
    __syncwarp();

    // ---- Phase B: mma (w @ Ww1^T) -> bn2/relu -> mma (Ww2) -> softmax ----
    {
        const int nfr = lane >> 2;       // 0..7
        const int kfr = 2 * (lane & 3);  // 0,2,4,6

        // one-shot B-fragment + constant preloads (per warp = per point)
        u32 bf[4][2];
        #pragma unroll
        for (int ch = 0; ch < 4; ++ch) {
            const float* wr = &Ww1[nfr * 64 + ch * 16 + kfr];
            bf[ch][0] = f22h(wr[0], wr[1]);
            bf[ch][1] = f22h(wr[8], wr[9]);
        }
        const u32 bW2f = f22h(Ww2[nfr * 8 + kfr], Ww2[nfr * 8 + kfr + 1]);
        const float cbw1A = bw1[kfr],     cbw1B = bw1[kfr + 1];
        float tA = wg2[kfr]     * rsqrtf(wv2[kfr]     + EPSV);
        float tB = wg2[kfr + 1] * rsqrtf(wv2[kfr + 1] + EPSV);
        const float ca2A = tA, cb2A = wb2[kfr]     - wm2[kfr]     * tA;
        const float ca2B = tB, cb2B = wb2[kfr + 1] - wm2[kfr + 1] * tB;
        const float cbw2A = bw2[kfr], cbw2B = bw2[kfr + 1];

        // ldmatrix A fragments of w (16x64 fp16)
        u32 afr[4][4];
        const int arow = lane & 15;
        const int acol = (lane >> 4) << 3;
        #pragma unroll
        for (int ch = 0; ch < 4; ++ch) {
            u32 ad = smem_u32(&ssw16[w][arow][ch * 16 + acol]);
            asm volatile("ldmatrix.sync.aligned.m8n8.x4.shared.b16 {%0,%1,%2,%3}, [%4];"
                : "=r"(afr[ch][0]), "=r"(afr[ch][1]), "=r"(afr[ch][2]), "=r"(afr[ch][3])
                : "r"(ad));
        }
        float d0 = 0.f, d1 = 0.f, d2 = 0.f, d3 = 0.f;
        #pragma unroll
        for (int ch = 0; ch < 4; ++ch) {
            asm volatile("mma.sync.aligned.m16n8k16.row.col.f32.f16.f16.f32 "
                "{%0,%1,%2,%3}, {%4,%5,%6,%7}, {%8,%9}, {%0,%1,%2,%3};"
                : "+f"(d0), "+f"(d1), "+f"(d2), "+f"(d3)
                : "r"(afr[ch][0]), "r"(afr[ch][1]), "r"(afr[ch][2]), "r"(afr[ch][3]),
                  "r"(bf[ch][0]), "r"(bf[ch][1]));
        }
        float h0 = fmaxf(0.f, fmaf(d0 + cbw1A, ca2A, cb2A));
        float h1 = fmaxf(0.f, fmaf(d1 + cbw1B, ca2B, cb2B));
        float h2 = fmaxf(0.f, fmaf(d2 + cbw1A, ca2A, cb2A));
        float h3 = fmaxf(0.f, fmaf(d3 + cbw1B, ca2B, cb2B));
        u32 ha0 = f22h(h0, h1), ha1 = f22h(h2, h3);
        float l0 = 0.f, l1 = 0.f, l2 = 0.f, l3 = 0.f;
        asm volatile("mma.sync.aligned.m16n8k8.row.col.f32.f16.f16.f32 "
            "{%0,%1,%2,%3}, {%4,%5}, {%6}, {%0,%1,%2,%3};"
            : "+f"(l0), "+f"(l1), "+f"(l2), "+f"(l3)
            : "r"(ha0), "r"(ha1), "r"(bW2f));
        l0 += cbw2A; l1 += cbw2B; l2 += cbw2A; l3 += cbw2B;

        // softmax over the 16 neighbors (rows nfr and nfr+8, spread on lane>>2)
        float mA = fmaxf(l0, l2), mB = fmaxf(l1, l3);
        #pragma unroll
        for (int dlt = 4; dlt <= 16; dlt <<= 1) {
            mA = fmaxf(mA, __shfl_xor_sync(0xffffffffu, mA, dlt));
            mB = fmaxf(mB, __shfl_xor_sync(0xffffffffu, mB, dlt));
        }
        float e0 = __expf(l0 - mA), e1 = __expf(l1 - mB);
        float e2 = __expf(l2 - mA), e3 = __expf(l3 - mB);
        float sA = e0 + e2, sB = e1 + e3;
        #pragma unroll
        for (int dlt = 4; dlt <= 16; dlt <<= 1) {
            sA += __shfl_xor_sync(0xffffffffu, sA, dlt);
            sB += __shfl_xor_sync(0xffffffffu, sB, dlt);
        }
        float iA = 1.f / sA, iB = 1.f / sB;
        *(u64*)&swl[w][nfr][kfr]     = pk2(e0 * iA, e1 * iB);
        *(u64*)&swl[w][nfr + 8][kfr] = pk2(e2 * iA, e3 * iB);
    }
    __syncwarp();

    // ---- Phase C: re-gather xv (LDG.128), recompute pe, weighted sum ----
    {
        const u64 wpA0 = pk2(Wp2[(c0+0)*3+0], Wp2[(c0+1)*3+0]);
        const u64 wpA1 = pk2(Wp2[(c0+0)*3+1], Wp2[(c0+1)*3+1]);
        const u64 wpA2 = pk2(Wp2[(c0+0)*3+2], Wp2[(c0+1)*3+2]);
        const u64 wpB0 = pk2(Wp2[(c0+2)*3+0], Wp2[(c0+3)*3+0]);
        const u64 wpB1 = pk2(Wp2[(c0+2)*3+1], Wp2[(c0+3)*3+1]);
        const u64 wpB2 = pk2(Wp2[(c0+2)*3+2], Wp2[(c0+3)*3+2]);
        const u64 bpA  = pk2(bp2[c0],     bp2[c0 + 1]);
        const u64 bpB  = pk2(bp2[c0 + 2], bp2[c0 + 3]);
        const int csq  = c0 & 7;   // 0 or 4 -> aligned 16B into swl row

        u64 acc0 = 0ull, acc1 = 0ull;
        #pragma unroll
        for (int it = 0; it < 8; ++it) {
            const int kk = 2 * it + sub;
            float4 tv = stv4[w][kk];
            int j = __float_as_int(tv.w);
            u64 t0d = pk2(tv.x, tv.x), t1d = pk2(tv.y, tv.y), t2d = pk2(tv.z, tv.z);
            ulonglong2 xvp = *(const ulonglong2*)&g_xv[j * 64 + c0];  // LDG.128
            u64 peA = ffma2(wpA0, t0d, ffma2(wpA1, t1d, ffma2(wpA2, t2d, bpA)));
            u64 peB = ffma2(wpB0, t0d, ffma2(wpB1, t1d, ffma2(wpB2, t2d, bpB)));
            ulonglong2 g2 = *(const ulonglong2*)&swl[w][kk][csq];     // LDS.128
            acc0 = ffma2(fadd2(xvp.x, peA), g2.x, acc0);
            acc1 = ffma2(fadd2(xvp.y, peB), g2.y, acc1);
        }
        float o0, o1, o2, o3;
        upk2(acc0, o0, o1); upk2(acc1, o2, o3);
        o0 += __shfl_xor_sync(0xffffffffu, o0, 16);
        o1 += __shfl_xor_sync(0xffffffffu, o1, 16);
        o2 += __shfl_xor_sync(0xffffffffu, o2, 16);
        o3 += __shfl_xor_sync(0xffffffffu, o3, 16);
        if (sub == 0)
            *(float4*)&out[n * 64 + c0] = make_float4(o0, o1, o2, o3);
    }
}

// =====================================================================
extern "C" void kernel_launch(void* const* d_in, const int* in_sizes, int n_in,
                              void* d_out, int out_size)
{
    const float* p   = (const float*)d_in[0];
    const float* x   = (const float*)d_in[1];
    const int*   idx = (const int*)  d_in[2];
    const float* Wq  = (const float*)d_in[3];
    const float* bq  = (const float*)d_in[4];
    const float* Wk  = (const float*)d_in[5];
    const float* bk  = (const float*)d_in[6];
    const float* Wv  = (const float*)d_in[7];
    const float* bv  = (const float*)d_in[8];
    const float* Wp1 = (const float*)d_in[9];
    const float* bp1 = (const float*)d_in[10];
    const float* pg  = (const float*)d_in[11];
    const float* pb  = (const float*)d_in[12];
    const float* pm  = (const float*)d_in[13];
    const float* pv  = (const float*)d_in[14];
    const float* Wp2 = (const float*)d_in[15];
    const float* bp2 = (const float*)d_in[16];
    const float* wg1 = (const float*)d_in[17];
    const float* wb1 = (const float*)d_in[18];
    const float* wm1 = (const float*)d_in[19];
    const float* wv1 = (const float*)d_in[20];
    const float* Ww1 = (const float*)d_in[21];
    const float* bw1 = (const float*)d_in[22];
    const float* wg2 = (const float*)d_in[23];
    const float* wb2 = (const float*)d_in[24];
    const float* wm2 = (const float*)d_in[25];
    const float* wv2 = (const float*)d_in[26];
    const float* Ww2 = (const float*)d_in[27];
    const float* bw2 = (const float*)d_in[28];
    float* out = (float*)d_out;

    gemm_qkv<<<dim3(NPTS / 64, 3, 1), 256>>>(x, Wq, bq, Wk, bk, Wv, bv);
    fused_pt<<<NPTS / NBW, 128>>>(p, idx, Wp1, bp1, pg, pb, pm, pv, Wp2, bp2,
                                  wg1, wb1, wm1, wv1, Ww1, bw1,
                                  wg2, wb2, wm2, wv2, Ww2, bw2, out);
}

// round 8
// speedup vs baseline: 1.5737x; 1.0407x over previous
#include <cuda_runtime.h>
#include <cuda_bf16.h>
#include <cuda_fp16.h>

typedef unsigned long long u64;
typedef unsigned int u32;

#define NPTS   65536
#define CCH    64
#define NSMP   16
#define CSW    8
#define EPSV   1e-5f
#define NBW    4   // points (warps) per block in fused kernel

// ---------------- f32x2 helpers ----------------
__device__ __forceinline__ u64 pk2(float a, float b) {
    u64 r; asm("mov.b64 %0, {%1, %2};" : "=l"(r) : "f"(a), "f"(b)); return r;
}
__device__ __forceinline__ void upk2(u64 v, float& a, float& b) {
    asm("mov.b64 {%0, %1}, %2;" : "=f"(a), "=f"(b) : "l"(v));
}
__device__ __forceinline__ u64 ffma2(u64 a, u64 b, u64 c) {
    u64 d; asm("fma.rn.f32x2 %0, %1, %2, %3;" : "=l"(d) : "l"(a), "l"(b), "l"(c)); return d;
}
__device__ __forceinline__ u64 fadd2(u64 a, u64 b) {
    u64 d; asm("add.rn.f32x2 %0, %1, %2;" : "=l"(d) : "l"(a), "l"(b)); return d;
}
__device__ __forceinline__ u64 neg2(u64 v) { return v ^ 0x8000000080000000ULL; }
__device__ __forceinline__ u32 f22h(float a, float b) {
    __half2 h = __floats2half2_rn(a, b);
    return *reinterpret_cast<u32*>(&h);
}
__device__ __forceinline__ u32 smem_u32(const void* p) {
    return (u32)__cvta_generic_to_shared(p);
}
// unpack u64 of 4 halves -> two packed f32x2
__device__ __forceinline__ void h4_to_f22(u64 h4, u64& loPair, u64& hiPair) {
    u32 lo = (u32)h4, hi = (u32)(h4 >> 32);
    __half2 hlo = *reinterpret_cast<__half2*>(&lo);
    __half2 hhi = *reinterpret_cast<__half2*>(&hi);
    float2 flo = __half22float2(hlo), fhi = __half22float2(hhi);
    loPair = pk2(flo.x, flo.y);
    hiPair = pk2(fhi.x, fhi.y);
}

// ---------------- scratch tables (fp16, L2-resident: 3 x 8MB) ----------------
// stored as u64 quads for guaranteed 8B alignment: entry = 4 channels
__device__ u64 g_xq[NPTS * CCH / 4];
__device__ u64 g_xk[NPTS * CCH / 4];
__device__ u64 g_xv[NPTS * CCH / 4];

// =====================================================================
// Kernel 1: xq/xk/xv = x @ W^T + b  -> fp16 tables
// XOR-swizzled smem (stride 64): col' = col ^ ((k&3)<<4).
// =====================================================================
#define SWZ(k, c) ((c) ^ (((k) & 3) << 4))

__global__ __launch_bounds__(256) void gemm_qkv(
    const float* __restrict__ x,
    const float* __restrict__ Wq, const float* __restrict__ bq,
    const float* __restrict__ Wk, const float* __restrict__ bk,
    const float* __restrict__ Wv, const float* __restrict__ bv)
{
    __shared__ __align__(16) float sXf[64 * 64];
    __shared__ __align__(16) float sWf[64 * 64];
    __shared__ float sB[64];

    const int tid = threadIdx.x;
    const int mat = blockIdx.y;
    const float* W = (mat == 0) ? Wq : (mat == 1) ? Wk : Wv;
    const float* B = (mat == 0) ? bq : (mat == 1) ? bk : bv;
    u64* outp      = (mat == 0) ? g_xq : (mat == 1) ? g_xk : g_xv;
    const int row0 = blockIdx.x * 64;

    const int r  = tid & 63;
    const int kb = (tid >> 6) << 4;
    #pragma unroll
    for (int e = 0; e < 4; ++e) {
        float4 vx = *(const float4*)&x[(row0 + r) * 64 + kb + 4 * e];
        sXf[(kb + 4 * e + 0) * 64 + (r ^ 0) ] = vx.x;
        sXf[(kb + 4 * e + 1) * 64 + (r ^ 16)] = vx.y;
        sXf[(kb + 4 * e + 2) * 64 + (r ^ 32)] = vx.z;
        sXf[(kb + 4 * e + 3) * 64 + (r ^ 48)] = vx.w;
        float4 vw = *(const float4*)&W[r * 64 + kb + 4 * e];
        sWf[(kb + 4 * e + 0) * 64 + (r ^ 0) ] = vw.x;
        sWf[(kb + 4 * e + 1) * 64 + (r ^ 16)] = vw.y;
        sWf[(kb + 4 * e + 2) * 64 + (r ^ 32)] = vw.z;
        sWf[(kb + 4 * e + 3) * 64 + (r ^ 48)] = vw.w;
    }
    if (tid < 64) sB[tid] = B[tid];
    __syncthreads();

    const int tx = tid & 15;   // cols 4*tx..4*tx+3
    const int ty = tid >> 4;   // rows 4*ty..4*ty+3

    u64 acc[2][4];
    #pragma unroll
    for (int c = 0; c < 4; ++c) {
        float bb = sB[4 * tx + c];
        u64 bd = pk2(bb, bb);
        acc[0][c] = bd; acc[1][c] = bd;
    }

    #pragma unroll
    for (int k = 0; k < 64; ++k) {
        u64 a0 = *(const u64*)&sXf[k * 64 + SWZ(k, 4 * ty)];
        u64 a1 = *(const u64*)&sXf[k * 64 + SWZ(k, 4 * ty) + 2];
        float4 b4 = *(const float4*)&sWf[k * 64 + SWZ(k, 4 * tx)];
        u64 b0 = pk2(b4.x, b4.x), b1 = pk2(b4.y, b4.y);
        u64 b2 = pk2(b4.z, b4.z), b3 = pk2(b4.w, b4.w);
        acc[0][0] = ffma2(a0, b0, acc[0][0]);  acc[1][0] = ffma2(a1, b0, acc[1][0]);
        acc[0][1] = ffma2(a0, b1, acc[0][1]);  acc[1][1] = ffma2(a1, b1, acc[1][1]);
        acc[0][2] = ffma2(a0, b2, acc[0][2]);  acc[1][2] = ffma2(a1, b2, acc[1][2]);
        acc[0][3] = ffma2(a0, b3, acc[0][3]);  acc[1][3] = ffma2(a1, b3, acc[1][3]);
    }

    #pragma unroll
    for (int rp = 0; rp < 2; ++rp) {
        float lo0, hi0, lo1, hi1, lo2, hi2, lo3, hi3;
        upk2(acc[rp][0], lo0, hi0); upk2(acc[rp][1], lo1, hi1);
        upk2(acc[rp][2], lo2, hi2); upk2(acc[rp][3], lo3, hi3);
        const int row = row0 + 4 * ty + 2 * rp;
        // fp16 quad store: 4 channels = one u64 element
        outp[((row + 0) * 64 + 4 * tx) >> 2] =
            (u64)f22h(lo0, lo1) | ((u64)f22h(lo2, lo3) << 32);
        outp[((row + 1) * 64 + 4 * tx) >> 2] =
            (u64)f22h(hi0, hi1) | ((u64)f22h(hi2, hi3) << 32);
    }
}

// =====================================================================
// Kernel 2: fused point-transformer. One warp per point. fp16 tables.
// =====================================================================
__global__ void __launch_bounds__(128, 8) fused_pt(
    const float* __restrict__ p,   const int*   __restrict__ idx,
    const float* __restrict__ Wp1, const float* __restrict__ bp1,
    const float* __restrict__ pg,  const float* __restrict__ pb,
    const float* __restrict__ pm,  const float* __restrict__ pv,
    const float* __restrict__ Wp2, const float* __restrict__ bp2,
    const float* __restrict__ wg1, const float* __restrict__ wb1,
    const float* __restrict__ wm1, const float* __restrict__ wv1,
    const float* __restrict__ Ww1, const float* __restrict__ bw1,
    const float* __restrict__ wg2, const float* __restrict__ wb2,
    const float* __restrict__ wm2, const float* __restrict__ wv2,
    const float* __restrict__ Ww2, const float* __restrict__ bw2,
    float* __restrict__ out)
{
    __shared__ float  sWp1[9], sbp1v[3], spa[3], spbv[3];
    // per-warp (per point)
    __shared__ __align__(16) __half  ssw16[NBW][16][72];  // w[k][c] fp16, row 144B
    __shared__ __align__(16) float4  stv4 [NBW][16];      // {t0,t1,t2,bits(j)}
    __shared__ __align__(16) float   swl  [NBW][16][8];   // softmax weights

    const int tid = threadIdx.x;
    if (tid < 9) sWp1[tid] = Wp1[tid];
    if (tid < 3) {
        sbp1v[tid] = bp1[tid];
        float a = pg[tid] * rsqrtf(pv[tid] + EPSV);
        spa[tid] = a; spbv[tid] = pb[tid] - pm[tid] * a;
    }
    __syncthreads();

    const int w    = tid >> 5;
    const int lane = tid & 31;
    const int n    = blockIdx.x * NBW + w;
    const int q    = lane & 15;
    const int sub  = lane >> 4;
    const int c0   = 4 * q;      // channel quad owned in phases A & C
    const int qidx = q;          // u64 quad index within a row (16 quads/row)

    // ---- Phase 0: neighbor t values + index, packed per neighbor ----
    if (lane < 16) {
        int j = idx[n * 16 + lane];
        float pnx = p[n * 3 + 0], pny = p[n * 3 + 1], pnz = p[n * 3 + 2];
        float prx = p[j * 3 + 0] - pnx;
        float pry = p[j * 3 + 1] - pny;
        float prz = p[j * 3 + 2] - pnz;
        float u0 = prx * sWp1[0] + pry * sWp1[1] + prz * sWp1[2] + sbp1v[0];
        float u1 = prx * sWp1[3] + pry * sWp1[4] + prz * sWp1[5] + sbp1v[1];
        float u2 = prx * sWp1[6] + pry * sWp1[7] + prz * sWp1[8] + sbp1v[2];
        float t0 = fmaxf(0.f, fmaf(u0, spa[0], spbv[0]));
        float t1 = fmaxf(0.f, fmaf(u1, spa[1], spbv[1]));
        float t2 = fmaxf(0.f, fmaf(u2, spa[2], spbv[2]));
        stv4[w][lane] = make_float4(t0, t1, t2, __int_as_float(j));
    }
    __syncwarp();

    // ---- Phase A: gather xk (fp16 LDG.64), relation + pos-enc -> ssw16 ----
    {
        u64 xqA, xqB;
        h4_to_f22(g_xq[n * 16 + qidx], xqA, xqB);
        const u64 nxqA = neg2(xqA), nxqB = neg2(xqB);
        const u64 wpA0 = pk2(Wp2[(c0+0)*3+0], Wp2[(c0+1)*3+0]);
        const u64 wpA1 = pk2(Wp2[(c0+0)*3+1], Wp2[(c0+1)*3+1]);
        const u64 wpA2 = pk2(Wp2[(c0+0)*3+2], Wp2[(c0+1)*3+2]);
        const u64 wpB0 = pk2(Wp2[(c0+2)*3+0], Wp2[(c0+3)*3+0]);
        const u64 wpB1 = pk2(Wp2[(c0+2)*3+1], Wp2[(c0+3)*3+1]);
        const u64 wpB2 = pk2(Wp2[(c0+2)*3+2], Wp2[(c0+3)*3+2]);
        const u64 bpA  = pk2(bp2[c0],     bp2[c0 + 1]);
        const u64 bpB  = pk2(bp2[c0 + 2], bp2[c0 + 3]);
        float a1v[4], b1v[4];
        #pragma unroll
        for (int e = 0; e < 4; ++e) {
            float a = wg1[c0 + e] * rsqrtf(wv1[c0 + e] + EPSV);
            a1v[e] = a; b1v[e] = wb1[c0 + e] - wm1[c0 + e] * a;
        }

        #pragma unroll
        for (int it = 0; it < 8; ++it) {
            const int kk = 2 * it + sub;
            float4 tv = stv4[w][kk];
            int j = __float_as_int(tv.w);
            u64 t0d = pk2(tv.x, tv.x), t1d = pk2(tv.y, tv.y), t2d = pk2(tv.z, tv.z);
            u64 xkq = g_xk[j * 16 + qidx];                 // LDG.64 fp16 quad
            u64 kA, kB; h4_to_f22(xkq, kA, kB);
            u64 peA = ffma2(wpA0, t0d, ffma2(wpA1, t1d, ffma2(wpA2, t2d, bpA)));
            u64 peB = ffma2(wpB0, t0d, ffma2(wpB1, t1d, ffma2(wpB2, t2d, bpB)));
            u64 rA  = fadd2(fadd2(kA, nxqA), peA);
            u64 rB  = fadd2(fadd2(kB, nxqB), peB);
            float r0, r1, r2, r3;
            upk2(rA, r0, r1); upk2(rB, r2, r3);
            float w0 = fmaxf(0.f, fmaf(r0, a1v[0], b1v[0]));
            float w1 = fmaxf(0.f, fmaf(r1, a1v[1], b1v[1]));
            float w2_ = fmaxf(0.f, fmaf(r2, a1v[2], b1v[2]));
            float w3 = fmaxf(0.f, fmaf(r3, a1v[3], b1v[3]));
            u32 hlo = f22h(w0, w1), hhi = f22h(w2_, w3);
            *(u64*)&ssw16[w][kk][c0] = (u64)hlo | ((u64)hhi << 32);  // STS.64
        }
    }
    __syncwarp();

    // ---- Phase B: mma (w @ Ww1^T) -> bn2/relu -> mma (Ww2) -> softmax ----
    {
        const int nfr = lane >> 2;       // 0..7
        const int kfr = 2 * (lane & 3);  // 0,2,4,6

        u32 bf[4][2];
        #pragma unroll
        for (int ch = 0; ch < 4; ++ch) {
            const float* wr = &Ww1[nfr * 64 + ch * 16 + kfr];
            bf[ch][0] = f22h(wr[0], wr[1]);
            bf[ch][1] = f22h(wr[8], wr[9]);
        }
        const u32 bW2f = f22h(Ww2[nfr * 8 + kfr], Ww2[nfr * 8 + kfr + 1]);
        const float cbw1A = bw1[kfr],     cbw1B = bw1[kfr + 1];
        float tA = wg2[kfr]     * rsqrtf(wv2[kfr]     + EPSV);
        float tB = wg2[kfr + 1] * rsqrtf(wv2[kfr + 1] + EPSV);
        const float ca2A = tA, cb2A = wb2[kfr]     - wm2[kfr]     * tA;
        const float ca2B = tB, cb2B = wb2[kfr + 1] - wm2[kfr + 1] * tB;
        const float cbw2A = bw2[kfr], cbw2B = bw2[kfr + 1];

        u32 afr[4][4];
        const int arow = lane & 15;
        const int acol = (lane >> 4) << 3;
        #pragma unroll
        for (int ch = 0; ch < 4; ++ch) {
            u32 ad = smem_u32(&ssw16[w][arow][ch * 16 + acol]);
            asm volatile("ldmatrix.sync.aligned.m8n8.x4.shared.b16 {%0,%1,%2,%3}, [%4];"
                : "=r"(afr[ch][0]), "=r"(afr[ch][1]), "=r"(afr[ch][2]), "=r"(afr[ch][3])
                : "r"(ad));
        }
        float d0 = 0.f, d1 = 0.f, d2 = 0.f, d3 = 0.f;
        #pragma unroll
        for (int ch = 0; ch < 4; ++ch) {
            asm volatile("mma.sync.aligned.m16n8k16.row.col.f32.f16.f16.f32 "
                "{%0,%1,%2,%3}, {%4,%5,%6,%7}, {%8,%9}, {%0,%1,%2,%3};"
                : "+f"(d0), "+f"(d1), "+f"(d2), "+f"(d3)
                : "r"(afr[ch][0]), "r"(afr[ch][1]), "r"(afr[ch][2]), "r"(afr[ch][3]),
                  "r"(bf[ch][0]), "r"(bf[ch][1]));
        }
        float h0 = fmaxf(0.f, fmaf(d0 + cbw1A, ca2A, cb2A));
        float h1 = fmaxf(0.f, fmaf(d1 + cbw1B, ca2B, cb2B));
        float h2 = fmaxf(0.f, fmaf(d2 + cbw1A, ca2A, cb2A));
        float h3 = fmaxf(0.f, fmaf(d3 + cbw1B, ca2B, cb2B));
        u32 ha0 = f22h(h0, h1), ha1 = f22h(h2, h3);
        float l0 = 0.f, l1 = 0.f, l2 = 0.f, l3 = 0.f;
        asm volatile("mma.sync.aligned.m16n8k8.row.col.f32.f16.f16.f32 "
            "{%0,%1,%2,%3}, {%4,%5}, {%6}, {%0,%1,%2,%3};"
            : "+f"(l0), "+f"(l1), "+f"(l2), "+f"(l3)
            : "r"(ha0), "r"(ha1), "r"(bW2f));
        l0 += cbw2A; l1 += cbw2B; l2 += cbw2A; l3 += cbw2B;

        float mA = fmaxf(l0, l2), mB = fmaxf(l1, l3);
        #pragma unroll
        for (int dlt = 4; dlt <= 16; dlt <<= 1) {
            mA = fmaxf(mA, __shfl_xor_sync(0xffffffffu, mA, dlt));
            mB = fmaxf(mB, __shfl_xor_sync(0xffffffffu, mB, dlt));
        }
        float e0 = __expf(l0 - mA), e1 = __expf(l1 - mB);
        float e2 = __expf(l2 - mA), e3 = __expf(l3 - mB);
        float sA = e0 + e2, sB = e1 + e3;
        #pragma unroll
        for (int dlt = 4; dlt <= 16; dlt <<= 1) {
            sA += __shfl_xor_sync(0xffffffffu, sA, dlt);
            sB += __shfl_xor_sync(0xffffffffu, sB, dlt);
        }
        float iA = 1.f / sA, iB = 1.f / sB;
        *(u64*)&swl[w][nfr][kfr]     = pk2(e0 * iA, e1 * iB);
        *(u64*)&swl[w][nfr + 8][kfr] = pk2(e2 * iA, e3 * iB);
    }
    __syncwarp();

    // ---- Phase C: re-gather xv (fp16 LDG.64), recompute pe, weighted sum ----
    {
        const u64 wpA0 = pk2(Wp2[(c0+0)*3+0], Wp2[(c0+1)*3+0]);
        const u64 wpA1 = pk2(Wp2[(c0+0)*3+1], Wp2[(c0+1)*3+1]);
        const u64 wpA2 = pk2(Wp2[(c0+0)*3+2], Wp2[(c0+1)*3+2]);
        const u64 wpB0 = pk2(Wp2[(c0+2)*3+0], Wp2[(c0+3)*3+0]);
        const u64 wpB1 = pk2(Wp2[(c0+2)*3+1], Wp2[(c0+3)*3+1]);
        const u64 wpB2 = pk2(Wp2[(c0+2)*3+2], Wp2[(c0+3)*3+2]);
        const u64 bpA  = pk2(bp2[c0],     bp2[c0 + 1]);
        const u64 bpB  = pk2(bp2[c0 + 2], bp2[c0 + 3]);
        const int csq  = c0 & 7;   // 0 or 4 -> aligned 16B into swl row

        u64 acc0 = 0ull, acc1 = 0ull;
        #pragma unroll
        for (int it = 0; it < 8; ++it) {
            const int kk = 2 * it + sub;
            float4 tv = stv4[w][kk];
            int j = __float_as_int(tv.w);
            u64 t0d = pk2(tv.x, tv.x), t1d = pk2(tv.y, tv.y), t2d = pk2(tv.z, tv.z);
            u64 xvq = g_xv[j * 16 + qidx];                 // LDG.64 fp16 quad
            u64 vA, vB; h4_to_f22(xvq, vA, vB);
            u64 peA = ffma2(wpA0, t0d, ffma2(wpA1, t1d, ffma2(wpA2, t2d, bpA)));
            u64 peB = ffma2(wpB0, t0d, ffma2(wpB1, t1d, ffma2(wpB2, t2d, bpB)));
            ulonglong2 g2 = *(const ulonglong2*)&swl[w][kk][csq];     // LDS.128
            acc0 = ffma2(fadd2(vA, peA), g2.x, acc0);
            acc1 = ffma2(fadd2(vB, peB), g2.y, acc1);
        }
        float o0, o1, o2, o3;
        upk2(acc0, o0, o1); upk2(acc1, o2, o3);
        o0 += __shfl_xor_sync(0xffffffffu, o0, 16);
        o1 += __shfl_xor_sync(0xffffffffu, o1, 16);
        o2 += __shfl_xor_sync(0xffffffffu, o2, 16);
        o3 += __shfl_xor_sync(0xffffffffu, o3, 16);
        if (sub == 0)
            *(float4*)&out[n * 64 + c0] = make_float4(o0, o1, o2, o3);
    }
}

// =====================================================================
extern "C" void kernel_launch(void* const* d_in, const int* in_sizes, int n_in,
                              void* d_out, int out_size)
{
    const float* p   = (const float*)d_in[0];
    const float* x   = (const float*)d_in[1];
    const int*   idx = (const int*)  d_in[2];
    const float* Wq  = (const float*)d_in[3];
    const float* bq  = (const float*)d_in[4];
    const float* Wk  = (const float*)d_in[5];
    const float* bk  = (const float*)d_in[6];
    const float* Wv  = (const float*)d_in[7];
    const float* bv  = (const float*)d_in[8];
    const float* Wp1 = (const float*)d_in[9];
    const float* bp1 = (const float*)d_in[10];
    const float* pg  = (const float*)d_in[11];
    const float* pb  = (const float*)d_in[12];
    const float* pm  = (const float*)d_in[13];
    const float* pv  = (const float*)d_in[14];
    const float* Wp2 = (const float*)d_in[15];
    const float* bp2 = (const float*)d_in[16];
    const float* wg1 = (const float*)d_in[17];
    const float* wb1 = (const float*)d_in[18];
    const float* wm1 = (const float*)d_in[19];
    const float* wv1 = (const float*)d_in[20];
    const float* Ww1 = (const float*)d_in[21];
    const float* bw1 = (const float*)d_in[22];
    const float* wg2 = (const float*)d_in[23];
    const float* wb2 = (const float*)d_in[24];
    const float* wm2 = (const float*)d_in[25];
    const float* wv2 = (const float*)d_in[26];
    const float* Ww2 = (const float*)d_in[27];
    const float* bw2 = (const float*)d_in[28];
    float* out = (float*)d_out;

    gemm_qkv<<<dim3(NPTS / 64, 3, 1), 256>>>(x, Wq, bq, Wk, bk, Wv, bv);
    fused_pt<<<NPTS / NBW, 128>>>(p, idx, Wp1, bp1, pg, pb, pm, pv, Wp2, bp2,
                                  wg1, wb1, wm1, wv1, Ww1, bw1,
                                  wg2, wb2, wm2, wv2, Ww2, bw2, out);
}

// round 9
// speedup vs baseline: 1.9625x; 1.2470x over previous
#include <cuda_runtime.h>
#include <cuda_bf16.h>
#include <cuda_fp16.h>

typedef unsigned long long u64;
typedef unsigned int u32;

#define NPTS   65536
#define CCH    64
#define NSMP   16
#define CSW    8
#define EPSV   1e-5f
#define NBW    4   // points (warps) per block in fused kernel

// ---------------- f32x2 helpers ----------------
__device__ __forceinline__ u64 pk2(float a, float b) {
    u64 r; asm("mov.b64 %0, {%1, %2};" : "=l"(r) : "f"(a), "f"(b)); return r;
}
__device__ __forceinline__ void upk2(u64 v, float& a, float& b) {
    asm("mov.b64 {%0, %1}, %2;" : "=f"(a), "=f"(b) : "l"(v));
}
__device__ __forceinline__ u64 ffma2(u64 a, u64 b, u64 c) {
    u64 d; asm("fma.rn.f32x2 %0, %1, %2, %3;" : "=l"(d) : "l"(a), "l"(b), "l"(c)); return d;
}
__device__ __forceinline__ u64 fadd2(u64 a, u64 b) {
    u64 d; asm("add.rn.f32x2 %0, %1, %2;" : "=l"(d) : "l"(a), "l"(b)); return d;
}
__device__ __forceinline__ u64 neg2(u64 v) { return v ^ 0x8000000080000000ULL; }
__device__ __forceinline__ u32 f22h(float a, float b) {
    __half2 h = __floats2half2_rn(a, b);
    return *reinterpret_cast<u32*>(&h);
}
__device__ __forceinline__ u32 smem_u32(const void* p) {
    return (u32)__cvta_generic_to_shared(p);
}
// unpack u64 of 4 halves -> two packed f32x2
__device__ __forceinline__ void h4_to_f22(u64 h4, u64& loPair, u64& hiPair) {
    u32 lo = (u32)h4, hi = (u32)(h4 >> 32);
    __half2 hlo = *reinterpret_cast<__half2*>(&lo);
    __half2 hhi = *reinterpret_cast<__half2*>(&hi);
    float2 flo = __half22float2(hlo), fhi = __half22float2(hhi);
    loPair = pk2(flo.x, flo.y);
    hiPair = pk2(fhi.x, fhi.y);
}

// ---------------- scratch tables (fp16, L2-resident: 3 x 8MB) ----------------
__device__ u64 g_xq[NPTS * CCH / 4];
__device__ u64 g_xk[NPTS * CCH / 4];
__device__ u64 g_xv[NPTS * CCH / 4];

// =====================================================================
// Kernel 1: xq/xk/xv = x @ W^T + b via fp16 tensor-core MMA.
// One block = 64 rows; x loaded/converted ONCE, A-fragments shared
// across all 3 weight matrices. Warp w owns output col-tile n0 = 8w.
// =====================================================================
__global__ __launch_bounds__(256) void gemm_qkv_mma(
    const float* __restrict__ x,
    const float* __restrict__ Wq, const float* __restrict__ bq,
    const float* __restrict__ Wk, const float* __restrict__ bk,
    const float* __restrict__ Wv, const float* __restrict__ bv)
{
    __shared__ __align__(16) __half sx[64][72];   // row stride 144B (ldmatrix-safe)

    const int tid  = threadIdx.x;
    const int warp = tid >> 5;
    const int lane = tid & 31;
    const int row0 = blockIdx.x * 64;

    // load x tile (fp32) -> fp16 smem
    {
        const int r  = tid & 63;
        const int kb = (tid >> 6) * 16;
        const float* xr = &x[(row0 + r) * 64 + kb];
        float4 v0 = *(const float4*)&xr[0];
        float4 v1 = *(const float4*)&xr[4];
        float4 v2 = *(const float4*)&xr[8];
        float4 v3 = *(const float4*)&xr[12];
        uint4 h0 = make_uint4(f22h(v0.x, v0.y), f22h(v0.z, v0.w),
                              f22h(v1.x, v1.y), f22h(v1.z, v1.w));
        uint4 h1 = make_uint4(f22h(v2.x, v2.y), f22h(v2.z, v2.w),
                              f22h(v3.x, v3.y), f22h(v3.z, v3.w));
        *(uint4*)&sx[r][kb]     = h0;
        *(uint4*)&sx[r][kb + 8] = h1;
    }
    __syncthreads();

    const int n0  = warp * 8;
    const int nn  = n0 + (lane >> 2);
    const int kfr = 2 * (lane & 3);

    // B fragments (fp16) + biases, one-shot per warp
    const float* Ws[3] = {Wq, Wk, Wv};
    const float* Bs[3] = {bq, bk, bv};
    u32* outs[3] = {(u32*)g_xq, (u32*)g_xk, (u32*)g_xv};
    u32 bf[3][4][2];
    float bsx[3], bsy[3];
    #pragma unroll
    for (int m = 0; m < 3; ++m) {
        #pragma unroll
        for (int ks = 0; ks < 4; ++ks) {
            const float* wr = &Ws[m][nn * 64 + ks * 16 + kfr];
            bf[m][ks][0] = f22h(wr[0], wr[1]);
            bf[m][ks][1] = f22h(wr[8], wr[9]);
        }
        bsx[m] = Bs[m][n0 + kfr];
        bsy[m] = Bs[m][n0 + kfr + 1];
    }

    #pragma unroll
    for (int rt = 0; rt < 4; ++rt) {
        const int r0 = rt * 16;
        u32 afr[4][4];
        const int arow  = r0 + (lane & 15);
        const int acolb = (lane >> 4) << 3;
        #pragma unroll
        for (int ks = 0; ks < 4; ++ks) {
            u32 ad = smem_u32(&sx[arow][ks * 16 + acolb]);
            asm volatile("ldmatrix.sync.aligned.m8n8.x4.shared.b16 {%0,%1,%2,%3}, [%4];"
                : "=r"(afr[ks][0]), "=r"(afr[ks][1]), "=r"(afr[ks][2]), "=r"(afr[ks][3])
                : "r"(ad));
        }
        #pragma unroll
        for (int m = 0; m < 3; ++m) {
            float d0 = 0.f, d1 = 0.f, d2 = 0.f, d3 = 0.f;
            #pragma unroll
            for (int ks = 0; ks < 4; ++ks) {
                asm volatile("mma.sync.aligned.m16n8k16.row.col.f32.f16.f16.f32 "
                    "{%0,%1,%2,%3}, {%4,%5,%6,%7}, {%8,%9}, {%0,%1,%2,%3};"
                    : "+f"(d0), "+f"(d1), "+f"(d2), "+f"(d3)
                    : "r"(afr[ks][0]), "r"(afr[ks][1]), "r"(afr[ks][2]), "r"(afr[ks][3]),
                      "r"(bf[m][ks][0]), "r"(bf[m][ks][1]));
            }
            d0 += bsx[m]; d1 += bsy[m]; d2 += bsx[m]; d3 += bsy[m];
            const int row = row0 + r0 + (lane >> 2);
            u32* o = outs[m];
            o[row * 32 + ((n0 + kfr) >> 1)]       = f22h(d0, d1);
            o[(row + 8) * 32 + ((n0 + kfr) >> 1)] = f22h(d2, d3);
        }
    }
}

// =====================================================================
// Kernel 2: fused point-transformer. One warp per point. fp16 tables.
// Phase A also computes vpe = xv + pe -> fp16 smem; Phase C is a pure
// smem weighted sum (no LDG, no pe recompute).
// =====================================================================
__global__ void __launch_bounds__(128, 8) fused_pt(
    const float* __restrict__ p,   const int*   __restrict__ idx,
    const float* __restrict__ Wp1, const float* __restrict__ bp1,
    const float* __restrict__ pg,  const float* __restrict__ pb,
    const float* __restrict__ pm,  const float* __restrict__ pv,
    const float* __restrict__ Wp2, const float* __restrict__ bp2,
    const float* __restrict__ wg1, const float* __restrict__ wb1,
    const float* __restrict__ wm1, const float* __restrict__ wv1,
    const float* __restrict__ Ww1, const float* __restrict__ bw1,
    const float* __restrict__ wg2, const float* __restrict__ wb2,
    const float* __restrict__ wm2, const float* __restrict__ wv2,
    const float* __restrict__ Ww2, const float* __restrict__ bw2,
    float* __restrict__ out)
{
    __shared__ float  sWp1[9], sbp1v[3], spa[3], spbv[3];
    // per-warp (per point)
    __shared__ __align__(16) __half  ssw16 [NBW][16][72];  // w[k][c] fp16 (ldmatrix pad)
    __shared__ __align__(16) __half  svpe16[NBW][16][64];  // (xv+pe)[k][c] fp16
    __shared__ __align__(16) float4  stv4  [NBW][16];      // {t0,t1,t2,bits(j)}
    __shared__ __align__(16) float   swl   [NBW][16][8];   // softmax weights

    const int tid = threadIdx.x;
    if (tid < 9) sWp1[tid] = Wp1[tid];
    if (tid < 3) {
        sbp1v[tid] = bp1[tid];
        float a = pg[tid] * rsqrtf(pv[tid] + EPSV);
        spa[tid] = a; spbv[tid] = pb[tid] - pm[tid] * a;
    }
    __syncthreads();

    const int w    = tid >> 5;
    const int lane = tid & 31;
    const int n    = blockIdx.x * NBW + w;
    const int q    = lane & 15;
    const int sub  = lane >> 4;
    const int c0   = 4 * q;      // channel quad owned in phases A & C
    const int qidx = q;          // u64 quad index within a row

    // ---- Phase 0: neighbor t values + index, packed per neighbor ----
    if (lane < 16) {
        int j = idx[n * 16 + lane];
        float pnx = p[n * 3 + 0], pny = p[n * 3 + 1], pnz = p[n * 3 + 2];
        float prx = p[j * 3 + 0] - pnx;
        float pry = p[j * 3 + 1] - pny;
        float prz = p[j * 3 + 2] - pnz;
        float u0 = prx * sWp1[0] + pry * sWp1[1] + prz * sWp1[2] + sbp1v[0];
        float u1 = prx * sWp1[3] + pry * sWp1[4] + prz * sWp1[5] + sbp1v[1];
        float u2 = prx * sWp1[6] + pry * sWp1[7] + prz * sWp1[8] + sbp1v[2];
        float t0 = fmaxf(0.f, fmaf(u0, spa[0], spbv[0]));
        float t1 = fmaxf(0.f, fmaf(u1, spa[1], spbv[1]));
        float t2 = fmaxf(0.f, fmaf(u2, spa[2], spbv[2]));
        stv4[w][lane] = make_float4(t0, t1, t2, __int_as_float(j));
    }
    __syncwarp();

    // ---- Phase A: gather xk+xv (fp16 LDG.64), relation + pos-enc ----
    {
        u64 xqA, xqB;
        h4_to_f22(g_xq[n * 16 + qidx], xqA, xqB);
        const u64 nxqA = neg2(xqA), nxqB = neg2(xqB);
        const u64 wpA0 = pk2(Wp2[(c0+0)*3+0], Wp2[(c0+1)*3+0]);
        const u64 wpA1 = pk2(Wp2[(c0+0)*3+1], Wp2[(c0+1)*3+1]);
        const u64 wpA2 = pk2(Wp2[(c0+0)*3+2], Wp2[(c0+1)*3+2]);
        const u64 wpB0 = pk2(Wp2[(c0+2)*3+0], Wp2[(c0+3)*3+0]);
        const u64 wpB1 = pk2(Wp2[(c0+2)*3+1], Wp2[(c0+3)*3+1]);
        const u64 wpB2 = pk2(Wp2[(c0+2)*3+2], Wp2[(c0+3)*3+2]);
        const u64 bpA  = pk2(bp2[c0],     bp2[c0 + 1]);
        const u64 bpB  = pk2(bp2[c0 + 2], bp2[c0 + 3]);
        float a1v[4], b1v[4];
        #pragma unroll
        for (int e = 0; e < 4; ++e) {
            float a = wg1[c0 + e] * rsqrtf(wv1[c0 + e] + EPSV);
            a1v[e] = a; b1v[e] = wb1[c0 + e] - wm1[c0 + e] * a;
        }

        #pragma unroll
        for (int it = 0; it < 8; ++it) {
            const int kk = 2 * it + sub;
            float4 tv = stv4[w][kk];
            int j = __float_as_int(tv.w);
            u64 xkq = g_xk[j * 16 + qidx];                 // LDG.64 fp16 quad
            u64 xvq = g_xv[j * 16 + qidx];                 // LDG.64 fp16 quad
            u64 t0d = pk2(tv.x, tv.x), t1d = pk2(tv.y, tv.y), t2d = pk2(tv.z, tv.z);
            u64 peA = ffma2(wpA0, t0d, ffma2(wpA1, t1d, ffma2(wpA2, t2d, bpA)));
            u64 peB = ffma2(wpB0, t0d, ffma2(wpB1, t1d, ffma2(wpB2, t2d, bpB)));
            u64 kA, kB; h4_to_f22(xkq, kA, kB);
            u64 vA, vB; h4_to_f22(xvq, vA, vB);
            u64 rA  = fadd2(fadd2(kA, nxqA), peA);
            u64 rB  = fadd2(fadd2(kB, nxqB), peB);
            float r0, r1, r2, r3;
            upk2(rA, r0, r1); upk2(rB, r2, r3);
            float w0 = fmaxf(0.f, fmaf(r0, a1v[0], b1v[0]));
            float w1 = fmaxf(0.f, fmaf(r1, a1v[1], b1v[1]));
            float w2_ = fmaxf(0.f, fmaf(r2, a1v[2], b1v[2]));
            float w3 = fmaxf(0.f, fmaf(r3, a1v[3], b1v[3]));
            *(u64*)&ssw16[w][kk][c0] =
                (u64)f22h(w0, w1) | ((u64)f22h(w2_, w3) << 32);     // STS.64
            u64 vpeA = fadd2(vA, peA), vpeB = fadd2(vB, peB);
            float p0, p1, p2, p3;
            upk2(vpeA, p0, p1); upk2(vpeB, p2, p3);
            *(u64*)&svpe16[w][kk][c0] =
                (u64)f22h(p0, p1) | ((u64)f22h(p2, p3) << 32);      // STS.64
        }
    }
    __syncwarp();

    // ---- Phase B: mma (w @ Ww1^T) -> bn2/relu -> mma (Ww2) -> softmax ----
    {
        const int nfr = lane >> 2;       // 0..7
        const int kfr = 2 * (lane & 3);  // 0,2,4,6

        u32 bf[4][2];
        #pragma unroll
        for (int ch = 0; ch < 4; ++ch) {
            const float* wr = &Ww1[nfr * 64 + ch * 16 + kfr];
            bf[ch][0] = f22h(wr[0], wr[1]);
            bf[ch][1] = f22h(wr[8], wr[9]);
        }
        const u32 bW2f = f22h(Ww2[nfr * 8 + kfr], Ww2[nfr * 8 + kfr + 1]);
        const float cbw1A = bw1[kfr],     cbw1B = bw1[kfr + 1];
        float tA = wg2[kfr]     * rsqrtf(wv2[kfr]     + EPSV);
        float tB = wg2[kfr + 1] * rsqrtf(wv2[kfr + 1] + EPSV);
        const float ca2A = tA, cb2A = wb2[kfr]     - wm2[kfr]     * tA;
        const float ca2B = tB, cb2B = wb2[kfr + 1] - wm2[kfr + 1] * tB;
        const float cbw2A = bw2[kfr], cbw2B = bw2[kfr + 1];

        u32 afr[4][4];
        const int arow = lane & 15;
        const int acol = (lane >> 4) << 3;
        #pragma unroll
        for (int ch = 0; ch < 4; ++ch) {
            u32 ad = smem_u32(&ssw16[w][arow][ch * 16 + acol]);
            asm volatile("ldmatrix.sync.aligned.m8n8.x4.shared.b16 {%0,%1,%2,%3}, [%4];"
                : "=r"(afr[ch][0]), "=r"(afr[ch][1]), "=r"(afr[ch][2]), "=r"(afr[ch][3])
                : "r"(ad));
        }
        float d0 = 0.f, d1 = 0.f, d2 = 0.f, d3 = 0.f;
        #pragma unroll
        for (int ch = 0; ch < 4; ++ch) {
            asm volatile("mma.sync.aligned.m16n8k16.row.col.f32.f16.f16.f32 "
                "{%0,%1,%2,%3}, {%4,%5,%6,%7}, {%8,%9}, {%0,%1,%2,%3};"
                : "+f"(d0), "+f"(d1), "+f"(d2), "+f"(d3)
                : "r"(afr[ch][0]), "r"(afr[ch][1]), "r"(afr[ch][2]), "r"(afr[ch][3]),
                  "r"(bf[ch][0]), "r"(bf[ch][1]));
        }
        float h0 = fmaxf(0.f, fmaf(d0 + cbw1A, ca2A, cb2A));
        float h1 = fmaxf(0.f, fmaf(d1 + cbw1B, ca2B, cb2B));
        float h2 = fmaxf(0.f, fmaf(d2 + cbw1A, ca2A, cb2A));
        float h3 = fmaxf(0.f, fmaf(d3 + cbw1B, ca2B, cb2B));
        u32 ha0 = f22h(h0, h1), ha1 = f22h(h2, h3);
        float l0 = 0.f, l1 = 0.f, l2 = 0.f, l3 = 0.f;
        asm volatile("mma.sync.aligned.m16n8k8.row.col.f32.f16.f16.f32 "
            "{%0,%1,%2,%3}, {%4,%5}, {%6}, {%0,%1,%2,%3};"
            : "+f"(l0), "+f"(l1), "+f"(l2), "+f"(l3)
            : "r"(ha0), "r"(ha1), "r"(bW2f));
        l0 += cbw2A; l1 += cbw2B; l2 += cbw2A; l3 += cbw2B;

        float mA = fmaxf(l0, l2), mB = fmaxf(l1, l3);
        #pragma unroll
        for (int dlt = 4; dlt <= 16; dlt <<= 1) {
            mA = fmaxf(mA, __shfl_xor_sync(0xffffffffu, mA, dlt));
            mB = fmaxf(mB, __shfl_xor_sync(0xffffffffu, mB, dlt));
        }
        float e0 = __expf(l0 - mA), e1 = __expf(l1 - mB);
        float e2 = __expf(l2 - mA), e3 = __expf(l3 - mB);
        float sA = e0 + e2, sB = e1 + e3;
        #pragma unroll
        for (int dlt = 4; dlt <= 16; dlt <<= 1) {
            sA += __shfl_xor_sync(0xffffffffu, sA, dlt);
            sB += __shfl_xor_sync(0xffffffffu, sB, dlt);
        }
        float iA = 1.f / sA, iB = 1.f / sB;
        *(u64*)&swl[w][nfr][kfr]     = pk2(e0 * iA, e1 * iB);
        *(u64*)&swl[w][nfr + 8][kfr] = pk2(e2 * iA, e3 * iB);
    }
    __syncwarp();

    // ---- Phase C: pure smem weighted sum over neighbors ----
    {
        const int csq = c0 & 7;   // 0 or 4 -> aligned 16B into swl row

        u64 acc0 = 0ull, acc1 = 0ull;
        #pragma unroll
        for (int it = 0; it < 8; ++it) {
            const int kk = 2 * it + sub;
            u64 vq = *(const u64*)&svpe16[w][kk][c0];                 // LDS.64
            u64 vA, vB; h4_to_f22(vq, vA, vB);
            ulonglong2 g2 = *(const ulonglong2*)&swl[w][kk][csq];     // LDS.128
            acc0 = ffma2(vA, g2.x, acc0);
            acc1 = ffma2(vB, g2.y, acc1);
        }
        float o0, o1, o2, o3;
        upk2(acc0, o0, o1); upk2(acc1, o2, o3);
        o0 += __shfl_xor_sync(0xffffffffu, o0, 16);
        o1 += __shfl_xor_sync(0xffffffffu, o1, 16);
        o2 += __shfl_xor_sync(0xffffffffu, o2, 16);
        o3 += __shfl_xor_sync(0xffffffffu, o3, 16);
        if (sub == 0)
            *(float4*)&out[n * 64 + c0] = make_float4(o0, o1, o2, o3);
    }
}

// =====================================================================
extern "C" void kernel_launch(void* const* d_in, const int* in_sizes, int n_in,
                              void* d_out, int out_size)
{
    const float* p   = (const float*)d_in[0];
    const float* x   = (const float*)d_in[1];
    const int*   idx = (const int*)  d_in[2];
    const float* Wq  = (const float*)d_in[3];
    const float* bq  = (const float*)d_in[4];
    const float* Wk  = (const float*)d_in[5];
    const float* bk  = (const float*)d_in[6];
    const float* Wv  = (const float*)d_in[7];
    const float* bv  = (const float*)d_in[8];
    const float* Wp1 = (const float*)d_in[9];
    const float* bp1 = (const float*)d_in[10];
    const float* pg  = (const float*)d_in[11];
    const float* pb  = (const float*)d_in[12];
    const float* pm  = (const float*)d_in[13];
    const float* pv  = (const float*)d_in[14];
    const float* Wp2 = (const float*)d_in[15];
    const float* bp2 = (const float*)d_in[16];
    const float* wg1 = (const float*)d_in[17];
    const float* wb1 = (const float*)d_in[18];
    const float* wm1 = (const float*)d_in[19];
    const float* wv1 = (const float*)d_in[20];
    const float* Ww1 = (const float*)d_in[21];
    const float* bw1 = (const float*)d_in[22];
    const float* wg2 = (const float*)d_in[23];
    const float* wb2 = (const float*)d_in[24];
    const float* wm2 = (const float*)d_in[25];
    const float* wv2 = (const float*)d_in[26];
    const float* Ww2 = (const float*)d_in[27];
    const float* bw2 = (const float*)d_in[28];
    float* out = (float*)d_out;

    gemm_qkv_mma<<<NPTS / 64, 256>>>(x, Wq, bq, Wk, bk, Wv, bv);
    fused_pt<<<NPTS / NBW, 128>>>(p, idx, Wp1, bp1, pg, pb, pm, pv, Wp2, bp2,
                                  wg1, wb1, wm1, wv1, Ww1, bw1,
                                  wg2, wb2, wm2, wv2, Ww2, bw2, out);
}

// round 10
// speedup vs baseline: 1.9985x; 1.0183x over previous
#include <cuda_runtime.h>
#include <cuda_bf16.h>
#include <cuda_fp16.h>

typedef unsigned long long u64;
typedef unsigned int u32;

#define NPTS   65536
#define CCH    64
#define NSMP   16
#define CSW    8
#define EPSV   1e-5f
#define NBW    4   // points (warps) per block in fused kernel

// ---------------- f32x2 helpers ----------------
__device__ __forceinline__ u64 pk2(float a, float b) {
    u64 r; asm("mov.b64 %0, {%1, %2};" : "=l"(r) : "f"(a), "f"(b)); return r;
}
__device__ __forceinline__ void upk2(u64 v, float& a, float& b) {
    asm("mov.b64 {%0, %1}, %2;" : "=f"(a), "=f"(b) : "l"(v));
}
__device__ __forceinline__ u64 ffma2(u64 a, u64 b, u64 c) {
    u64 d; asm("fma.rn.f32x2 %0, %1, %2, %3;" : "=l"(d) : "l"(a), "l"(b), "l"(c)); return d;
}
__device__ __forceinline__ u64 fadd2(u64 a, u64 b) {
    u64 d; asm("add.rn.f32x2 %0, %1, %2;" : "=l"(d) : "l"(a), "l"(b)); return d;
}
__device__ __forceinline__ u64 neg2(u64 v) { return v ^ 0x8000000080000000ULL; }
__device__ __forceinline__ u32 f22h(float a, float b) {
    __half2 h = __floats2half2_rn(a, b);
    return *reinterpret_cast<u32*>(&h);
}
__device__ __forceinline__ u32 smem_u32(const void* p) {
    return (u32)__cvta_generic_to_shared(p);
}
// unpack u64 of 4 halves -> two packed f32x2
__device__ __forceinline__ void h4_to_f22(u64 h4, u64& loPair, u64& hiPair) {
    u32 lo = (u32)h4, hi = (u32)(h4 >> 32);
    __half2 hlo = *reinterpret_cast<__half2*>(&lo);
    __half2 hhi = *reinterpret_cast<__half2*>(&hi);
    float2 flo = __half22float2(hlo), fhi = __half22float2(hhi);
    loPair = pk2(flo.x, flo.y);
    hiPair = pk2(fhi.x, fhi.y);
}

// ---------------- scratch tables (fp16, L2-resident) ----------------
__device__ u64        g_xq [NPTS * CCH / 4];   // xq quads
__device__ ulonglong2 g_xkv[NPTS * 16];        // per row: 16 x {xk quad, xv quad}
__device__ float4     g_p4 [NPTS];             // padded coords

// =====================================================================
// Kernel 1: xq/xk/xv = x @ W^T + b via fp16 tensor-core MMA.
// Also builds the padded coordinate table g_p4.
// =====================================================================
__global__ __launch_bounds__(256) void gemm_qkv_mma(
    const float* __restrict__ x, const float* __restrict__ p,
    const float* __restrict__ Wq, const float* __restrict__ bq,
    const float* __restrict__ Wk, const float* __restrict__ bk,
    const float* __restrict__ Wv, const float* __restrict__ bv)
{
    __shared__ __align__(16) __half sx[64][72];   // row stride 144B (ldmatrix-safe)

    const int tid  = threadIdx.x;
    const int warp = tid >> 5;
    const int lane = tid & 31;
    const int row0 = blockIdx.x * 64;

    // build p4 table slice (64 rows)
    if (tid < 64) {
        const float* pr = &p[(row0 + tid) * 3];
        g_p4[row0 + tid] = make_float4(pr[0], pr[1], pr[2], 0.f);
    }

    // load x tile (fp32) -> fp16 smem
    {
        const int r  = tid & 63;
        const int kb = (tid >> 6) * 16;
        const float* xr = &x[(row0 + r) * 64 + kb];
        float4 v0 = *(const float4*)&xr[0];
        float4 v1 = *(const float4*)&xr[4];
        float4 v2 = *(const float4*)&xr[8];
        float4 v3 = *(const float4*)&xr[12];
        uint4 h0 = make_uint4(f22h(v0.x, v0.y), f22h(v0.z, v0.w),
                              f22h(v1.x, v1.y), f22h(v1.z, v1.w));
        uint4 h1 = make_uint4(f22h(v2.x, v2.y), f22h(v2.z, v2.w),
                              f22h(v3.x, v3.y), f22h(v3.z, v3.w));
        *(uint4*)&sx[r][kb]     = h0;
        *(uint4*)&sx[r][kb + 8] = h1;
    }
    __syncthreads();

    const int n0  = warp * 8;
    const int nn  = n0 + (lane >> 2);
    const int kfr = 2 * (lane & 3);

    const float* Ws[3] = {Wq, Wk, Wv};
    const float* Bs[3] = {bq, bk, bv};
    u32 bf[3][4][2];
    float bsx[3], bsy[3];
    #pragma unroll
    for (int m = 0; m < 3; ++m) {
        #pragma unroll
        for (int ks = 0; ks < 4; ++ks) {
            const float* wr = &Ws[m][nn * 64 + ks * 16 + kfr];
            bf[m][ks][0] = f22h(wr[0], wr[1]);
            bf[m][ks][1] = f22h(wr[8], wr[9]);
        }
        bsx[m] = Bs[m][n0 + kfr];
        bsy[m] = Bs[m][n0 + kfr + 1];
    }

    // pair index within row for this thread's outputs
    const int pp   = (n0 + kfr) >> 1;   // 0..31
    const int qq   = pp >> 1;           // quad 0..15
    const int half = pp & 1;

    #pragma unroll
    for (int rt = 0; rt < 4; ++rt) {
        const int r0 = rt * 16;
        u32 afr[4][4];
        const int arow  = r0 + (lane & 15);
        const int acolb = (lane >> 4) << 3;
        #pragma unroll
        for (int ks = 0; ks < 4; ++ks) {
            u32 ad = smem_u32(&sx[arow][ks * 16 + acolb]);
            asm volatile("ldmatrix.sync.aligned.m8n8.x4.shared.b16 {%0,%1,%2,%3}, [%4];"
                : "=r"(afr[ks][0]), "=r"(afr[ks][1]), "=r"(afr[ks][2]), "=r"(afr[ks][3])
                : "r"(ad));
        }
        const int rowA = row0 + r0 + (lane >> 2);
        const int rowB = rowA + 8;
        #pragma unroll
        for (int m = 0; m < 3; ++m) {
            float d0 = 0.f, d1 = 0.f, d2 = 0.f, d3 = 0.f;
            #pragma unroll
            for (int ks = 0; ks < 4; ++ks) {
                asm volatile("mma.sync.aligned.m16n8k16.row.col.f32.f16.f16.f32 "
                    "{%0,%1,%2,%3}, {%4,%5,%6,%7}, {%8,%9}, {%0,%1,%2,%3};"
                    : "+f"(d0), "+f"(d1), "+f"(d2), "+f"(d3)
                    : "r"(afr[ks][0]), "r"(afr[ks][1]), "r"(afr[ks][2]), "r"(afr[ks][3]),
                      "r"(bf[m][ks][0]), "r"(bf[m][ks][1]));
            }
            d0 += bsx[m]; d1 += bsy[m]; d2 += bsx[m]; d3 += bsy[m];
            if (m == 0) {
                u32* o = (u32*)g_xq;
                o[rowA * 32 + pp] = f22h(d0, d1);
                o[rowB * 32 + pp] = f22h(d2, d3);
            } else {
                u32* o = (u32*)g_xkv;   // row stride 64 u32
                const int sub2 = (m == 1) ? 0 : 2;
                o[rowA * 64 + qq * 4 + sub2 + half] = f22h(d0, d1);
                o[rowB * 64 + qq * 4 + sub2 + half] = f22h(d2, d3);
            }
        }
    }
}

// =====================================================================
// Kernel 2: fused point-transformer. One warp per point.
// xk/xv interleaved table -> single LDG.128 gather per (2 nbr, quad).
// =====================================================================
__global__ void __launch_bounds__(128, 8) fused_pt(
    const int*   __restrict__ idx,
    const float* __restrict__ Wp1, const float* __restrict__ bp1,
    const float* __restrict__ pg,  const float* __restrict__ pb,
    const float* __restrict__ pm,  const float* __restrict__ pv,
    const float* __restrict__ Wp2, const float* __restrict__ bp2,
    const float* __restrict__ wg1, const float* __restrict__ wb1,
    const float* __restrict__ wm1, const float* __restrict__ wv1,
    const float* __restrict__ Ww1, const float* __restrict__ bw1,
    const float* __restrict__ wg2, const float* __restrict__ wb2,
    const float* __restrict__ wm2, const float* __restrict__ wv2,
    const float* __restrict__ Ww2, const float* __restrict__ bw2,
    float* __restrict__ out)
{
    __shared__ float  sWp1[9], sbp1v[3], spa[3], spbv[3];
    // per-warp (per point)
    __shared__ __align__(16) __half  ssw16 [NBW][16][72];  // w[k][c] fp16 (ldmatrix pad)
    __shared__ __align__(16) __half  svpe16[NBW][16][64];  // (xv+pe)[k][c] fp16
    __shared__ __align__(16) float4  stv4  [NBW][16];      // {t0,t1,t2,bits(j)}
    __shared__ __align__(16) float   swl   [NBW][16][8];   // softmax weights

    const int tid = threadIdx.x;
    if (tid < 9) sWp1[tid] = Wp1[tid];
    if (tid < 3) {
        sbp1v[tid] = bp1[tid];
        float a = pg[tid] * rsqrtf(pv[tid] + EPSV);
        spa[tid] = a; spbv[tid] = pb[tid] - pm[tid] * a;
    }
    __syncthreads();

    const int w    = tid >> 5;
    const int lane = tid & 31;
    const int n    = blockIdx.x * NBW + w;
    const int q    = lane & 15;
    const int sub  = lane >> 4;
    const int c0   = 4 * q;      // channel quad owned in phases A & C

    // ---- Phase 0: neighbor t values + index (padded p4 loads) ----
    if (lane < 16) {
        int j = idx[n * 16 + lane];
        float4 pn = g_p4[n];     // broadcast
        float4 pj = g_p4[j];     // 1 LDG.128 per lane
        float prx = pj.x - pn.x;
        float pry = pj.y - pn.y;
        float prz = pj.z - pn.z;
        float u0 = prx * sWp1[0] + pry * sWp1[1] + prz * sWp1[2] + sbp1v[0];
        float u1 = prx * sWp1[3] + pry * sWp1[4] + prz * sWp1[5] + sbp1v[1];
        float u2 = prx * sWp1[6] + pry * sWp1[7] + prz * sWp1[8] + sbp1v[2];
        float t0 = fmaxf(0.f, fmaf(u0, spa[0], spbv[0]));
        float t1 = fmaxf(0.f, fmaf(u1, spa[1], spbv[1]));
        float t2 = fmaxf(0.f, fmaf(u2, spa[2], spbv[2]));
        stv4[w][lane] = make_float4(t0, t1, t2, __int_as_float(j));
    }
    __syncwarp();

    // ---- Phase A: single LDG.128 gather (xk|xv quad), relation + pe ----
    {
        u64 xqA, xqB;
        h4_to_f22(g_xq[n * 16 + q], xqA, xqB);
        const u64 nxqA = neg2(xqA), nxqB = neg2(xqB);
        const u64 wpA0 = pk2(Wp2[(c0+0)*3+0], Wp2[(c0+1)*3+0]);
        const u64 wpA1 = pk2(Wp2[(c0+0)*3+1], Wp2[(c0+1)*3+1]);
        const u64 wpA2 = pk2(Wp2[(c0+0)*3+2], Wp2[(c0+1)*3+2]);
        const u64 wpB0 = pk2(Wp2[(c0+2)*3+0], Wp2[(c0+3)*3+0]);
        const u64 wpB1 = pk2(Wp2[(c0+2)*3+1], Wp2[(c0+3)*3+1]);
        const u64 wpB2 = pk2(Wp2[(c0+2)*3+2], Wp2[(c0+3)*3+2]);
        const u64 bpA  = pk2(bp2[c0],     bp2[c0 + 1]);
        const u64 bpB  = pk2(bp2[c0 + 2], bp2[c0 + 3]);
        float a1v[4], b1v[4];
        #pragma unroll
        for (int e = 0; e < 4; ++e) {
            float a = wg1[c0 + e] * rsqrtf(wv1[c0 + e] + EPSV);
            a1v[e] = a; b1v[e] = wb1[c0 + e] - wm1[c0 + e] * a;
        }

        #pragma unroll
        for (int it = 0; it < 8; ++it) {
            const int kk = 2 * it + sub;
            float4 tv = stv4[w][kk];
            int j = __float_as_int(tv.w);
            ulonglong2 kv = g_xkv[j * 16 + q];             // ONE LDG.128: xk|xv quads
            u64 t0d = pk2(tv.x, tv.x), t1d = pk2(tv.y, tv.y), t2d = pk2(tv.z, tv.z);
            u64 peA = ffma2(wpA0, t0d, ffma2(wpA1, t1d, ffma2(wpA2, t2d, bpA)));
            u64 peB = ffma2(wpB0, t0d, ffma2(wpB1, t1d, ffma2(wpB2, t2d, bpB)));
            u64 kA, kB; h4_to_f22(kv.x, kA, kB);
            u64 vA, vB; h4_to_f22(kv.y, vA, vB);
            u64 rA  = fadd2(fadd2(kA, nxqA), peA);
            u64 rB  = fadd2(fadd2(kB, nxqB), peB);
            float r0, r1, r2, r3;
            upk2(rA, r0, r1); upk2(rB, r2, r3);
            float w0 = fmaxf(0.f, fmaf(r0, a1v[0], b1v[0]));
            float w1 = fmaxf(0.f, fmaf(r1, a1v[1], b1v[1]));
            float w2_ = fmaxf(0.f, fmaf(r2, a1v[2], b1v[2]));
            float w3 = fmaxf(0.f, fmaf(r3, a1v[3], b1v[3]));
            *(u64*)&ssw16[w][kk][c0] =
                (u64)f22h(w0, w1) | ((u64)f22h(w2_, w3) << 32);     // STS.64
            u64 vpeA = fadd2(vA, peA), vpeB = fadd2(vB, peB);
            float p0, p1, p2, p3;
            upk2(vpeA, p0, p1); upk2(vpeB, p2, p3);
            *(u64*)&svpe16[w][kk][c0] =
                (u64)f22h(p0, p1) | ((u64)f22h(p2, p3) << 32);      // STS.64
        }
    }
    __syncwarp();

    // ---- Phase B: mma (w @ Ww1^T) -> bn2/relu -> mma (Ww2) -> softmax ----
    {
        const int nfr = lane >> 2;       // 0..7
        const int kfr = 2 * (lane & 3);  // 0,2,4,6

        u32 bf[4][2];
        #pragma unroll
        for (int ch = 0; ch < 4; ++ch) {
            const float* wr = &Ww1[nfr * 64 + ch * 16 + kfr];
            bf[ch][0] = f22h(wr[0], wr[1]);
            bf[ch][1] = f22h(wr[8], wr[9]);
        }
        const u32 bW2f = f22h(Ww2[nfr * 8 + kfr], Ww2[nfr * 8 + kfr + 1]);
        const float cbw1A = bw1[kfr],     cbw1B = bw1[kfr + 1];
        float tA = wg2[kfr]     * rsqrtf(wv2[kfr]     + EPSV);
        float tB = wg2[kfr + 1] * rsqrtf(wv2[kfr + 1] + EPSV);
        const float ca2A = tA, cb2A = wb2[kfr]     - wm2[kfr]     * tA;
        const float ca2B = tB, cb2B = wb2[kfr + 1] - wm2[kfr + 1] * tB;
        const float cbw2A = bw2[kfr], cbw2B = bw2[kfr + 1];

        u32 afr[4][4];
        const int arow = lane & 15;
        const int acol = (lane >> 4) << 3;
        #pragma unroll
        for (int ch = 0; ch < 4; ++ch) {
            u32 ad = smem_u32(&ssw16[w][arow][ch * 16 + acol]);
            asm volatile("ldmatrix.sync.aligned.m8n8.x4.shared.b16 {%0,%1,%2,%3}, [%4];"
                : "=r"(afr[ch][0]), "=r"(afr[ch][1]), "=r"(afr[ch][2]), "=r"(afr[ch][3])
                : "r"(ad));
        }
        float d0 = 0.f, d1 = 0.f, d2 = 0.f, d3 = 0.f;
        #pragma unroll
        for (int ch = 0; ch < 4; ++ch) {
            asm volatile("mma.sync.aligned.m16n8k16.row.col.f32.f16.f16.f32 "
                "{%0,%1,%2,%3}, {%4,%5,%6,%7}, {%8,%9}, {%0,%1,%2,%3};"
                : "+f"(d0), "+f"(d1), "+f"(d2), "+f"(d3)
                : "r"(afr[ch][0]), "r"(afr[ch][1]), "r"(afr[ch][2]), "r"(afr[ch][3]),
                  "r"(bf[ch][0]), "r"(bf[ch][1]));
        }
        float h0 = fmaxf(0.f, fmaf(d0 + cbw1A, ca2A, cb2A));
        float h1 = fmaxf(0.f, fmaf(d1 + cbw1B, ca2B, cb2B));
        float h2 = fmaxf(0.f, fmaf(d2 + cbw1A, ca2A, cb2A));
        float h3 = fmaxf(0.f, fmaf(d3 + cbw1B, ca2B, cb2B));
        u32 ha0 = f22h(h0, h1), ha1 = f22h(h2, h3);
        float l0 = 0.f, l1 = 0.f, l2 = 0.f, l3 = 0.f;
        asm volatile("mma.sync.aligned.m16n8k8.row.col.f32.f16.f16.f32 "
            "{%0,%1,%2,%3}, {%4,%5}, {%6}, {%0,%1,%2,%3};"
            : "+f"(l0), "+f"(l1), "+f"(l2), "+f"(l3)
            : "r"(ha0), "r"(ha1), "r"(bW2f));
        l0 += cbw2A; l1 += cbw2B; l2 += cbw2A; l3 += cbw2B;

        float mA = fmaxf(l0, l2), mB = fmaxf(l1, l3);
        #pragma unroll
        for (int dlt = 4; dlt <= 16; dlt <<= 1) {
            mA = fmaxf(mA, __shfl_xor_sync(0xffffffffu, mA, dlt));
            mB = fmaxf(mB, __shfl_xor_sync(0xffffffffu, mB, dlt));
        }
        float e0 = __expf(l0 - mA), e1 = __expf(l1 - mB);
        float e2 = __expf(l2 - mA), e3 = __expf(l3 - mB);
        float sA = e0 + e2, sB = e1 + e3;
        #pragma unroll
        for (int dlt = 4; dlt <= 16; dlt <<= 1) {
            sA += __shfl_xor_sync(0xffffffffu, sA, dlt);
            sB += __shfl_xor_sync(0xffffffffu, sB, dlt);
        }
        float iA = 1.f / sA, iB = 1.f / sB;
        *(u64*)&swl[w][nfr][kfr]     = pk2(e0 * iA, e1 * iB);
        *(u64*)&swl[w][nfr + 8][kfr] = pk2(e2 * iA, e3 * iB);
    }
    __syncwarp();

    // ---- Phase C: pure smem weighted sum over neighbors ----
    {
        const int csq = c0 & 7;   // 0 or 4 -> aligned 16B into swl row

        u64 acc0 = 0ull, acc1 = 0ull;
        #pragma unroll
        for (int it = 0; it < 8; ++it) {
            const int kk = 2 * it + sub;
            u64 vq = *(const u64*)&svpe16[w][kk][c0];                 // LDS.64
            u64 vA, vB; h4_to_f22(vq, vA, vB);
            ulonglong2 g2 = *(const ulonglong2*)&swl[w][kk][csq];     // LDS.128
            acc0 = ffma2(vA, g2.x, acc0);
            acc1 = ffma2(vB, g2.y, acc1);
        }
        float o0, o1, o2, o3;
        upk2(acc0, o0, o1); upk2(acc1, o2, o3);
        o0 += __shfl_xor_sync(0xffffffffu, o0, 16);
        o1 += __shfl_xor_sync(0xffffffffu, o1, 16);
        o2 += __shfl_xor_sync(0xffffffffu, o2, 16);
        o3 += __shfl_xor_sync(0xffffffffu, o3, 16);
        if (sub == 0)
            *(float4*)&out[n * 64 + c0] = make_float4(o0, o1, o2, o3);
    }
}

// =====================================================================
extern "C" void kernel_launch(void* const* d_in, const int* in_sizes, int n_in,
                              void* d_out, int out_size)
{
    const float* p   = (const float*)d_in[0];
    const float* x   = (const float*)d_in[1];
    const int*   idx = (const int*)  d_in[2];
    const float* Wq  = (const float*)d_in[3];
    const float* bq  = (const float*)d_in[4];
    const float* Wk  = (const float*)d_in[5];
    const float* bk  = (const float*)d_in[6];
    const float* Wv  = (const float*)d_in[7];
    const float* bv  = (const float*)d_in[8];
    const float* Wp1 = (const float*)d_in[9];
    const float* bp1 = (const float*)d_in[10];
    const float* pg  = (const float*)d_in[11];
    const float* pb  = (const float*)d_in[12];
    const float* pm  = (const float*)d_in[13];
    const float* pv  = (const float*)d_in[14];
    const float* Wp2 = (const float*)d_in[15];
    const float* bp2 = (const float*)d_in[16];
    const float* wg1 = (const float*)d_in[17];
    const float* wb1 = (const float*)d_in[18];
    const float* wm1 = (const float*)d_in[19];
    const float* wv1 = (const float*)d_in[20];
    const float* Ww1 = (const float*)d_in[21];
    const float* bw1 = (const float*)d_in[22];
    const float* wg2 = (const float*)d_in[23];
    const float* wb2 = (const float*)d_in[24];
    const float* wm2 = (const float*)d_in[25];
    const float* wv2 = (const float*)d_in[26];
    const float* Ww2 = (const float*)d_in[27];
    const float* bw2 = (const float*)d_in[28];
    float* out = (float*)d_out;

    gemm_qkv_mma<<<NPTS / 64, 256>>>(x, p, Wq, bq, Wk, bk, Wv, bv);
    fused_pt<<<NPTS / NBW, 128>>>(idx, Wp1, bp1, pg, pb, pm, pv, Wp2, bp2,
                                  wg1, wb1, wm1, wv1, Ww1, bw1,
                                  wg2, wb2, wm2, wv2, Ww2, bw2, out);
}

// round 11
// speedup vs baseline: 2.4859x; 1.2439x over previous
#include <cuda_runtime.h>
#include <cuda_bf16.h>
#include <cuda_fp16.h>

typedef unsigned long long u64;
typedef unsigned int u32;

#define NPTS   65536
#define CCH    64
#define NSMP   16
#define CSW    8
#define EPSV   1e-5f
#define NBW    4   // points (warps) per block in fused kernel

// ---------------- f32x2 helpers ----------------
__device__ __forceinline__ u64 pk2(float a, float b) {
    u64 r; asm("mov.b64 %0, {%1, %2};" : "=l"(r) : "f"(a), "f"(b)); return r;
}
__device__ __forceinline__ void upk2(u64 v, float& a, float& b) {
    asm("mov.b64 {%0, %1}, %2;" : "=f"(a), "=f"(b) : "l"(v));
}
__device__ __forceinline__ u64 ffma2(u64 a, u64 b, u64 c) {
    u64 d; asm("fma.rn.f32x2 %0, %1, %2, %3;" : "=l"(d) : "l"(a), "l"(b), "l"(c)); return d;
}
__device__ __forceinline__ u64 fadd2(u64 a, u64 b) {
    u64 d; asm("add.rn.f32x2 %0, %1, %2;" : "=l"(d) : "l"(a), "l"(b)); return d;
}
__device__ __forceinline__ u32 f22h(float a, float b) {
    __half2 h = __floats2half2_rn(a, b);
    return *reinterpret_cast<u32*>(&h);
}
__device__ __forceinline__ u32 smem_u32(const void* p) {
    return (u32)__cvta_generic_to_shared(p);
}
// unpack u64 of 4 halves -> two packed f32x2
__device__ __forceinline__ void h4_to_f22(u64 h4, u64& loPair, u64& hiPair) {
    u32 lo = (u32)h4, hi = (u32)(h4 >> 32);
    __half2 hlo = *reinterpret_cast<__half2*>(&lo);
    __half2 hhi = *reinterpret_cast<__half2*>(&hi);
    float2 flo = __half22float2(hlo), fhi = __half22float2(hhi);
    loPair = pk2(flo.x, flo.y);
    hiPair = pk2(fhi.x, fhi.y);
}
// ---------------- half2-as-u32 helpers ----------------
__device__ __forceinline__ u32 hfma2u(u32 a, u32 b, u32 c) {
    __half2 r = __hfma2(*(__half2*)&a, *(__half2*)&b, *(__half2*)&c);
    return *(u32*)&r;
}
__device__ __forceinline__ u32 hadd2u(u32 a, u32 b) {
    __half2 r = __hadd2(*(__half2*)&a, *(__half2*)&b);
    return *(u32*)&r;
}
__device__ __forceinline__ u32 hsub2u(u32 a, u32 b) {
    __half2 r = __hsub2(*(__half2*)&a, *(__half2*)&b);
    return *(u32*)&r;
}
__device__ __forceinline__ u32 hrelu2u(u32 a) {
    __half2 z = __floats2half2_rn(0.f, 0.f);
    __half2 r = __hmax2(*(__half2*)&a, z);
    return *(u32*)&r;
}

// ---------------- scratch tables (fp16, L2-resident) ----------------
__device__ u64        g_xq [NPTS * CCH / 4];   // xq quads
__device__ ulonglong2 g_xkv[NPTS * 16];        // per row: 16 x {xk quad, xv quad}
__device__ float4     g_p4 [NPTS];             // padded coords

// =====================================================================
// Kernel 1: xq/xk/xv = x @ W^T + b via fp16 tensor-core MMA.
// Also builds the padded coordinate table g_p4.
// =====================================================================
__global__ __launch_bounds__(256) void gemm_qkv_mma(
    const float* __restrict__ x, const float* __restrict__ p,
    const float* __restrict__ Wq, const float* __restrict__ bq,
    const float* __restrict__ Wk, const float* __restrict__ bk,
    const float* __restrict__ Wv, const float* __restrict__ bv)
{
    __shared__ __align__(16) __half sx[64][72];   // row stride 144B (ldmatrix-safe)

    const int tid  = threadIdx.x;
    const int warp = tid >> 5;
    const int lane = tid & 31;
    const int row0 = blockIdx.x * 64;

    if (tid < 64) {
        const float* pr = &p[(row0 + tid) * 3];
        g_p4[row0 + tid] = make_float4(pr[0], pr[1], pr[2], 0.f);
    }

    {
        const int r  = tid & 63;
        const int kb = (tid >> 6) * 16;
        const float* xr = &x[(row0 + r) * 64 + kb];
        float4 v0 = *(const float4*)&xr[0];
        float4 v1 = *(const float4*)&xr[4];
        float4 v2 = *(const float4*)&xr[8];
        float4 v3 = *(const float4*)&xr[12];
        uint4 h0 = make_uint4(f22h(v0.x, v0.y), f22h(v0.z, v0.w),
                              f22h(v1.x, v1.y), f22h(v1.z, v1.w));
        uint4 h1 = make_uint4(f22h(v2.x, v2.y), f22h(v2.z, v2.w),
                              f22h(v3.x, v3.y), f22h(v3.z, v3.w));
        *(uint4*)&sx[r][kb]     = h0;
        *(uint4*)&sx[r][kb + 8] = h1;
    }
    __syncthreads();

    const int n0  = warp * 8;
    const int nn  = n0 + (lane >> 2);
    const int kfr = 2 * (lane & 3);

    const float* Ws[3] = {Wq, Wk, Wv};
    const float* Bs[3] = {bq, bk, bv};
    u32 bf[3][4][2];
    float bsx[3], bsy[3];
    #pragma unroll
    for (int m = 0; m < 3; ++m) {
        #pragma unroll
        for (int ks = 0; ks < 4; ++ks) {
            const float* wr = &Ws[m][nn * 64 + ks * 16 + kfr];
            float2 wa = *(const float2*)&wr[0];
            float2 wb = *(const float2*)&wr[8];
            bf[m][ks][0] = f22h(wa.x, wa.y);
            bf[m][ks][1] = f22h(wb.x, wb.y);
        }
        float2 bb = *(const float2*)&Bs[m][n0 + kfr];
        bsx[m] = bb.x; bsy[m] = bb.y;
    }

    const int pp   = (n0 + kfr) >> 1;   // 0..31
    const int qq   = pp >> 1;           // quad 0..15
    const int half = pp & 1;

    #pragma unroll
    for (int rt = 0; rt < 4; ++rt) {
        const int r0 = rt * 16;
        u32 afr[4][4];
        const int arow  = r0 + (lane & 15);
        const int acolb = (lane >> 4) << 3;
        #pragma unroll
        for (int ks = 0; ks < 4; ++ks) {
            u32 ad = smem_u32(&sx[arow][ks * 16 + acolb]);
            asm volatile("ldmatrix.sync.aligned.m8n8.x4.shared.b16 {%0,%1,%2,%3}, [%4];"
                : "=r"(afr[ks][0]), "=r"(afr[ks][1]), "=r"(afr[ks][2]), "=r"(afr[ks][3])
                : "r"(ad));
        }
        const int rowA = row0 + r0 + (lane >> 2);
        const int rowB = rowA + 8;
        #pragma unroll
        for (int m = 0; m < 3; ++m) {
            float d0 = 0.f, d1 = 0.f, d2 = 0.f, d3 = 0.f;
            #pragma unroll
            for (int ks = 0; ks < 4; ++ks) {
                asm volatile("mma.sync.aligned.m16n8k16.row.col.f32.f16.f16.f32 "
                    "{%0,%1,%2,%3}, {%4,%5,%6,%7}, {%8,%9}, {%0,%1,%2,%3};"
                    : "+f"(d0), "+f"(d1), "+f"(d2), "+f"(d3)
                    : "r"(afr[ks][0]), "r"(afr[ks][1]), "r"(afr[ks][2]), "r"(afr[ks][3]),
                      "r"(bf[m][ks][0]), "r"(bf[m][ks][1]));
            }
            d0 += bsx[m]; d1 += bsy[m]; d2 += bsx[m]; d3 += bsy[m];
            if (m == 0) {
                u32* o = (u32*)g_xq;
                o[rowA * 32 + pp] = f22h(d0, d1);
                o[rowB * 32 + pp] = f22h(d2, d3);
            } else {
                u32* o = (u32*)g_xkv;   // row stride 64 u32
                const int sub2 = (m == 1) ? 0 : 2;
                o[rowA * 64 + qq * 4 + sub2 + half] = f22h(d0, d1);
                o[rowB * 64 + qq * 4 + sub2 + half] = f22h(d2, d3);
            }
        }
    }
}

// =====================================================================
// Kernel 2: fused point-transformer. One warp per point.
// Phase A in pure half2 arithmetic (no converts/packs).
// =====================================================================
__global__ void __launch_bounds__(128, 8) fused_pt(
    const int*   __restrict__ idx,
    const float* __restrict__ Wp1, const float* __restrict__ bp1,
    const float* __restrict__ pg,  const float* __restrict__ pb,
    const float* __restrict__ pm,  const float* __restrict__ pv,
    const float* __restrict__ Wp2, const float* __restrict__ bp2,
    const float* __restrict__ wg1, const float* __restrict__ wb1,
    const float* __restrict__ wm1, const float* __restrict__ wv1,
    const float* __restrict__ Ww1, const float* __restrict__ bw1,
    const float* __restrict__ wg2, const float* __restrict__ wb2,
    const float* __restrict__ wm2, const float* __restrict__ wv2,
    const float* __restrict__ Ww2, const float* __restrict__ bw2,
    float* __restrict__ out)
{
    __shared__ float  sWp1[9], sbp1v[3], spa[3], spbv[3];
    // per-warp (per point)
    __shared__ __align__(16) __half  ssw16 [NBW][16][72];  // w[k][c] fp16 (ldmatrix pad)
    __shared__ __align__(16) __half  svpe16[NBW][16][64];  // (xv+pe)[k][c] fp16
    __shared__ __align__(16) uint4   stvh  [NBW][16];      // {t0h2,t1h2,t2h2,j}
    __shared__ __align__(16) float   swl   [NBW][16][8];   // softmax weights

    const int tid = threadIdx.x;
    if (tid < 9) sWp1[tid] = Wp1[tid];
    if (tid < 3) {
        sbp1v[tid] = bp1[tid];
        float a = pg[tid] * rsqrtf(pv[tid] + EPSV);
        spa[tid] = a; spbv[tid] = pb[tid] - pm[tid] * a;
    }
    __syncthreads();

    const int w    = tid >> 5;
    const int lane = tid & 31;
    const int n    = blockIdx.x * NBW + w;
    const int q    = lane & 15;
    const int sub  = lane >> 4;
    const int c0   = 4 * q;      // channel quad owned in phases A & C

    // ---- Phase 0: neighbor t values + index (half2-packed) ----
    if (lane < 16) {
        int j = idx[n * 16 + lane];
        float4 pn = g_p4[n];
        float4 pj = g_p4[j];
        float prx = pj.x - pn.x;
        float pry = pj.y - pn.y;
        float prz = pj.z - pn.z;
        float u0 = prx * sWp1[0] + pry * sWp1[1] + prz * sWp1[2] + sbp1v[0];
        float u1 = prx * sWp1[3] + pry * sWp1[4] + prz * sWp1[5] + sbp1v[1];
        float u2 = prx * sWp1[6] + pry * sWp1[7] + prz * sWp1[8] + sbp1v[2];
        float t0 = fmaxf(0.f, fmaf(u0, spa[0], spbv[0]));
        float t1 = fmaxf(0.f, fmaf(u1, spa[1], spbv[1]));
        float t2 = fmaxf(0.f, fmaf(u2, spa[2], spbv[2]));
        stvh[w][lane] = make_uint4(f22h(t0, t0), f22h(t1, t1), f22h(t2, t2), (u32)j);
    }
    __syncwarp();

    // ---- Phase A: half2 gather + relation + pos-enc (no converts) ----
    {
        // xq quad (fp16, no conversion)
        u64 xqq = g_xq[n * 16 + q];
        const u32 xqA = (u32)xqq, xqB = (u32)(xqq >> 32);
        // Wp2 rows for 4 channels: 12 contiguous floats at c0*3 (16B-aligned)
        float4 wpr0 = *(const float4*)&Wp2[c0 * 3];
        float4 wpr1 = *(const float4*)&Wp2[c0 * 3 + 4];
        float4 wpr2 = *(const float4*)&Wp2[c0 * 3 + 8];
        const u32 wpA0 = f22h(wpr0.x, wpr0.w);   // {W[c0][0],   W[c0+1][0]}
        const u32 wpA1 = f22h(wpr0.y, wpr1.x);   // {W[c0][1],   W[c0+1][1]}
        const u32 wpA2 = f22h(wpr0.z, wpr1.y);   // {W[c0][2],   W[c0+1][2]}
        const u32 wpB0 = f22h(wpr1.z, wpr2.y);   // {W[c0+2][0], W[c0+3][0]}
        const u32 wpB1 = f22h(wpr1.w, wpr2.z);   // {W[c0+2][1], W[c0+3][1]}
        const u32 wpB2 = f22h(wpr2.x, wpr2.w);   // {W[c0+2][2], W[c0+3][2]}
        float4 bpv = *(const float4*)&bp2[c0];
        const u32 bpA = f22h(bpv.x, bpv.y), bpB = f22h(bpv.z, bpv.w);
        // folded BN1 (vector loads)
        float4 g1 = *(const float4*)&wg1[c0];
        float4 b1 = *(const float4*)&wb1[c0];
        float4 m1 = *(const float4*)&wm1[c0];
        float4 v1 = *(const float4*)&wv1[c0];
        float a0f = g1.x * rsqrtf(v1.x + EPSV);
        float a1f = g1.y * rsqrtf(v1.y + EPSV);
        float a2f = g1.z * rsqrtf(v1.z + EPSV);
        float a3f = g1.w * rsqrtf(v1.w + EPSV);
        const u32 a1A = f22h(a0f, a1f), a1B = f22h(a2f, a3f);
        const u32 b1A = f22h(b1.x - m1.x * a0f, b1.y - m1.y * a1f);
        const u32 b1B = f22h(b1.z - m1.z * a2f, b1.w - m1.w * a3f);

        #pragma unroll
        for (int it = 0; it < 8; ++it) {
            const int kk = 2 * it + sub;
            uint4 tv = stvh[w][kk];                        // LDS.128 bcast
            int j = (int)tv.w;
            ulonglong2 kv = g_xkv[j * 16 + q];             // LDG.128: xk|xv quads
            u32 kA = (u32)kv.x, kB = (u32)(kv.x >> 32);
            u32 vA = (u32)kv.y, vB = (u32)(kv.y >> 32);
            u32 peA = hfma2u(wpA0, tv.x, hfma2u(wpA1, tv.y, hfma2u(wpA2, tv.z, bpA)));
            u32 peB = hfma2u(wpB0, tv.x, hfma2u(wpB1, tv.y, hfma2u(wpB2, tv.z, bpB)));
            u32 rA  = hadd2u(hsub2u(kA, xqA), peA);
            u32 rB  = hadd2u(hsub2u(kB, xqB), peB);
            u32 wA  = hrelu2u(hfma2u(rA, a1A, b1A));
            u32 wB  = hrelu2u(hfma2u(rB, a1B, b1B));
            *(u64*)&ssw16[w][kk][c0]  = (u64)wA | ((u64)wB << 32);   // STS.64
            u32 vpA = hadd2u(vA, peA);
            u32 vpB = hadd2u(vB, peB);
            *(u64*)&svpe16[w][kk][c0] = (u64)vpA | ((u64)vpB << 32); // STS.64
        }
    }
    __syncwarp();

    // ---- Phase B: mma (w @ Ww1^T) -> bn2/relu -> mma (Ww2) -> softmax ----
    {
        const int nfr = lane >> 2;       // 0..7
        const int kfr = 2 * (lane & 3);  // 0,2,4,6

        u32 bf[4][2];
        #pragma unroll
        for (int ch = 0; ch < 4; ++ch) {
            const float* wr = &Ww1[nfr * 64 + ch * 16 + kfr];
            float2 wa = *(const float2*)&wr[0];
            float2 wb = *(const float2*)&wr[8];
            bf[ch][0] = f22h(wa.x, wa.y);
            bf[ch][1] = f22h(wb.x, wb.y);
        }
        float2 w2p = *(const float2*)&Ww2[nfr * 8 + kfr];
        const u32 bW2f = f22h(w2p.x, w2p.y);
        float2 bw1p = *(const float2*)&bw1[kfr];
        float2 g2p  = *(const float2*)&wg2[kfr];
        float2 v2p  = *(const float2*)&wv2[kfr];
        float2 b2p  = *(const float2*)&wb2[kfr];
        float2 m2p  = *(const float2*)&wm2[kfr];
        float2 bb2p = *(const float2*)&bw2[kfr];
        const float cbw1A = bw1p.x, cbw1B = bw1p.y;
        float tA = g2p.x * rsqrtf(v2p.x + EPSV);
        float tB = g2p.y * rsqrtf(v2p.y + EPSV);
        const float ca2A = tA, cb2A = b2p.x - m2p.x * tA;
        const float ca2B = tB, cb2B = b2p.y - m2p.y * tB;
        const float cbw2A = bb2p.x, cbw2B = bb2p.y;

        u32 afr[4][4];
        const int arow = lane & 15;
        const int acol = (lane >> 4) << 3;
        #pragma unroll
        for (int ch = 0; ch < 4; ++ch) {
            u32 ad = smem_u32(&ssw16[w][arow][ch * 16 + acol]);
            asm volatile("ldmatrix.sync.aligned.m8n8.x4.shared.b16 {%0,%1,%2,%3}, [%4];"
                : "=r"(afr[ch][0]), "=r"(afr[ch][1]), "=r"(afr[ch][2]), "=r"(afr[ch][3])
                : "r"(ad));
        }
        float d0 = 0.f, d1 = 0.f, d2 = 0.f, d3 = 0.f;
        #pragma unroll
        for (int ch = 0; ch < 4; ++ch) {
            asm volatile("mma.sync.aligned.m16n8k16.row.col.f32.f16.f16.f32 "
                "{%0,%1,%2,%3}, {%4,%5,%6,%7}, {%8,%9}, {%0,%1,%2,%3};"
                : "+f"(d0), "+f"(d1), "+f"(d2), "+f"(d3)
                : "r"(afr[ch][0]), "r"(afr[ch][1]), "r"(afr[ch][2]), "r"(afr[ch][3]),
                  "r"(bf[ch][0]), "r"(bf[ch][1]));
        }
        float h0 = fmaxf(0.f, fmaf(d0 + cbw1A, ca2A, cb2A));
        float h1 = fmaxf(0.f, fmaf(d1 + cbw1B, ca2B, cb2B));
        float h2 = fmaxf(0.f, fmaf(d2 + cbw1A, ca2A, cb2A));
        float h3 = fmaxf(0.f, fmaf(d3 + cbw1B, ca2B, cb2B));
        u32 ha0 = f22h(h0, h1), ha1 = f22h(h2, h3);
        float l0 = 0.f, l1 = 0.f, l2 = 0.f, l3 = 0.f;
        asm volatile("mma.sync.aligned.m16n8k8.row.col.f32.f16.f16.f32 "
            "{%0,%1,%2,%3}, {%4,%5}, {%6}, {%0,%1,%2,%3};"
            : "+f"(l0), "+f"(l1), "+f"(l2), "+f"(l3)
            : "r"(ha0), "r"(ha1), "r"(bW2f));
        l0 += cbw2A; l1 += cbw2B; l2 += cbw2A; l3 += cbw2B;

        float mA = fmaxf(l0, l2), mB = fmaxf(l1, l3);
        #pragma unroll
        for (int dlt = 4; dlt <= 16; dlt <<= 1) {
            mA = fmaxf(mA, __shfl_xor_sync(0xffffffffu, mA, dlt));
            mB = fmaxf(mB, __shfl_xor_sync(0xffffffffu, mB, dlt));
        }
        float e0 = __expf(l0 - mA), e1 = __expf(l1 - mB);
        float e2 = __expf(l2 - mA), e3 = __expf(l3 - mB);
        float sA = e0 + e2, sB = e1 + e3;
        #pragma unroll
        for (int dlt = 4; dlt <= 16; dlt <<= 1) {
            sA += __shfl_xor_sync(0xffffffffu, sA, dlt);
            sB += __shfl_xor_sync(0xffffffffu, sB, dlt);
        }
        float iA = 1.f / sA, iB = 1.f / sB;
        *(u64*)&swl[w][nfr][kfr]     = pk2(e0 * iA, e1 * iB);
        *(u64*)&swl[w][nfr + 8][kfr] = pk2(e2 * iA, e3 * iB);
    }
    __syncwarp();

    // ---- Phase C: pure smem weighted sum over neighbors (fp32 accum) ----
    {
        const int csq = c0 & 7;   // 0 or 4 -> aligned 16B into swl row

        u64 acc0 = 0ull, acc1 = 0ull;
        #pragma unroll
        for (int it = 0; it < 8; ++it) {
            const int kk = 2 * it + sub;
            u64 vq = *(const u64*)&svpe16[w][kk][c0];                 // LDS.64
            u64 vA, vB; h4_to_f22(vq, vA, vB);
            ulonglong2 g2 = *(const ulonglong2*)&swl[w][kk][csq];     // LDS.128
            acc0 = ffma2(vA, g2.x, acc0);
            acc1 = ffma2(vB, g2.y, acc1);
        }
        float o0, o1, o2, o3;
        upk2(acc0, o0, o1); upk2(acc1, o2, o3);
        o0 += __shfl_xor_sync(0xffffffffu, o0, 16);
        o1 += __shfl_xor_sync(0xffffffffu, o1, 16);
        o2 += __shfl_xor_sync(0xffffffffu, o2, 16);
        o3 += __shfl_xor_sync(0xffffffffu, o3, 16);
        if (sub == 0)
            *(float4*)&out[n * 64 + c0] = make_float4(o0, o1, o2, o3);
    }
}

// =====================================================================
extern "C" void kernel_launch(void* const* d_in, const int* in_sizes, int n_in,
                              void* d_out, int out_size)
{
    const float* p   = (const float*)d_in[0];
    const float* x   = (const float*)d_in[1];
    const int*   idx = (const int*)  d_in[2];
    const float* Wq  = (const float*)d_in[3];
    const float* bq  = (const float*)d_in[4];
    const float* Wk  = (const float*)d_in[5];
    const float* bk  = (const float*)d_in[6];
    const float* Wv  = (const float*)d_in[7];
    const float* bv  = (const float*)d_in[8];
    const float* Wp1 = (const float*)d_in[9];
    const float* bp1 = (const float*)d_in[10];
    const float* pg  = (const float*)d_in[11];
    const float* pb  = (const float*)d_in[12];
    const float* pm  = (const float*)d_in[13];
    const float* pv  = (const float*)d_in[14];
    const float* Wp2 = (const float*)d_in[15];
    const float* bp2 = (const float*)d_in[16];
    const float* wg1 = (const float*)d_in[17];
    const float* wb1 = (const float*)d_in[18];
    const float* wm1 = (const float*)d_in[19];
    const float* wv1 = (const float*)d_in[20];
    const float* Ww1 = (const float*)d_in[21];
    const float* bw1 = (const float*)d_in[22];
    const float* wg2 = (const float*)d_in[23];
    const float* wb2 = (const float*)d_in[24];
    const float* wm2 = (const float*)d_in[25];
    const float* wv2 = (const float*)d_in[26];
    const float* Ww2 = (const float*)d_in[27];
    const float* bw2 = (const float*)d_in[28];
    float* out = (float*)d_out;

    gemm_qkv_mma<<<NPTS / 64, 256>>>(x, p, Wq, bq, Wk, bk, Wv, bv);
    fused_pt<<<NPTS / NBW, 128>>>(idx, Wp1, bp1, pg, pb, pm, pv, Wp2, bp2,
                                  wg1, wb1, wm1, wv1, Ww1, bw1,
                                  wg2, wb2, wm2, wv2, Ww2, bw2, out);
}

// round 12
// speedup vs baseline: 2.9351x; 1.1807x over previous
#include <cuda_runtime.h>
#include <cuda_bf16.h>
#include <cuda_fp16.h>

typedef unsigned long long u64;
typedef unsigned int u32;

#define NPTS   65536
#define CCH    64
#define NSMP   16
#define CSW    8
#define EPSV   1e-5f
#define NBW    4   // warps per block in fused kernel
#define PPW    4   // points per warp (looped)

// ---------------- f32x2 helpers ----------------
__device__ __forceinline__ u64 pk2(float a, float b) {
    u64 r; asm("mov.b64 %0, {%1, %2};" : "=l"(r) : "f"(a), "f"(b)); return r;
}
__device__ __forceinline__ void upk2(u64 v, float& a, float& b) {
    asm("mov.b64 {%0, %1}, %2;" : "=f"(a), "=f"(b) : "l"(v));
}
__device__ __forceinline__ u64 ffma2(u64 a, u64 b, u64 c) {
    u64 d; asm("fma.rn.f32x2 %0, %1, %2, %3;" : "=l"(d) : "l"(a), "l"(b), "l"(c)); return d;
}
__device__ __forceinline__ u32 f22h(float a, float b) {
    __half2 h = __floats2half2_rn(a, b);
    return *reinterpret_cast<u32*>(&h);
}
__device__ __forceinline__ u32 smem_u32(const void* p) {
    return (u32)__cvta_generic_to_shared(p);
}
__device__ __forceinline__ void h4_to_f22(u64 h4, u64& loPair, u64& hiPair) {
    u32 lo = (u32)h4, hi = (u32)(h4 >> 32);
    __half2 hlo = *reinterpret_cast<__half2*>(&lo);
    __half2 hhi = *reinterpret_cast<__half2*>(&hi);
    float2 flo = __half22float2(hlo), fhi = __half22float2(hhi);
    loPair = pk2(flo.x, flo.y);
    hiPair = pk2(fhi.x, fhi.y);
}
// ---------------- half2-as-u32 helpers ----------------
__device__ __forceinline__ u32 hfma2u(u32 a, u32 b, u32 c) {
    __half2 r = __hfma2(*(__half2*)&a, *(__half2*)&b, *(__half2*)&c);
    return *(u32*)&r;
}
__device__ __forceinline__ u32 hadd2u(u32 a, u32 b) {
    __half2 r = __hadd2(*(__half2*)&a, *(__half2*)&b);
    return *(u32*)&r;
}
__device__ __forceinline__ u32 hsub2u(u32 a, u32 b) {
    __half2 r = __hsub2(*(__half2*)&a, *(__half2*)&b);
    return *(u32*)&r;
}
__device__ __forceinline__ u32 hrelu2u(u32 a) {
    __half2 z = __floats2half2_rn(0.f, 0.f);
    __half2 r = __hmax2(*(__half2*)&a, z);
    return *(u32*)&r;
}

// ---------------- scratch tables (fp16, L2-resident) ----------------
__device__ u64        g_xq [NPTS * CCH / 4];   // xq quads
__device__ ulonglong2 g_xkv[NPTS * 16];        // per row: 16 x {xk quad, xv quad}
__device__ float4     g_p4 [NPTS];             // padded coords

// =====================================================================
// Kernel 1: xq/xk/xv = x @ W^T + b via fp16 tensor-core MMA. (unchanged)
// =====================================================================
__global__ __launch_bounds__(256) void gemm_qkv_mma(
    const float* __restrict__ x, const float* __restrict__ p,
    const float* __restrict__ Wq, const float* __restrict__ bq,
    const float* __restrict__ Wk, const float* __restrict__ bk,
    const float* __restrict__ Wv, const float* __restrict__ bv)
{
    __shared__ __align__(16) __half sx[64][72];

    const int tid  = threadIdx.x;
    const int warp = tid >> 5;
    const int lane = tid & 31;
    const int row0 = blockIdx.x * 64;

    if (tid < 64) {
        const float* pr = &p[(row0 + tid) * 3];
        g_p4[row0 + tid] = make_float4(pr[0], pr[1], pr[2], 0.f);
    }

    {
        const int r  = tid & 63;
        const int kb = (tid >> 6) * 16;
        const float* xr = &x[(row0 + r) * 64 + kb];
        float4 v0 = *(const float4*)&xr[0];
        float4 v1 = *(const float4*)&xr[4];
        float4 v2 = *(const float4*)&xr[8];
        float4 v3 = *(const float4*)&xr[12];
        uint4 h0 = make_uint4(f22h(v0.x, v0.y), f22h(v0.z, v0.w),
                              f22h(v1.x, v1.y), f22h(v1.z, v1.w));
        uint4 h1 = make_uint4(f22h(v2.x, v2.y), f22h(v2.z, v2.w),
                              f22h(v3.x, v3.y), f22h(v3.z, v3.w));
        *(uint4*)&sx[r][kb]     = h0;
        *(uint4*)&sx[r][kb + 8] = h1;
    }
    __syncthreads();

    const int n0  = warp * 8;
    const int nn  = n0 + (lane >> 2);
    const int kfr = 2 * (lane & 3);

    const float* Ws[3] = {Wq, Wk, Wv};
    const float* Bs[3] = {bq, bk, bv};
    u32 bf[3][4][2];
    float bsx[3], bsy[3];
    #pragma unroll
    for (int m = 0; m < 3; ++m) {
        #pragma unroll
        for (int ks = 0; ks < 4; ++ks) {
            const float* wr = &Ws[m][nn * 64 + ks * 16 + kfr];
            float2 wa = *(const float2*)&wr[0];
            float2 wb = *(const float2*)&wr[8];
            bf[m][ks][0] = f22h(wa.x, wa.y);
            bf[m][ks][1] = f22h(wb.x, wb.y);
        }
        float2 bb = *(const float2*)&Bs[m][n0 + kfr];
        bsx[m] = bb.x; bsy[m] = bb.y;
    }

    const int pp   = (n0 + kfr) >> 1;
    const int qq   = pp >> 1;
    const int half = pp & 1;

    #pragma unroll
    for (int rt = 0; rt < 4; ++rt) {
        const int r0 = rt * 16;
        u32 afr[4][4];
        const int arow  = r0 + (lane & 15);
        const int acolb = (lane >> 4) << 3;
        #pragma unroll
        for (int ks = 0; ks < 4; ++ks) {
            u32 ad = smem_u32(&sx[arow][ks * 16 + acolb]);
            asm volatile("ldmatrix.sync.aligned.m8n8.x4.shared.b16 {%0,%1,%2,%3}, [%4];"
                : "=r"(afr[ks][0]), "=r"(afr[ks][1]), "=r"(afr[ks][2]), "=r"(afr[ks][3])
                : "r"(ad));
        }
        const int rowA = row0 + r0 + (lane >> 2);
        const int rowB = rowA + 8;
        #pragma unroll
        for (int m = 0; m < 3; ++m) {
            float d0 = 0.f, d1 = 0.f, d2 = 0.f, d3 = 0.f;
            #pragma unroll
            for (int ks = 0; ks < 4; ++ks) {
                asm volatile("mma.sync.aligned.m16n8k16.row.col.f32.f16.f16.f32 "
                    "{%0,%1,%2,%3}, {%4,%5,%6,%7}, {%8,%9}, {%0,%1,%2,%3};"
                    : "+f"(d0), "+f"(d1), "+f"(d2), "+f"(d3)
                    : "r"(afr[ks][0]), "r"(afr[ks][1]), "r"(afr[ks][2]), "r"(afr[ks][3]),
                      "r"(bf[m][ks][0]), "r"(bf[m][ks][1]));
            }
            d0 += bsx[m]; d1 += bsy[m]; d2 += bsx[m]; d3 += bsy[m];
            if (m == 0) {
                u32* o = (u32*)g_xq;
                o[rowA * 32 + pp] = f22h(d0, d1);
                o[rowB * 32 + pp] = f22h(d2, d3);
            } else {
                u32* o = (u32*)g_xkv;
                const int sub2 = (m == 1) ? 0 : 2;
                o[rowA * 64 + qq * 4 + sub2 + half] = f22h(d0, d1);
                o[rowB * 64 + qq * 4 + sub2 + half] = f22h(d2, d3);
            }
        }
    }
}

// =====================================================================
// Kernel 2: fused point-transformer. One warp handles PPW points; all
// point-invariant constants hoisted out of the loop (computed once).
// =====================================================================
__global__ void __launch_bounds__(128, 7) fused_pt(
    const int*   __restrict__ idx,
    const float* __restrict__ Wp1, const float* __restrict__ bp1,
    const float* __restrict__ pg,  const float* __restrict__ pb,
    const float* __restrict__ pm,  const float* __restrict__ pv,
    const float* __restrict__ Wp2, const float* __restrict__ bp2,
    const float* __restrict__ wg1, const float* __restrict__ wb1,
    const float* __restrict__ wm1, const float* __restrict__ wv1,
    const float* __restrict__ Ww1, const float* __restrict__ bw1,
    const float* __restrict__ wg2, const float* __restrict__ wb2,
    const float* __restrict__ wm2, const float* __restrict__ wv2,
    const float* __restrict__ Ww2, const float* __restrict__ bw2,
    float* __restrict__ out)
{
    __shared__ float  sWp1[9], sbp1v[3], spa[3], spbv[3];
    // per-warp buffers, reused across the point loop
    __shared__ __align__(16) __half  ssw16 [NBW][16][72];
    __shared__ __align__(16) __half  svpe16[NBW][16][64];
    __shared__ __align__(16) uint4   stvh  [NBW][16];
    __shared__ __align__(16) float   swl   [NBW][16][8];

    const int tid = threadIdx.x;
    if (tid < 9) sWp1[tid] = Wp1[tid];
    if (tid < 3) {
        sbp1v[tid] = bp1[tid];
        float a = pg[tid] * rsqrtf(pv[tid] + EPSV);
        spa[tid] = a; spbv[tid] = pb[tid] - pm[tid] * a;
    }
    __syncthreads();

    const int w    = tid >> 5;
    const int lane = tid & 31;
    const int q    = lane & 15;
    const int sub  = lane >> 4;
    const int c0   = 4 * q;

    // ======== hoisted point-invariant constants (once per warp) ========
    // Phase A constants
    float4 wpr0 = *(const float4*)&Wp2[c0 * 3];
    float4 wpr1 = *(const float4*)&Wp2[c0 * 3 + 4];
    float4 wpr2 = *(const float4*)&Wp2[c0 * 3 + 8];
    const u32 wpA0 = f22h(wpr0.x, wpr0.w);
    const u32 wpA1 = f22h(wpr0.y, wpr1.x);
    const u32 wpA2 = f22h(wpr0.z, wpr1.y);
    const u32 wpB0 = f22h(wpr1.z, wpr2.y);
    const u32 wpB1 = f22h(wpr1.w, wpr2.z);
    const u32 wpB2 = f22h(wpr2.x, wpr2.w);
    float4 bpv = *(const float4*)&bp2[c0];
    const u32 bpA = f22h(bpv.x, bpv.y), bpB = f22h(bpv.z, bpv.w);
    float4 g1 = *(const float4*)&wg1[c0];
    float4 b1 = *(const float4*)&wb1[c0];
    float4 m1 = *(const float4*)&wm1[c0];
    float4 v1 = *(const float4*)&wv1[c0];
    float a0f = g1.x * rsqrtf(v1.x + EPSV);
    float a1f = g1.y * rsqrtf(v1.y + EPSV);
    float a2f = g1.z * rsqrtf(v1.z + EPSV);
    float a3f = g1.w * rsqrtf(v1.w + EPSV);
    const u32 a1A = f22h(a0f, a1f), a1B = f22h(a2f, a3f);
    const u32 b1A = f22h(b1.x - m1.x * a0f, b1.y - m1.y * a1f);
    const u32 b1B = f22h(b1.z - m1.z * a2f, b1.w - m1.w * a3f);
    // Phase B constants
    const int nfr = lane >> 2;
    const int kfr = 2 * (lane & 3);
    u32 bfB[4][2];
    #pragma unroll
    for (int ch = 0; ch < 4; ++ch) {
        const float* wr = &Ww1[nfr * 64 + ch * 16 + kfr];
        float2 wa = *(const float2*)&wr[0];
        float2 wb = *(const float2*)&wr[8];
        bfB[ch][0] = f22h(wa.x, wa.y);
        bfB[ch][1] = f22h(wb.x, wb.y);
    }
    float2 w2p = *(const float2*)&Ww2[nfr * 8 + kfr];
    const u32 bW2f = f22h(w2p.x, w2p.y);
    float2 bw1p = *(const float2*)&bw1[kfr];
    float2 g2p  = *(const float2*)&wg2[kfr];
    float2 v2p  = *(const float2*)&wv2[kfr];
    float2 b2p  = *(const float2*)&wb2[kfr];
    float2 m2p  = *(const float2*)&wm2[kfr];
    float2 bb2p = *(const float2*)&bw2[kfr];
    const float cbw1A = bw1p.x, cbw1B = bw1p.y;
    float tAc = g2p.x * rsqrtf(v2p.x + EPSV);
    float tBc = g2p.y * rsqrtf(v2p.y + EPSV);
    const float ca2A = tAc, cb2A = b2p.x - m2p.x * tAc;
    const float ca2B = tBc, cb2B = b2p.y - m2p.y * tBc;
    const float cbw2A = bb2p.x, cbw2B = bb2p.y;
    // ===================================================================

    const int nbase = blockIdx.x * (NBW * PPW) + w * PPW;

    for (int pt = 0; pt < PPW; ++pt) {
        const int n = nbase + pt;

        // ---- Phase 0: neighbor t values + index (half2-packed) ----
        if (lane < 16) {
            int j = idx[n * 16 + lane];
            float4 pn = g_p4[n];
            float4 pj = g_p4[j];
            float prx = pj.x - pn.x;
            float pry = pj.y - pn.y;
            float prz = pj.z - pn.z;
            float u0 = prx * sWp1[0] + pry * sWp1[1] + prz * sWp1[2] + sbp1v[0];
            float u1 = prx * sWp1[3] + pry * sWp1[4] + prz * sWp1[5] + sbp1v[1];
            float u2 = prx * sWp1[6] + pry * sWp1[7] + prz * sWp1[8] + sbp1v[2];
            float t0 = fmaxf(0.f, fmaf(u0, spa[0], spbv[0]));
            float t1 = fmaxf(0.f, fmaf(u1, spa[1], spbv[1]));
            float t2 = fmaxf(0.f, fmaf(u2, spa[2], spbv[2]));
            stvh[w][lane] = make_uint4(f22h(t0, t0), f22h(t1, t1), f22h(t2, t2), (u32)j);
        }
        __syncwarp();

        // ---- Phase A: half2 gather + relation + pos-enc ----
        {
            u64 xqq = g_xq[n * 16 + q];
            const u32 xqA = (u32)xqq, xqB = (u32)(xqq >> 32);

            #pragma unroll
            for (int it = 0; it < 8; ++it) {
                const int kk = 2 * it + sub;
                uint4 tv = stvh[w][kk];
                int j = (int)tv.w;
                ulonglong2 kv = g_xkv[j * 16 + q];
                u32 kA = (u32)kv.x, kB = (u32)(kv.x >> 32);
                u32 vA = (u32)kv.y, vB = (u32)(kv.y >> 32);
                u32 peA = hfma2u(wpA0, tv.x, hfma2u(wpA1, tv.y, hfma2u(wpA2, tv.z, bpA)));
                u32 peB = hfma2u(wpB0, tv.x, hfma2u(wpB1, tv.y, hfma2u(wpB2, tv.z, bpB)));
                u32 rA  = hadd2u(hsub2u(kA, xqA), peA);
                u32 rB  = hadd2u(hsub2u(kB, xqB), peB);
                u32 wA  = hrelu2u(hfma2u(rA, a1A, b1A));
                u32 wB  = hrelu2u(hfma2u(rB, a1B, b1B));
                *(u64*)&ssw16[w][kk][c0]  = (u64)wA | ((u64)wB << 32);
                u32 vpA = hadd2u(vA, peA);
                u32 vpB = hadd2u(vB, peB);
                *(u64*)&svpe16[w][kk][c0] = (u64)vpA | ((u64)vpB << 32);
            }
        }
        __syncwarp();

        // ---- Phase B: mma -> bn2/relu -> mma -> softmax ----
        {
            u32 afr[4][4];
            const int arow = lane & 15;
            const int acol = (lane >> 4) << 3;
            #pragma unroll
            for (int ch = 0; ch < 4; ++ch) {
                u32 ad = smem_u32(&ssw16[w][arow][ch * 16 + acol]);
                asm volatile("ldmatrix.sync.aligned.m8n8.x4.shared.b16 {%0,%1,%2,%3}, [%4];"
                    : "=r"(afr[ch][0]), "=r"(afr[ch][1]), "=r"(afr[ch][2]), "=r"(afr[ch][3])
                    : "r"(ad));
            }
            float d0 = 0.f, d1 = 0.f, d2 = 0.f, d3 = 0.f;
            #pragma unroll
            for (int ch = 0; ch < 4; ++ch) {
                asm volatile("mma.sync.aligned.m16n8k16.row.col.f32.f16.f16.f32 "
                    "{%0,%1,%2,%3}, {%4,%5,%6,%7}, {%8,%9}, {%0,%1,%2,%3};"
                    : "+f"(d0), "+f"(d1), "+f"(d2), "+f"(d3)
                    : "r"(afr[ch][0]), "r"(afr[ch][1]), "r"(afr[ch][2]), "r"(afr[ch][3]),
                      "r"(bfB[ch][0]), "r"(bfB[ch][1]));
            }
            float h0 = fmaxf(0.f, fmaf(d0 + cbw1A, ca2A, cb2A));
            float h1 = fmaxf(0.f, fmaf(d1 + cbw1B, ca2B, cb2B));
            float h2 = fmaxf(0.f, fmaf(d2 + cbw1A, ca2A, cb2A));
            float h3 = fmaxf(0.f, fmaf(d3 + cbw1B, ca2B, cb2B));
            u32 ha0 = f22h(h0, h1), ha1 = f22h(h2, h3);
            float l0 = 0.f, l1 = 0.f, l2 = 0.f, l3 = 0.f;
            asm volatile("mma.sync.aligned.m16n8k8.row.col.f32.f16.f16.f32 "
                "{%0,%1,%2,%3}, {%4,%5}, {%6}, {%0,%1,%2,%3};"
                : "+f"(l0), "+f"(l1), "+f"(l2), "+f"(l3)
                : "r"(ha0), "r"(ha1), "r"(bW2f));
            l0 += cbw2A; l1 += cbw2B; l2 += cbw2A; l3 += cbw2B;

            float mA = fmaxf(l0, l2), mB = fmaxf(l1, l3);
            #pragma unroll
            for (int dlt = 4; dlt <= 16; dlt <<= 1) {
                mA = fmaxf(mA, __shfl_xor_sync(0xffffffffu, mA, dlt));
                mB = fmaxf(mB, __shfl_xor_sync(0xffffffffu, mB, dlt));
            }
            float e0 = __expf(l0 - mA), e1 = __expf(l1 - mB);
            float e2 = __expf(l2 - mA), e3 = __expf(l3 - mB);
            float sA = e0 + e2, sB = e1 + e3;
            #pragma unroll
            for (int dlt = 4; dlt <= 16; dlt <<= 1) {
                sA += __shfl_xor_sync(0xffffffffu, sA, dlt);
                sB += __shfl_xor_sync(0xffffffffu, sB, dlt);
            }
            float iA = 1.f / sA, iB = 1.f / sB;
            *(u64*)&swl[w][nfr][kfr]     = pk2(e0 * iA, e1 * iB);
            *(u64*)&swl[w][nfr + 8][kfr] = pk2(e2 * iA, e3 * iB);
        }
        __syncwarp();

        // ---- Phase C: pure smem weighted sum (fp32 accum) ----
        {
            const int csq = c0 & 7;

            u64 acc0 = 0ull, acc1 = 0ull;
            #pragma unroll
            for (int it = 0; it < 8; ++it) {
                const int kk = 2 * it + sub;
                u64 vq = *(const u64*)&svpe16[w][kk][c0];
                u64 vA, vB; h4_to_f22(vq, vA, vB);
                ulonglong2 g2 = *(const ulonglong2*)&swl[w][kk][csq];
                acc0 = ffma2(vA, g2.x, acc0);
                acc1 = ffma2(vB, g2.y, acc1);
            }
            float o0, o1, o2, o3;
            upk2(acc0, o0, o1); upk2(acc1, o2, o3);
            o0 += __shfl_xor_sync(0xffffffffu, o0, 16);
            o1 += __shfl_xor_sync(0xffffffffu, o1, 16);
            o2 += __shfl_xor_sync(0xffffffffu, o2, 16);
            o3 += __shfl_xor_sync(0xffffffffu, o3, 16);
            if (sub == 0)
                *(float4*)&out[n * 64 + c0] = make_float4(o0, o1, o2, o3);
        }
        __syncwarp();
    }
}

// =====================================================================
extern "C" void kernel_launch(void* const* d_in, const int* in_sizes, int n_in,
                              void* d_out, int out_size)
{
    const float* p   = (const float*)d_in[0];
    const float* x   = (const float*)d_in[1];
    const int*   idx = (const int*)  d_in[2];
    const float* Wq  = (const float*)d_in[3];
    const float* bq  = (const float*)d_in[4];
    const float* Wk  = (const float*)d_in[5];
    const float* bk  = (const float*)d_in[6];
    const float* Wv  = (const float*)d_in[7];
    const float* bv  = (const float*)d_in[8];
    const float* Wp1 = (const float*)d_in[9];
    const float* bp1 = (const float*)d_in[10];
    const float* pg  = (const float*)d_in[11];
    const float* pb  = (const float*)d_in[12];
    const float* pm  = (const float*)d_in[13];
    const float* pv  = (const float*)d_in[14];
    const float* Wp2 = (const float*)d_in[15];
    const float* bp2 = (const float*)d_in[16];
    const float* wg1 = (const float*)d_in[17];
    const float* wb1 = (const float*)d_in[18];
    const float* wm1 = (const float*)d_in[19];
    const float* wv1 = (const float*)d_in[20];
    const float* Ww1 = (const float*)d_in[21];
    const float* bw1 = (const float*)d_in[22];
    const float* wg2 = (const float*)d_in[23];
    const float* wb2 = (const float*)d_in[24];
    const float* wm2 = (const float*)d_in[25];
    const float* wv2 = (const float*)d_in[26];
    const float* Ww2 = (const float*)d_in[27];
    const float* bw2 = (const float*)d_in[28];
    float* out = (float*)d_out;

    gemm_qkv_mma<<<NPTS / 64, 256>>>(x, p, Wq, bq, Wk, bk, Wv, bv);
    fused_pt<<<NPTS / (NBW * PPW), 128>>>(idx, Wp1, bp1, pg, pb, pm, pv, Wp2, bp2,
                                          wg1, wb1, wm1, wv1, Ww1, bw1,
                                          wg2, wb2, wm2, wv2, Ww2, bw2, out);
}

// round 13
// speedup vs baseline: 3.1688x; 1.0796x over previous
#include <cuda_runtime.h>
#include <cuda_bf16.h>
#include <cuda_fp16.h>

typedef unsigned long long u64;
typedef unsigned int u32;

#define NPTS   65536
#define CCH    64
#define NSMP   16
#define CSW    8
#define EPSV   1e-5f
#define NBW    4   // warps per block in fused kernel
#define PPW    4   // points per warp (looped)

// ---------------- f32x2 helpers ----------------
__device__ __forceinline__ u64 pk2(float a, float b) {
    u64 r; asm("mov.b64 %0, {%1, %2};" : "=l"(r) : "f"(a), "f"(b)); return r;
}
__device__ __forceinline__ void upk2(u64 v, float& a, float& b) {
    asm("mov.b64 {%0, %1}, %2;" : "=f"(a), "=f"(b) : "l"(v));
}
__device__ __forceinline__ u64 ffma2(u64 a, u64 b, u64 c) {
    u64 d; asm("fma.rn.f32x2 %0, %1, %2, %3;" : "=l"(d) : "l"(a), "l"(b), "l"(c)); return d;
}
__device__ __forceinline__ u32 f22h(float a, float b) {
    __half2 h = __floats2half2_rn(a, b);
    return *reinterpret_cast<u32*>(&h);
}
__device__ __forceinline__ u32 smem_u32(const void* p) {
    return (u32)__cvta_generic_to_shared(p);
}
__device__ __forceinline__ void h4_to_f22(u64 h4, u64& loPair, u64& hiPair) {
    u32 lo = (u32)h4, hi = (u32)(h4 >> 32);
    __half2 hlo = *reinterpret_cast<__half2*>(&lo);
    __half2 hhi = *reinterpret_cast<__half2*>(&hi);
    float2 flo = __half22float2(hlo), fhi = __half22float2(hhi);
    loPair = pk2(flo.x, flo.y);
    hiPair = pk2(fhi.x, fhi.y);
}
// ---------------- half2-as-u32 helpers ----------------
__device__ __forceinline__ u32 hfma2u(u32 a, u32 b, u32 c) {
    __half2 r = __hfma2(*(__half2*)&a, *(__half2*)&b, *(__half2*)&c);
    return *(u32*)&r;
}
__device__ __forceinline__ u32 hadd2u(u32 a, u32 b) {
    __half2 r = __hadd2(*(__half2*)&a, *(__half2*)&b);
    return *(u32*)&r;
}
__device__ __forceinline__ u32 hsub2u(u32 a, u32 b) {
    __half2 r = __hsub2(*(__half2*)&a, *(__half2*)&b);
    return *(u32*)&r;
}
__device__ __forceinline__ u32 hrelu2u(u32 a) {
    __half2 z = __floats2half2_rn(0.f, 0.f);
    __half2 r = __hmax2(*(__half2*)&a, z);
    return *(u32*)&r;
}

// ---------------- scratch tables (fp16, L2-resident) ----------------
__device__ u64        g_xq [NPTS * CCH / 4];   // xq quads
__device__ ulonglong2 g_xkv[NPTS * 16];        // per row: 16 x {xk quad, xv quad}
__device__ float4     g_p4 [NPTS];             // padded coords

// =====================================================================
// Kernel 1: xq/xk/xv = x @ W^T + b via fp16 tensor-core MMA. (unchanged)
// =====================================================================
__global__ __launch_bounds__(256) void gemm_qkv_mma(
    const float* __restrict__ x, const float* __restrict__ p,
    const float* __restrict__ Wq, const float* __restrict__ bq,
    const float* __restrict__ Wk, const float* __restrict__ bk,
    const float* __restrict__ Wv, const float* __restrict__ bv)
{
    __shared__ __align__(16) __half sx[64][72];

    const int tid  = threadIdx.x;
    const int warp = tid >> 5;
    const int lane = tid & 31;
    const int row0 = blockIdx.x * 64;

    if (tid < 64) {
        const float* pr = &p[(row0 + tid) * 3];
        g_p4[row0 + tid] = make_float4(pr[0], pr[1], pr[2], 0.f);
    }

    {
        const int r  = tid & 63;
        const int kb = (tid >> 6) * 16;
        const float* xr = &x[(row0 + r) * 64 + kb];
        float4 v0 = *(const float4*)&xr[0];
        float4 v1 = *(const float4*)&xr[4];
        float4 v2 = *(const float4*)&xr[8];
        float4 v3 = *(const float4*)&xr[12];
        uint4 h0 = make_uint4(f22h(v0.x, v0.y), f22h(v0.z, v0.w),
                              f22h(v1.x, v1.y), f22h(v1.z, v1.w));
        uint4 h1 = make_uint4(f22h(v2.x, v2.y), f22h(v2.z, v2.w),
                              f22h(v3.x, v3.y), f22h(v3.z, v3.w));
        *(uint4*)&sx[r][kb]     = h0;
        *(uint4*)&sx[r][kb + 8] = h1;
    }
    __syncthreads();

    const int n0  = warp * 8;
    const int nn  = n0 + (lane >> 2);
    const int kfr = 2 * (lane & 3);

    const float* Ws[3] = {Wq, Wk, Wv};
    const float* Bs[3] = {bq, bk, bv};
    u32 bf[3][4][2];
    float bsx[3], bsy[3];
    #pragma unroll
    for (int m = 0; m < 3; ++m) {
        #pragma unroll
        for (int ks = 0; ks < 4; ++ks) {
            const float* wr = &Ws[m][nn * 64 + ks * 16 + kfr];
            float2 wa = *(const float2*)&wr[0];
            float2 wb = *(const float2*)&wr[8];
            bf[m][ks][0] = f22h(wa.x, wa.y);
            bf[m][ks][1] = f22h(wb.x, wb.y);
        }
        float2 bb = *(const float2*)&Bs[m][n0 + kfr];
        bsx[m] = bb.x; bsy[m] = bb.y;
    }

    const int pp   = (n0 + kfr) >> 1;
    const int qq   = pp >> 1;
    const int half = pp & 1;

    #pragma unroll
    for (int rt = 0; rt < 4; ++rt) {
        const int r0 = rt * 16;
        u32 afr[4][4];
        const int arow  = r0 + (lane & 15);
        const int acolb = (lane >> 4) << 3;
        #pragma unroll
        for (int ks = 0; ks < 4; ++ks) {
            u32 ad = smem_u32(&sx[arow][ks * 16 + acolb]);
            asm volatile("ldmatrix.sync.aligned.m8n8.x4.shared.b16 {%0,%1,%2,%3}, [%4];"
                : "=r"(afr[ks][0]), "=r"(afr[ks][1]), "=r"(afr[ks][2]), "=r"(afr[ks][3])
                : "r"(ad));
        }
        const int rowA = row0 + r0 + (lane >> 2);
        const int rowB = rowA + 8;
        #pragma unroll
        for (int m = 0; m < 3; ++m) {
            float d0 = 0.f, d1 = 0.f, d2 = 0.f, d3 = 0.f;
            #pragma unroll
            for (int ks = 0; ks < 4; ++ks) {
                asm volatile("mma.sync.aligned.m16n8k16.row.col.f32.f16.f16.f32 "
                    "{%0,%1,%2,%3}, {%4,%5,%6,%7}, {%8,%9}, {%0,%1,%2,%3};"
                    : "+f"(d0), "+f"(d1), "+f"(d2), "+f"(d3)
                    : "r"(afr[ks][0]), "r"(afr[ks][1]), "r"(afr[ks][2]), "r"(afr[ks][3]),
                      "r"(bf[m][ks][0]), "r"(bf[m][ks][1]));
            }
            d0 += bsx[m]; d1 += bsy[m]; d2 += bsx[m]; d3 += bsy[m];
            if (m == 0) {
                u32* o = (u32*)g_xq;
                o[rowA * 32 + pp] = f22h(d0, d1);
                o[rowB * 32 + pp] = f22h(d2, d3);
            } else {
                u32* o = (u32*)g_xkv;
                const int sub2 = (m == 1) ? 0 : 2;
                o[rowA * 64 + qq * 4 + sub2 + half] = f22h(d0, d1);
                o[rowB * 64 + qq * 4 + sub2 + half] = f22h(d2, d3);
            }
        }
    }
}

// =====================================================================
// Kernel 2: fused point-transformer. PPW points/warp; Phase B constants
// staged in smem (built once per block) to fit the 64-reg / 8-block cap.
// =====================================================================
__global__ void __launch_bounds__(128, 8) fused_pt(
    const int*   __restrict__ idx,
    const float* __restrict__ Wp1, const float* __restrict__ bp1,
    const float* __restrict__ pg,  const float* __restrict__ pb,
    const float* __restrict__ pm,  const float* __restrict__ pv,
    const float* __restrict__ Wp2, const float* __restrict__ bp2,
    const float* __restrict__ wg1, const float* __restrict__ wb1,
    const float* __restrict__ wm1, const float* __restrict__ wv1,
    const float* __restrict__ Ww1, const float* __restrict__ bw1,
    const float* __restrict__ wg2, const float* __restrict__ wb2,
    const float* __restrict__ wm2, const float* __restrict__ wv2,
    const float* __restrict__ Ww2, const float* __restrict__ bw2,
    float* __restrict__ out)
{
    __shared__ float  sWp1[9], sbp1v[3], spa[3], spbv[3];
    __shared__ __align__(16) uint4   sBc[32][5];   // per-lane Phase B constants
    // per-warp buffers, reused across the point loop
    __shared__ __align__(16) __half  ssw16 [NBW][16][72];
    __shared__ __align__(16) __half  svpe16[NBW][16][64];
    __shared__ __align__(16) uint4   stvh  [NBW][16];
    __shared__ __align__(16) float   swl   [NBW][16][8];

    const int tid = threadIdx.x;
    if (tid < 9) sWp1[tid] = Wp1[tid];
    if (tid < 3) {
        sbp1v[tid] = bp1[tid];
        float a = pg[tid] * rsqrtf(pv[tid] + EPSV);
        spa[tid] = a; spbv[tid] = pb[tid] - pm[tid] * a;
    }
    // warp 0 builds the per-lane Phase B constant table (identical ∀ warps)
    if (tid < 32) {
        const int nfr = tid >> 2;
        const int kfr = 2 * (tid & 3);
        u32 bfB[8];
        #pragma unroll
        for (int ch = 0; ch < 4; ++ch) {
            const float* wr = &Ww1[nfr * 64 + ch * 16 + kfr];
            float2 wa = *(const float2*)&wr[0];
            float2 wb = *(const float2*)&wr[8];
            bfB[2 * ch]     = f22h(wa.x, wa.y);
            bfB[2 * ch + 1] = f22h(wb.x, wb.y);
        }
        float2 w2p  = *(const float2*)&Ww2[nfr * 8 + kfr];
        float2 bw1p = *(const float2*)&bw1[kfr];
        float2 g2p  = *(const float2*)&wg2[kfr];
        float2 v2p  = *(const float2*)&wv2[kfr];
        float2 b2p  = *(const float2*)&wb2[kfr];
        float2 m2p  = *(const float2*)&wm2[kfr];
        float2 bb2p = *(const float2*)&bw2[kfr];
        float tA = g2p.x * rsqrtf(v2p.x + EPSV);
        float tB = g2p.y * rsqrtf(v2p.y + EPSV);
        sBc[tid][0] = make_uint4(bfB[0], bfB[1], bfB[2], bfB[3]);
        sBc[tid][1] = make_uint4(bfB[4], bfB[5], bfB[6], bfB[7]);
        sBc[tid][2] = make_uint4(f22h(w2p.x, w2p.y),
                                 __float_as_uint(bw1p.x),
                                 __float_as_uint(bw1p.y),
                                 __float_as_uint(tA));
        sBc[tid][3] = make_uint4(__float_as_uint(tB),
                                 __float_as_uint(b2p.x - m2p.x * tA),
                                 __float_as_uint(b2p.y - m2p.y * tB),
                                 __float_as_uint(bb2p.x));
        sBc[tid][4] = make_uint4(__float_as_uint(bb2p.y), 0u, 0u, 0u);
    }
    __syncthreads();

    const int w    = tid >> 5;
    const int lane = tid & 31;
    const int q    = lane & 15;
    const int sub  = lane >> 4;
    const int c0   = 4 * q;

    // ======== hoisted Phase A constants (registers, once per warp) ========
    float4 wpr0 = *(const float4*)&Wp2[c0 * 3];
    float4 wpr1 = *(const float4*)&Wp2[c0 * 3 + 4];
    float4 wpr2 = *(const float4*)&Wp2[c0 * 3 + 8];
    const u32 wpA0 = f22h(wpr0.x, wpr0.w);
    const u32 wpA1 = f22h(wpr0.y, wpr1.x);
    const u32 wpA2 = f22h(wpr0.z, wpr1.y);
    const u32 wpB0 = f22h(wpr1.z, wpr2.y);
    const u32 wpB1 = f22h(wpr1.w, wpr2.z);
    const u32 wpB2 = f22h(wpr2.x, wpr2.w);
    float4 bpv = *(const float4*)&bp2[c0];
    const u32 bpA = f22h(bpv.x, bpv.y), bpB = f22h(bpv.z, bpv.w);
    float4 g1 = *(const float4*)&wg1[c0];
    float4 b1 = *(const float4*)&wb1[c0];
    float4 m1 = *(const float4*)&wm1[c0];
    float4 v1 = *(const float4*)&wv1[c0];
    float a0f = g1.x * rsqrtf(v1.x + EPSV);
    float a1f = g1.y * rsqrtf(v1.y + EPSV);
    float a2f = g1.z * rsqrtf(v1.z + EPSV);
    float a3f = g1.w * rsqrtf(v1.w + EPSV);
    const u32 a1A = f22h(a0f, a1f), a1B = f22h(a2f, a3f);
    const u32 b1A = f22h(b1.x - m1.x * a0f, b1.y - m1.y * a1f);
    const u32 b1B = f22h(b1.z - m1.z * a2f, b1.w - m1.w * a3f);
    // ======================================================================

    const int nfr = lane >> 2;
    const int kfr = 2 * (lane & 3);
    const int nbase = blockIdx.x * (NBW * PPW) + w * PPW;

    for (int pt = 0; pt < PPW; ++pt) {
        const int n = nbase + pt;

        // ---- Phase 0: neighbor t values + index (half2-packed) ----
        if (lane < 16) {
            int j = idx[n * 16 + lane];
            float4 pn = g_p4[n];
            float4 pj = g_p4[j];
            float prx = pj.x - pn.x;
            float pry = pj.y - pn.y;
            float prz = pj.z - pn.z;
            float u0 = prx * sWp1[0] + pry * sWp1[1] + prz * sWp1[2] + sbp1v[0];
            float u1 = prx * sWp1[3] + pry * sWp1[4] + prz * sWp1[5] + sbp1v[1];
            float u2 = prx * sWp1[6] + pry * sWp1[7] + prz * sWp1[8] + sbp1v[2];
            float t0 = fmaxf(0.f, fmaf(u0, spa[0], spbv[0]));
            float t1 = fmaxf(0.f, fmaf(u1, spa[1], spbv[1]));
            float t2 = fmaxf(0.f, fmaf(u2, spa[2], spbv[2]));
            stvh[w][lane] = make_uint4(f22h(t0, t0), f22h(t1, t1), f22h(t2, t2), (u32)j);
        }
        __syncwarp();

        // ---- Phase A: half2 gather + relation + pos-enc, 2 batches of 4 ----
        {
            u64 xqq = g_xq[n * 16 + q];
            const u32 xqA = (u32)xqq, xqB = (u32)(xqq >> 32);

            #pragma unroll
            for (int hb = 0; hb < 2; ++hb) {
                uint4 tv[4];
                ulonglong2 kv[4];
                // batch loads first (MLP=4)
                #pragma unroll
                for (int i = 0; i < 4; ++i) {
                    const int kk = 8 * hb + 2 * i + sub;
                    tv[i] = stvh[w][kk];
                    kv[i] = g_xkv[(int)tv[i].w * 16 + q];
                }
                #pragma unroll
                for (int i = 0; i < 4; ++i) {
                    const int kk = 8 * hb + 2 * i + sub;
                    u32 kA = (u32)kv[i].x, kB = (u32)(kv[i].x >> 32);
                    u32 vA = (u32)kv[i].y, vB = (u32)(kv[i].y >> 32);
                    u32 peA = hfma2u(wpA0, tv[i].x, hfma2u(wpA1, tv[i].y, hfma2u(wpA2, tv[i].z, bpA)));
                    u32 peB = hfma2u(wpB0, tv[i].x, hfma2u(wpB1, tv[i].y, hfma2u(wpB2, tv[i].z, bpB)));
                    u32 rA  = hadd2u(hsub2u(kA, xqA), peA);
                    u32 rB  = hadd2u(hsub2u(kB, xqB), peB);
                    u32 wA  = hrelu2u(hfma2u(rA, a1A, b1A));
                    u32 wB  = hrelu2u(hfma2u(rB, a1B, b1B));
                    *(u64*)&ssw16[w][kk][c0]  = (u64)wA | ((u64)wB << 32);
                    u32 vpA = hadd2u(vA, peA);
                    u32 vpB = hadd2u(vB, peB);
                    *(u64*)&svpe16[w][kk][c0] = (u64)vpA | ((u64)vpB << 32);
                }
            }
        }
        __syncwarp();

        // ---- Phase B: mma -> bn2/relu -> mma -> softmax ----
        {
            uint4 cb0 = sBc[lane][0];
            uint4 cb1 = sBc[lane][1];
            uint4 cb2 = sBc[lane][2];
            uint4 cb3 = sBc[lane][3];
            uint4 cb4 = sBc[lane][4];
            const u32 bW2f = cb2.x;
            const float cbw1A = __uint_as_float(cb2.y);
            const float cbw1B = __uint_as_float(cb2.z);
            const float ca2A  = __uint_as_float(cb2.w);
            const float ca2B  = __uint_as_float(cb3.x);
            const float cb2A  = __uint_as_float(cb3.y);
            const float cb2B  = __uint_as_float(cb3.z);
            const float cbw2A = __uint_as_float(cb3.w);
            const float cbw2B = __uint_as_float(cb4.x);

            u32 afr[4][4];
            const int arow = lane & 15;
            const int acol = (lane >> 4) << 3;
            #pragma unroll
            for (int ch = 0; ch < 4; ++ch) {
                u32 ad = smem_u32(&ssw16[w][arow][ch * 16 + acol]);
                asm volatile("ldmatrix.sync.aligned.m8n8.x4.shared.b16 {%0,%1,%2,%3}, [%4];"
                    : "=r"(afr[ch][0]), "=r"(afr[ch][1]), "=r"(afr[ch][2]), "=r"(afr[ch][3])
                    : "r"(ad));
            }
            float d0 = 0.f, d1 = 0.f, d2 = 0.f, d3 = 0.f;
            asm volatile("mma.sync.aligned.m16n8k16.row.col.f32.f16.f16.f32 "
                "{%0,%1,%2,%3}, {%4,%5,%6,%7}, {%8,%9}, {%0,%1,%2,%3};"
                : "+f"(d0), "+f"(d1), "+f"(d2), "+f"(d3)
                : "r"(afr[0][0]), "r"(afr[0][1]), "r"(afr[0][2]), "r"(afr[0][3]),
                  "r"(cb0.x), "r"(cb0.y));
            asm volatile("mma.sync.aligned.m16n8k16.row.col.f32.f16.f16.f32 "
                "{%0,%1,%2,%3}, {%4,%5,%6,%7}, {%8,%9}, {%0,%1,%2,%3};"
                : "+f"(d0), "+f"(d1), "+f"(d2), "+f"(d3)
                : "r"(afr[1][0]), "r"(afr[1][1]), "r"(afr[1][2]), "r"(afr[1][3]),
                  "r"(cb0.z), "r"(cb0.w));
            asm volatile("mma.sync.aligned.m16n8k16.row.col.f32.f16.f16.f32 "
                "{%0,%1,%2,%3}, {%4,%5,%6,%7}, {%8,%9}, {%0,%1,%2,%3};"
                : "+f"(d0), "+f"(d1), "+f"(d2), "+f"(d3)
                : "r"(afr[2][0]), "r"(afr[2][1]), "r"(afr[2][2]), "r"(afr[2][3]),
                  "r"(cb1.x), "r"(cb1.y));
            asm volatile("mma.sync.aligned.m16n8k16.row.col.f32.f16.f16.f32 "
                "{%0,%1,%2,%3}, {%4,%5,%6,%7}, {%8,%9}, {%0,%1,%2,%3};"
                : "+f"(d0), "+f"(d1), "+f"(d2), "+f"(d3)
                : "r"(afr[3][0]), "r"(afr[3][1]), "r"(afr[3][2]), "r"(afr[3][3]),
                  "r"(cb1.z), "r"(cb1.w));

            float h0 = fmaxf(0.f, fmaf(d0 + cbw1A, ca2A, cb2A));
            float h1 = fmaxf(0.f, fmaf(d1 + cbw1B, ca2B, cb2B));
            float h2 = fmaxf(0.f, fmaf(d2 + cbw1A, ca2A, cb2A));
            float h3 = fmaxf(0.f, fmaf(d3 + cbw1B, ca2B, cb2B));
            u32 ha0 = f22h(h0, h1), ha1 = f22h(h2, h3);
            float l0 = 0.f, l1 = 0.f, l2 = 0.f, l3 = 0.f;
            asm volatile("mma.sync.aligned.m16n8k8.row.col.f32.f16.f16.f32 "
                "{%0,%1,%2,%3}, {%4,%5}, {%6}, {%0,%1,%2,%3};"
                : "+f"(l0), "+f"(l1), "+f"(l2), "+f"(l3)
                : "r"(ha0), "r"(ha1), "r"(bW2f));
            l0 += cbw2A; l1 += cbw2B; l2 += cbw2A; l3 += cbw2B;

            float mA = fmaxf(l0, l2), mB = fmaxf(l1, l3);
            #pragma unroll
            for (int dlt = 4; dlt <= 16; dlt <<= 1) {
                mA = fmaxf(mA, __shfl_xor_sync(0xffffffffu, mA, dlt));
                mB = fmaxf(mB, __shfl_xor_sync(0xffffffffu, mB, dlt));
            }
            float e0 = __expf(l0 - mA), e1 = __expf(l1 - mB);
            float e2 = __expf(l2 - mA), e3 = __expf(l3 - mB);
            float sA = e0 + e2, sB = e1 + e3;
            #pragma unroll
            for (int dlt = 4; dlt <= 16; dlt <<= 1) {
                sA += __shfl_xor_sync(0xffffffffu, sA, dlt);
                sB += __shfl_xor_sync(0xffffffffu, sB, dlt);
            }
            float iA = 1.f / sA, iB = 1.f / sB;
            *(u64*)&swl[w][nfr][kfr]     = pk2(e0 * iA, e1 * iB);
            *(u64*)&swl[w][nfr + 8][kfr] = pk2(e2 * iA, e3 * iB);
        }
        __syncwarp();

        // ---- Phase C: pure smem weighted sum (fp32 accum) ----
        {
            const int csq = c0 & 7;

            u64 acc0 = 0ull, acc1 = 0ull;
            #pragma unroll
            for (int it = 0; it < 8; ++it) {
                const int kk = 2 * it + sub;
                u64 vq = *(const u64*)&svpe16[w][kk][c0];
                u64 vA, vB; h4_to_f22(vq, vA, vB);
                ulonglong2 g2 = *(const ulonglong2*)&swl[w][kk][csq];
                acc0 = ffma2(vA, g2.x, acc0);
                acc1 = ffma2(vB, g2.y, acc1);
            }
            float o0, o1, o2, o3;
            upk2(acc0, o0, o1); upk2(acc1, o2, o3);
            o0 += __shfl_xor_sync(0xffffffffu, o0, 16);
            o1 += __shfl_xor_sync(0xffffffffu, o1, 16);
            o2 += __shfl_xor_sync(0xffffffffu, o2, 16);
            o3 += __shfl_xor_sync(0xffffffffu, o3, 16);
            if (sub == 0)
                *(float4*)&out[n * 64 + c0] = make_float4(o0, o1, o2, o3);
        }
        __syncwarp();
    }
}

// =====================================================================
extern "C" void kernel_launch(void* const* d_in, const int* in_sizes, int n_in,
                              void* d_out, int out_size)
{
    const float* p   = (const float*)d_in[0];
    const float* x   = (const float*)d_in[1];
    const int*   idx = (const int*)  d_in[2];
    const float* Wq  = (const float*)d_in[3];
    const float* bq  = (const float*)d_in[4];
    const float* Wk  = (const float*)d_in[5];
    const float* bk  = (const float*)d_in[6];
    const float* Wv  = (const float*)d_in[7];
    const float* bv  = (const float*)d_in[8];
    const float* Wp1 = (const float*)d_in[9];
    const float* bp1 = (const float*)d_in[10];
    const float* pg  = (const float*)d_in[11];
    const float* pb  = (const float*)d_in[12];
    const float* pm  = (const float*)d_in[13];
    const float* pv  = (const float*)d_in[14];
    const float* Wp2 = (const float*)d_in[15];
    const float* bp2 = (const float*)d_in[16];
    const float* wg1 = (const float*)d_in[17];
    const float* wb1 = (const float*)d_in[18];
    const float* wm1 = (const float*)d_in[19];
    const float* wv1 = (const float*)d_in[20];
    const float* Ww1 = (const float*)d_in[21];
    const float* bw1 = (const float*)d_in[22];
    const float* wg2 = (const float*)d_in[23];
    const float* wb2 = (const float*)d_in[24];
    const float* wm2 = (const float*)d_in[25];
    const float* wv2 = (const float*)d_in[26];
    const float* Ww2 = (const float*)d_in[27];
    const float* bw2 = (const float*)d_in[28];
    float* out = (float*)d_out;

    gemm_qkv_mma<<<NPTS / 64, 256>>>(x, p, Wq, bq, Wk, bk, Wv, bv);
    fused_pt<<<NPTS / (NBW * PPW), 128>>>(idx, Wp1, bp1, pg, pb, pm, pv, Wp2, bp2,
                                          wg1, wb1, wm1, wv1, Ww1, bw1,
                                          wg2, wb2, wm2, wv2, Ww2, bw2, out);
}

// round 14
// speedup vs baseline: 3.3180x; 1.0471x over previous
#include <cuda_runtime.h>
#include <cuda_bf16.h>
#include <cuda_fp16.h>

typedef unsigned long long u64;
typedef unsigned int u32;

#define NPTS   65536
#define CCH    64
#define NSMP   16
#define CSW    8
#define EPSV   1e-5f
#define NBW    4   // warps per block in fused kernel
#define PPW    4   // points per warp (looped)

// ---------------- f32x2 helpers ----------------
__device__ __forceinline__ u64 pk2(float a, float b) {
    u64 r; asm("mov.b64 %0, {%1, %2};" : "=l"(r) : "f"(a), "f"(b)); return r;
}
__device__ __forceinline__ void upk2(u64 v, float& a, float& b) {
    asm("mov.b64 {%0, %1}, %2;" : "=f"(a), "=f"(b) : "l"(v));
}
__device__ __forceinline__ u64 ffma2(u64 a, u64 b, u64 c) {
    u64 d; asm("fma.rn.f32x2 %0, %1, %2, %3;" : "=l"(d) : "l"(a), "l"(b), "l"(c)); return d;
}
__device__ __forceinline__ u32 f22h(float a, float b) {
    __half2 h = __floats2half2_rn(a, b);
    return *reinterpret_cast<u32*>(&h);
}
__device__ __forceinline__ u32 smem_u32(const void* p) {
    return (u32)__cvta_generic_to_shared(p);
}
__device__ __forceinline__ void h4_to_f22(u64 h4, u64& loPair, u64& hiPair) {
    u32 lo = (u32)h4, hi = (u32)(h4 >> 32);
    __half2 hlo = *reinterpret_cast<__half2*>(&lo);
    __half2 hhi = *reinterpret_cast<__half2*>(&hi);
    float2 flo = __half22float2(hlo), fhi = __half22float2(hhi);
    loPair = pk2(flo.x, flo.y);
    hiPair = pk2(fhi.x, fhi.y);
}
// ---------------- half2-as-u32 helpers ----------------
__device__ __forceinline__ u32 hfma2u(u32 a, u32 b, u32 c) {
    __half2 r = __hfma2(*(__half2*)&a, *(__half2*)&b, *(__half2*)&c);
    return *(u32*)&r;
}
__device__ __forceinline__ u32 hadd2u(u32 a, u32 b) {
    __half2 r = __hadd2(*(__half2*)&a, *(__half2*)&b);
    return *(u32*)&r;
}
__device__ __forceinline__ u32 hsub2u(u32 a, u32 b) {
    __half2 r = __hsub2(*(__half2*)&a, *(__half2*)&b);
    return *(u32*)&r;
}
__device__ __forceinline__ u32 hrelu2u(u32 a) {
    __half2 z = __floats2half2_rn(0.f, 0.f);
    __half2 r = __hmax2(*(__half2*)&a, z);
    return *(u32*)&r;
}

// ---------------- scratch tables (fp16, L2-resident) ----------------
__device__ u64        g_xq [NPTS * CCH / 4];   // xq quads
__device__ ulonglong2 g_xkv[NPTS * 16];        // per row: 16 x {xk quad, xv quad}
__device__ float4     g_p4 [NPTS];             // padded coords

// =====================================================================
// Kernel 1: xq/xk/xv = x @ W^T + b via fp16 tensor-core MMA.
// Epilogue stages through swizzled smem -> fully coalesced uint4 STG.
// =====================================================================
__global__ __launch_bounds__(256) void gemm_qkv_mma(
    const float* __restrict__ x, const float* __restrict__ p,
    const float* __restrict__ Wq, const float* __restrict__ bq,
    const float* __restrict__ Wk, const float* __restrict__ bk,
    const float* __restrict__ Wv, const float* __restrict__ bv)
{
    __shared__ __align__(16) __half sx[64][72];
    __shared__ __align__(16) u32 sxq [64][32];   // staging, swizzled
    __shared__ __align__(16) u32 sxkv[64][64];   // staging, swizzled

    const int tid  = threadIdx.x;
    const int warp = tid >> 5;
    const int lane = tid & 31;
    const int row0 = blockIdx.x * 64;

    if (tid < 64) {
        const float* pr = &p[(row0 + tid) * 3];
        g_p4[row0 + tid] = make_float4(pr[0], pr[1], pr[2], 0.f);
    }

    {
        const int r  = tid & 63;
        const int kb = (tid >> 6) * 16;
        const float* xr = &x[(row0 + r) * 64 + kb];
        float4 v0 = *(const float4*)&xr[0];
        float4 v1 = *(const float4*)&xr[4];
        float4 v2 = *(const float4*)&xr[8];
        float4 v3 = *(const float4*)&xr[12];
        uint4 h0 = make_uint4(f22h(v0.x, v0.y), f22h(v0.z, v0.w),
                              f22h(v1.x, v1.y), f22h(v1.z, v1.w));
        uint4 h1 = make_uint4(f22h(v2.x, v2.y), f22h(v2.z, v2.w),
                              f22h(v3.x, v3.y), f22h(v3.z, v3.w));
        *(uint4*)&sx[r][kb]     = h0;
        *(uint4*)&sx[r][kb + 8] = h1;
    }
    __syncthreads();

    const int n0  = warp * 8;
    const int nn  = n0 + (lane >> 2);
    const int kfr = 2 * (lane & 3);

    const float* Ws[3] = {Wq, Wk, Wv};
    const float* Bs[3] = {bq, bk, bv};
    u32 bf[3][4][2];
    float bsx[3], bsy[3];
    #pragma unroll
    for (int m = 0; m < 3; ++m) {
        #pragma unroll
        for (int ks = 0; ks < 4; ++ks) {
            const float* wr = &Ws[m][nn * 64 + ks * 16 + kfr];
            float2 wa = *(const float2*)&wr[0];
            float2 wb = *(const float2*)&wr[8];
            bf[m][ks][0] = f22h(wa.x, wa.y);
            bf[m][ks][1] = f22h(wb.x, wb.y);
        }
        float2 bb = *(const float2*)&Bs[m][n0 + kfr];
        bsx[m] = bb.x; bsy[m] = bb.y;
    }

    const int pp   = (n0 + kfr) >> 1;   // 0..31
    const int qq   = pp >> 1;           // quad 0..15
    const int half = pp & 1;

    #pragma unroll
    for (int rt = 0; rt < 4; ++rt) {
        const int r0 = rt * 16;
        u32 afr[4][4];
        const int arow  = r0 + (lane & 15);
        const int acolb = (lane >> 4) << 3;
        #pragma unroll
        for (int ks = 0; ks < 4; ++ks) {
            u32 ad = smem_u32(&sx[arow][ks * 16 + acolb]);
            asm volatile("ldmatrix.sync.aligned.m8n8.x4.shared.b16 {%0,%1,%2,%3}, [%4];"
                : "=r"(afr[ks][0]), "=r"(afr[ks][1]), "=r"(afr[ks][2]), "=r"(afr[ks][3])
                : "r"(ad));
        }
        const int rA = r0 + (lane >> 2);   // local rows 0..63
        const int rB = rA + 8;
        #pragma unroll
        for (int m = 0; m < 3; ++m) {
            float d0 = 0.f, d1 = 0.f, d2 = 0.f, d3 = 0.f;
            #pragma unroll
            for (int ks = 0; ks < 4; ++ks) {
                asm volatile("mma.sync.aligned.m16n8k16.row.col.f32.f16.f16.f32 "
                    "{%0,%1,%2,%3}, {%4,%5,%6,%7}, {%8,%9}, {%0,%1,%2,%3};"
                    : "+f"(d0), "+f"(d1), "+f"(d2), "+f"(d3)
                    : "r"(afr[ks][0]), "r"(afr[ks][1]), "r"(afr[ks][2]), "r"(afr[ks][3]),
                      "r"(bf[m][ks][0]), "r"(bf[m][ks][1]));
            }
            d0 += bsx[m]; d1 += bsy[m]; d2 += bsx[m]; d3 += bsy[m];
            if (m == 0) {
                sxq[rA][pp ^ ((rA & 7) << 2)] = f22h(d0, d1);
                sxq[rB][pp ^ ((rB & 7) << 2)] = f22h(d2, d3);
            } else {
                const int col = qq * 4 + ((m == 1) ? 0 : 2) + half;
                sxkv[rA][col ^ ((rA & 7) << 2)] = f22h(d0, d1);
                sxkv[rB][col ^ ((rB & 7) << 2)] = f22h(d2, d3);
            }
        }
    }
    __syncthreads();

    // coalesced writes: xq (512 uint4), xkv (1024 uint4)
    {
        u32* oq = (u32*)g_xq;
        #pragma unroll
        for (int e = 0; e < 2; ++e) {
            int idx4 = tid + e * 256;
            int r = idx4 >> 3;            // 8 uint4 per row
            int i = idx4 & 7;
            int colb = (i * 4) ^ ((r & 7) << 2);
            uint4 v = *(uint4*)&sxq[r][colb];
            *(uint4*)&oq[(row0 + r) * 32 + i * 4] = v;
        }
        u32* okv = (u32*)g_xkv;
        #pragma unroll
        for (int e = 0; e < 4; ++e) {
            int idx4 = tid + e * 256;
            int r = idx4 >> 4;            // 16 uint4 per row
            int i = idx4 & 15;
            int colb = (i * 4) ^ ((r & 7) << 2);
            uint4 v = *(uint4*)&sxkv[r][colb];
            *(uint4*)&okv[(row0 + r) * 64 + i * 4] = v;
        }
    }
}

// =====================================================================
// Kernel 2: fused point-transformer. (round-13, unchanged)
// =====================================================================
__global__ void __launch_bounds__(128, 8) fused_pt(
    const int*   __restrict__ idx,
    const float* __restrict__ Wp1, const float* __restrict__ bp1,
    const float* __restrict__ pg,  const float* __restrict__ pb,
    const float* __restrict__ pm,  const float* __restrict__ pv,
    const float* __restrict__ Wp2, const float* __restrict__ bp2,
    const float* __restrict__ wg1, const float* __restrict__ wb1,
    const float* __restrict__ wm1, const float* __restrict__ wv1,
    const float* __restrict__ Ww1, const float* __restrict__ bw1,
    const float* __restrict__ wg2, const float* __restrict__ wb2,
    const float* __restrict__ wm2, const float* __restrict__ wv2,
    const float* __restrict__ Ww2, const float* __restrict__ bw2,
    float* __restrict__ out)
{
    __shared__ float  sWp1[9], sbp1v[3], spa[3], spbv[3];
    __shared__ __align__(16) uint4   sBc[32][5];   // per-lane Phase B constants
    __shared__ __align__(16) __half  ssw16 [NBW][16][72];
    __shared__ __align__(16) __half  svpe16[NBW][16][64];
    __shared__ __align__(16) uint4   stvh  [NBW][16];
    __shared__ __align__(16) float   swl   [NBW][16][8];

    const int tid = threadIdx.x;
    if (tid < 9) sWp1[tid] = Wp1[tid];
    if (tid < 3) {
        sbp1v[tid] = bp1[tid];
        float a = pg[tid] * rsqrtf(pv[tid] + EPSV);
        spa[tid] = a; spbv[tid] = pb[tid] - pm[tid] * a;
    }
    if (tid < 32) {
        const int nfr = tid >> 2;
        const int kfr = 2 * (tid & 3);
        u32 bfB[8];
        #pragma unroll
        for (int ch = 0; ch < 4; ++ch) {
            const float* wr = &Ww1[nfr * 64 + ch * 16 + kfr];
            float2 wa = *(const float2*)&wr[0];
            float2 wb = *(const float2*)&wr[8];
            bfB[2 * ch]     = f22h(wa.x, wa.y);
            bfB[2 * ch + 1] = f22h(wb.x, wb.y);
        }
        float2 w2p  = *(const float2*)&Ww2[nfr * 8 + kfr];
        float2 bw1p = *(const float2*)&bw1[kfr];
        float2 g2p  = *(const float2*)&wg2[kfr];
        float2 v2p  = *(const float2*)&wv2[kfr];
        float2 b2p  = *(const float2*)&wb2[kfr];
        float2 m2p  = *(const float2*)&wm2[kfr];
        float2 bb2p = *(const float2*)&bw2[kfr];
        float tA = g2p.x * rsqrtf(v2p.x + EPSV);
        float tB = g2p.y * rsqrtf(v2p.y + EPSV);
        sBc[tid][0] = make_uint4(bfB[0], bfB[1], bfB[2], bfB[3]);
        sBc[tid][1] = make_uint4(bfB[4], bfB[5], bfB[6], bfB[7]);
        sBc[tid][2] = make_uint4(f22h(w2p.x, w2p.y),
                                 __float_as_uint(bw1p.x),
                                 __float_as_uint(bw1p.y),
                                 __float_as_uint(tA));
        sBc[tid][3] = make_uint4(__float_as_uint(tB),
                                 __float_as_uint(b2p.x - m2p.x * tA),
                                 __float_as_uint(b2p.y - m2p.y * tB),
                                 __float_as_uint(bb2p.x));
        sBc[tid][4] = make_uint4(__float_as_uint(bb2p.y), 0u, 0u, 0u);
    }
    __syncthreads();

    const int w    = tid >> 5;
    const int lane = tid & 31;
    const int q    = lane & 15;
    const int sub  = lane >> 4;
    const int c0   = 4 * q;

    float4 wpr0 = *(const float4*)&Wp2[c0 * 3];
    float4 wpr1 = *(const float4*)&Wp2[c0 * 3 + 4];
    float4 wpr2 = *(const float4*)&Wp2[c0 * 3 + 8];
    const u32 wpA0 = f22h(wpr0.x, wpr0.w);
    const u32 wpA1 = f22h(wpr0.y, wpr1.x);
    const u32 wpA2 = f22h(wpr0.z, wpr1.y);
    const u32 wpB0 = f22h(wpr1.z, wpr2.y);
    const u32 wpB1 = f22h(wpr1.w, wpr2.z);
    const u32 wpB2 = f22h(wpr2.x, wpr2.w);
    float4 bpv = *(const float4*)&bp2[c0];
    const u32 bpA = f22h(bpv.x, bpv.y), bpB = f22h(bpv.z, bpv.w);
    float4 g1 = *(const float4*)&wg1[c0];
    float4 b1 = *(const float4*)&wb1[c0];
    float4 m1 = *(const float4*)&wm1[c0];
    float4 v1 = *(const float4*)&wv1[c0];
    float a0f = g1.x * rsqrtf(v1.x + EPSV);
    float a1f = g1.y * rsqrtf(v1.y + EPSV);
    float a2f = g1.z * rsqrtf(v1.z + EPSV);
    float a3f = g1.w * rsqrtf(v1.w + EPSV);
    const u32 a1A = f22h(a0f, a1f), a1B = f22h(a2f, a3f);
    const u32 b1A = f22h(b1.x - m1.x * a0f, b1.y - m1.y * a1f);
    const u32 b1B = f22h(b1.z - m1.z * a2f, b1.w - m1.w * a3f);

    const int nfr = lane >> 2;
    const int kfr = 2 * (lane & 3);
    const int nbase = blockIdx.x * (NBW * PPW) + w * PPW;

    for (int pt = 0; pt < PPW; ++pt) {
        const int n = nbase + pt;

        if (lane < 16) {
            int j = idx[n * 16 + lane];
            float4 pn = g_p4[n];
            float4 pj = g_p4[j];
            float prx = pj.x - pn.x;
            float pry = pj.y - pn.y;
            float prz = pj.z - pn.z;
            float u0 = prx * sWp1[0] + pry * sWp1[1] + prz * sWp1[2] + sbp1v[0];
            float u1 = prx * sWp1[3] + pry * sWp1[4] + prz * sWp1[5] + sbp1v[1];
            float u2 = prx * sWp1[6] + pry * sWp1[7] + prz * sWp1[8] + sbp1v[2];
            float t0 = fmaxf(0.f, fmaf(u0, spa[0], spbv[0]));
            float t1 = fmaxf(0.f, fmaf(u1, spa[1], spbv[1]));
            float t2 = fmaxf(0.f, fmaf(u2, spa[2], spbv[2]));
            stvh[w][lane] = make_uint4(f22h(t0, t0), f22h(t1, t1), f22h(t2, t2), (u32)j);
        }
        __syncwarp();

        {
            u64 xqq = g_xq[n * 16 + q];
            const u32 xqA = (u32)xqq, xqB = (u32)(xqq >> 32);

            #pragma unroll
            for (int hb = 0; hb < 2; ++hb) {
                uint4 tv[4];
                ulonglong2 kv[4];
                #pragma unroll
                for (int i = 0; i < 4; ++i) {
                    const int kk = 8 * hb + 2 * i + sub;
                    tv[i] = stvh[w][kk];
                    kv[i] = g_xkv[(int)tv[i].w * 16 + q];
                }
                #pragma unroll
                for (int i = 0; i < 4; ++i) {
                    const int kk = 8 * hb + 2 * i + sub;
                    u32 kA = (u32)kv[i].x, kB = (u32)(kv[i].x >> 32);
                    u32 vA = (u32)kv[i].y, vB = (u32)(kv[i].y >> 32);
                    u32 peA = hfma2u(wpA0, tv[i].x, hfma2u(wpA1, tv[i].y, hfma2u(wpA2, tv[i].z, bpA)));
                    u32 peB = hfma2u(wpB0, tv[i].x, hfma2u(wpB1, tv[i].y, hfma2u(wpB2, tv[i].z, bpB)));
                    u32 rA  = hadd2u(hsub2u(kA, xqA), peA);
                    u32 rB  = hadd2u(hsub2u(kB, xqB), peB);
                    u32 wA  = hrelu2u(hfma2u(rA, a1A, b1A));
                    u32 wB  = hrelu2u(hfma2u(rB, a1B, b1B));
                    *(u64*)&ssw16[w][kk][c0]  = (u64)wA | ((u64)wB << 32);
                    u32 vpA = hadd2u(vA, peA);
                    u32 vpB = hadd2u(vB, peB);
                    *(u64*)&svpe16[w][kk][c0] = (u64)vpA | ((u64)vpB << 32);
                }
            }
        }
        __syncwarp();

        {
            uint4 cb0 = sBc[lane][0];
            uint4 cb1 = sBc[lane][1];
            uint4 cb2 = sBc[lane][2];
            uint4 cb3 = sBc[lane][3];
            uint4 cb4 = sBc[lane][4];
            const u32 bW2f = cb2.x;
            const float cbw1A = __uint_as_float(cb2.y);
            const float cbw1B = __uint_as_float(cb2.z);
            const float ca2A  = __uint_as_float(cb2.w);
            const float ca2B  = __uint_as_float(cb3.x);
            const float cb2A  = __uint_as_float(cb3.y);
            const float cb2B  = __uint_as_float(cb3.z);
            const float cbw2A = __uint_as_float(cb3.w);
            const float cbw2B = __uint_as_float(cb4.x);

            u32 afr[4][4];
            const int arow = lane & 15;
            const int acol = (lane >> 4) << 3;
            #pragma unroll
            for (int ch = 0; ch < 4; ++ch) {
                u32 ad = smem_u32(&ssw16[w][arow][ch * 16 + acol]);
                asm volatile("ldmatrix.sync.aligned.m8n8.x4.shared.b16 {%0,%1,%2,%3}, [%4];"
                    : "=r"(afr[ch][0]), "=r"(afr[ch][1]), "=r"(afr[ch][2]), "=r"(afr[ch][3])
                    : "r"(ad));
            }
            float d0 = 0.f, d1 = 0.f, d2 = 0.f, d3 = 0.f;
            asm volatile("mma.sync.aligned.m16n8k16.row.col.f32.f16.f16.f32 "
                "{%0,%1,%2,%3}, {%4,%5,%6,%7}, {%8,%9}, {%0,%1,%2,%3};"
                : "+f"(d0), "+f"(d1), "+f"(d2), "+f"(d3)
                : "r"(afr[0][0]), "r"(afr[0][1]), "r"(afr[0][2]), "r"(afr[0][3]),
                  "r"(cb0.x), "r"(cb0.y));
            asm volatile("mma.sync.aligned.m16n8k16.row.col.f32.f16.f16.f32 "
                "{%0,%1,%2,%3}, {%4,%5,%6,%7}, {%8,%9}, {%0,%1,%2,%3};"
                : "+f"(d0), "+f"(d1), "+f"(d2), "+f"(d3)
                : "r"(afr[1][0]), "r"(afr[1][1]), "r"(afr[1][2]), "r"(afr[1][3]),
                  "r"(cb0.z), "r"(cb0.w));
            asm volatile("mma.sync.aligned.m16n8k16.row.col.f32.f16.f16.f32 "
                "{%0,%1,%2,%3}, {%4,%5,%6,%7}, {%8,%9}, {%0,%1,%2,%3};"
                : "+f"(d0), "+f"(d1), "+f"(d2), "+f"(d3)
                : "r"(afr[2][0]), "r"(afr[2][1]), "r"(afr[2][2]), "r"(afr[2][3]),
                  "r"(cb1.x), "r"(cb1.y));
            asm volatile("mma.sync.aligned.m16n8k16.row.col.f32.f16.f16.f32 "
                "{%0,%1,%2,%3}, {%4,%5,%6,%7}, {%8,%9}, {%0,%1,%2,%3};"
                : "+f"(d0), "+f"(d1), "+f"(d2), "+f"(d3)
                : "r"(afr[3][0]), "r"(afr[3][1]), "r"(afr[3][2]), "r"(afr[3][3]),
                  "r"(cb1.z), "r"(cb1.w));

            float h0 = fmaxf(0.f, fmaf(d0 + cbw1A, ca2A, cb2A));
            float h1 = fmaxf(0.f, fmaf(d1 + cbw1B, ca2B, cb2B));
            float h2 = fmaxf(0.f, fmaf(d2 + cbw1A, ca2A, cb2A));
            float h3 = fmaxf(0.f, fmaf(d3 + cbw1B, ca2B, cb2B));
            u32 ha0 = f22h(h0, h1), ha1 = f22h(h2, h3);
            float l0 = 0.f, l1 = 0.f, l2 = 0.f, l3 = 0.f;
            asm volatile("mma.sync.aligned.m16n8k8.row.col.f32.f16.f16.f32 "
                "{%0,%1,%2,%3}, {%4,%5}, {%6}, {%0,%1,%2,%3};"
                : "+f"(l0), "+f"(l1), "+f"(l2), "+f"(l3)
                : "r"(ha0), "r"(ha1), "r"(bW2f));
            l0 += cbw2A; l1 += cbw2B; l2 += cbw2A; l3 += cbw2B;

            float mA = fmaxf(l0, l2), mB = fmaxf(l1, l3);
            #pragma unroll
            for (int dlt = 4; dlt <= 16; dlt <<= 1) {
                mA = fmaxf(mA, __shfl_xor_sync(0xffffffffu, mA, dlt));
                mB = fmaxf(mB, __shfl_xor_sync(0xffffffffu, mB, dlt));
            }
            float e0 = __expf(l0 - mA), e1 = __expf(l1 - mB);
            float e2 = __expf(l2 - mA), e3 = __expf(l3 - mB);
            float sA = e0 + e2, sB = e1 + e3;
            #pragma unroll
            for (int dlt = 4; dlt <= 16; dlt <<= 1) {
                sA += __shfl_xor_sync(0xffffffffu, sA, dlt);
                sB += __shfl_xor_sync(0xffffffffu, sB, dlt);
            }
            float iA = 1.f / sA, iB = 1.f / sB;
            *(u64*)&swl[w][nfr][kfr]     = pk2(e0 * iA, e1 * iB);
            *(u64*)&swl[w][nfr + 8][kfr] = pk2(e2 * iA, e3 * iB);
        }
        __syncwarp();

        {
            const int csq = c0 & 7;

            u64 acc0 = 0ull, acc1 = 0ull;
            #pragma unroll
            for (int it = 0; it < 8; ++it) {
                const int kk = 2 * it + sub;
                u64 vq = *(const u64*)&svpe16[w][kk][c0];
                u64 vA, vB; h4_to_f22(vq, vA, vB);
                ulonglong2 g2 = *(const ulonglong2*)&swl[w][kk][csq];
                acc0 = ffma2(vA, g2.x, acc0);
                acc1 = ffma2(vB, g2.y, acc1);
            }
            float o0, o1, o2, o3;
            upk2(acc0, o0, o1); upk2(acc1, o2, o3);
            o0 += __shfl_xor_sync(0xffffffffu, o0, 16);
            o1 += __shfl_xor_sync(0xffffffffu, o1, 16);
            o2 += __shfl_xor_sync(0xffffffffu, o2, 16);
            o3 += __shfl_xor_sync(0xffffffffu, o3, 16);
            if (sub == 0)
                *(float4*)&out[n * 64 + c0] = make_float4(o0, o1, o2, o3);
        }
        __syncwarp();
    }
}

// =====================================================================
extern "C" void kernel_launch(void* const* d_in, const int* in_sizes, int n_in,
                              void* d_out, int out_size)
{
    const float* p   = (const float*)d_in[0];
    const float* x   = (const float*)d_in[1];
    const int*   idx = (const int*)  d_in[2];
    const float* Wq  = (const float*)d_in[3];
    const float* bq  = (const float*)d_in[4];
    const float* Wk  = (const float*)d_in[5];
    const float* bk  = (const float*)d_in[6];
    const float* Wv  = (const float*)d_in[7];
    const float* bv  = (const float*)d_in[8];
    const float* Wp1 = (const float*)d_in[9];
    const float* bp1 = (const float*)d_in[10];
    const float* pg  = (const float*)d_in[11];
    const float* pb  = (const float*)d_in[12];
    const float* pm  = (const float*)d_in[13];
    const float* pv  = (const float*)d_in[14];
    const float* Wp2 = (const float*)d_in[15];
    const float* bp2 = (const float*)d_in[16];
    const float* wg1 = (const float*)d_in[17];
    const float* wb1 = (const float*)d_in[18];
    const float* wm1 = (const float*)d_in[19];
    const float* wv1 = (const float*)d_in[20];
    const float* Ww1 = (const float*)d_in[21];
    const float* bw1 = (const float*)d_in[22];
    const float* wg2 = (const float*)d_in[23];
    const float* wb2 = (const float*)d_in[24];
    const float* wm2 = (const float*)d_in[25];
    const float* wv2 = (const float*)d_in[26];
    const float* Ww2 = (const float*)d_in[27];
    const float* bw2 = (const float*)d_in[28];
    float* out = (float*)d_out;

    gemm_qkv_mma<<<NPTS / 64, 256>>>(x, p, Wq, bq, Wk, bk, Wv, bv);
    fused_pt<<<NPTS / (NBW * PPW), 128>>>(idx, Wp1, bp1, pg, pb, pm, pv, Wp2, bp2,
                                          wg1, wb1, wm1, wv1, Ww1, bw1,
                                          wg2, wb2, wm2, wv2, Ww2, bw2, out);
}

// round 15
// speedup vs baseline: 3.3572x; 1.0118x over previous
#include <cuda_runtime.h>
#include <cuda_bf16.h>
#include <cuda_fp16.h>

typedef unsigned long long u64;
typedef unsigned int u32;

#define NPTS   65536
#define CCH    64
#define NSMP   16
#define CSW    8
#define EPSV   1e-5f
#define NBW    4   // warps per block in fused kernel
#define PPW    4   // points per warp (looped)

// ---------------- f32x2 helpers ----------------
__device__ __forceinline__ u64 pk2(float a, float b) {
    u64 r; asm("mov.b64 %0, {%1, %2};" : "=l"(r) : "f"(a), "f"(b)); return r;
}
__device__ __forceinline__ void upk2(u64 v, float& a, float& b) {
    asm("mov.b64 {%0, %1}, %2;" : "=f"(a), "=f"(b) : "l"(v));
}
__device__ __forceinline__ u64 ffma2(u64 a, u64 b, u64 c) {
    u64 d; asm("fma.rn.f32x2 %0, %1, %2, %3;" : "=l"(d) : "l"(a), "l"(b), "l"(c)); return d;
}
__device__ __forceinline__ u32 f22h(float a, float b) {
    __half2 h = __floats2half2_rn(a, b);
    return *reinterpret_cast<u32*>(&h);
}
__device__ __forceinline__ u32 smem_u32(const void* p) {
    return (u32)__cvta_generic_to_shared(p);
}
__device__ __forceinline__ void h4_to_f22(u64 h4, u64& loPair, u64& hiPair) {
    u32 lo = (u32)h4, hi = (u32)(h4 >> 32);
    __half2 hlo = *reinterpret_cast<__half2*>(&lo);
    __half2 hhi = *reinterpret_cast<__half2*>(&hi);
    float2 flo = __half22float2(hlo), fhi = __half22float2(hhi);
    loPair = pk2(flo.x, flo.y);
    hiPair = pk2(fhi.x, fhi.y);
}
// ---------------- half2-as-u32 helpers ----------------
__device__ __forceinline__ u32 hfma2u(u32 a, u32 b, u32 c) {
    __half2 r = __hfma2(*(__half2*)&a, *(__half2*)&b, *(__half2*)&c);
    return *(u32*)&r;
}
__device__ __forceinline__ u32 hadd2u(u32 a, u32 b) {
    __half2 r = __hadd2(*(__half2*)&a, *(__half2*)&b);
    return *(u32*)&r;
}
__device__ __forceinline__ u32 hsub2u(u32 a, u32 b) {
    __half2 r = __hsub2(*(__half2*)&a, *(__half2*)&b);
    return *(u32*)&r;
}
__device__ __forceinline__ u32 hrelu2u(u32 a) {
    __half2 z = __floats2half2_rn(0.f, 0.f);
    __half2 r = __hmax2(*(__half2*)&a, z);
    return *(u32*)&r;
}

// ---------------- scratch tables (fp16, L2-resident) ----------------
__device__ u64        g_xq [NPTS * CCH / 4];   // xq quads
__device__ ulonglong2 g_xkv[NPTS * 16];        // per row: 16 x {xk quad, xv quad}
__device__ float4     g_p4 [NPTS];             // padded coords

// =====================================================================
// Kernel 1: xq/xk/xv = x @ W^T + b via fp16 tensor-core MMA.
// 256 rows per block in 4 chunks; B-fragments built ONCE per block.
// Epilogue stages through swizzled smem -> coalesced uint4 STG.
// =====================================================================
__global__ __launch_bounds__(256) void gemm_qkv_mma(
    const float* __restrict__ x, const float* __restrict__ p,
    const float* __restrict__ Wq, const float* __restrict__ bq,
    const float* __restrict__ Wk, const float* __restrict__ bk,
    const float* __restrict__ Wv, const float* __restrict__ bv)
{
    __shared__ __align__(16) __half sx[64][72];
    __shared__ __align__(16) u32 sxq [64][32];   // staging, swizzled
    __shared__ __align__(16) u32 sxkv[64][64];   // staging, swizzled

    const int tid  = threadIdx.x;
    const int warp = tid >> 5;
    const int lane = tid & 31;
    const int row0 = blockIdx.x * 256;

    // p4 table slice (256 rows)
    {
        const float* pr = &p[(row0 + tid) * 3];
        g_p4[row0 + tid] = make_float4(pr[0], pr[1], pr[2], 0.f);
    }

    // ---- B fragments + biases: built once per block ----
    const int n0  = warp * 8;
    const int nn  = n0 + (lane >> 2);
    const int kfr = 2 * (lane & 3);

    const float* Ws[3] = {Wq, Wk, Wv};
    const float* Bs[3] = {bq, bk, bv};
    u32 bf[3][4][2];
    float bsx[3], bsy[3];
    #pragma unroll
    for (int m = 0; m < 3; ++m) {
        #pragma unroll
        for (int ks = 0; ks < 4; ++ks) {
            const float* wr = &Ws[m][nn * 64 + ks * 16 + kfr];
            float2 wa = *(const float2*)&wr[0];
            float2 wb = *(const float2*)&wr[8];
            bf[m][ks][0] = f22h(wa.x, wa.y);
            bf[m][ks][1] = f22h(wb.x, wb.y);
        }
        float2 bb = *(const float2*)&Bs[m][n0 + kfr];
        bsx[m] = bb.x; bsy[m] = bb.y;
    }

    const int pp   = (n0 + kfr) >> 1;   // 0..31
    const int qq   = pp >> 1;           // quad 0..15
    const int half = pp & 1;

    for (int ck = 0; ck < 4; ++ck) {
        const int rowc = row0 + ck * 64;

        // load x chunk (fp32) -> fp16 smem
        {
            const int r  = tid & 63;
            const int kb = (tid >> 6) * 16;
            const float* xr = &x[(rowc + r) * 64 + kb];
            float4 v0 = *(const float4*)&xr[0];
            float4 v1 = *(const float4*)&xr[4];
            float4 v2 = *(const float4*)&xr[8];
            float4 v3 = *(const float4*)&xr[12];
            uint4 h0 = make_uint4(f22h(v0.x, v0.y), f22h(v0.z, v0.w),
                                  f22h(v1.x, v1.y), f22h(v1.z, v1.w));
            uint4 h1 = make_uint4(f22h(v2.x, v2.y), f22h(v2.z, v2.w),
                                  f22h(v3.x, v3.y), f22h(v3.z, v3.w));
            *(uint4*)&sx[r][kb]     = h0;
            *(uint4*)&sx[r][kb + 8] = h1;
        }
        __syncthreads();

        #pragma unroll
        for (int rt = 0; rt < 4; ++rt) {
            const int r0 = rt * 16;
            u32 afr[4][4];
            const int arow  = r0 + (lane & 15);
            const int acolb = (lane >> 4) << 3;
            #pragma unroll
            for (int ks = 0; ks < 4; ++ks) {
                u32 ad = smem_u32(&sx[arow][ks * 16 + acolb]);
                asm volatile("ldmatrix.sync.aligned.m8n8.x4.shared.b16 {%0,%1,%2,%3}, [%4];"
                    : "=r"(afr[ks][0]), "=r"(afr[ks][1]), "=r"(afr[ks][2]), "=r"(afr[ks][3])
                    : "r"(ad));
            }
            const int rA = r0 + (lane >> 2);   // local rows 0..63
            const int rB = rA + 8;
            #pragma unroll
            for (int m = 0; m < 3; ++m) {
                float d0 = 0.f, d1 = 0.f, d2 = 0.f, d3 = 0.f;
                #pragma unroll
                for (int ks = 0; ks < 4; ++ks) {
                    asm volatile("mma.sync.aligned.m16n8k16.row.col.f32.f16.f16.f32 "
                        "{%0,%1,%2,%3}, {%4,%5,%6,%7}, {%8,%9}, {%0,%1,%2,%3};"
                        : "+f"(d0), "+f"(d1), "+f"(d2), "+f"(d3)
                        : "r"(afr[ks][0]), "r"(afr[ks][1]), "r"(afr[ks][2]), "r"(afr[ks][3]),
                          "r"(bf[m][ks][0]), "r"(bf[m][ks][1]));
                }
                d0 += bsx[m]; d1 += bsy[m]; d2 += bsx[m]; d3 += bsy[m];
                if (m == 0) {
                    sxq[rA][pp ^ ((rA & 7) << 2)] = f22h(d0, d1);
                    sxq[rB][pp ^ ((rB & 7) << 2)] = f22h(d2, d3);
                } else {
                    const int col = qq * 4 + ((m == 1) ? 0 : 2) + half;
                    sxkv[rA][col ^ ((rA & 7) << 2)] = f22h(d0, d1);
                    sxkv[rB][col ^ ((rB & 7) << 2)] = f22h(d2, d3);
                }
            }
        }
        __syncthreads();

        // coalesced writes: xq (512 uint4), xkv (1024 uint4)
        {
            u32* oq = (u32*)g_xq;
            #pragma unroll
            for (int e = 0; e < 2; ++e) {
                int idx4 = tid + e * 256;
                int r = idx4 >> 3;
                int i = idx4 & 7;
                int colb = (i * 4) ^ ((r & 7) << 2);
                uint4 v = *(uint4*)&sxq[r][colb];
                *(uint4*)&oq[(rowc + r) * 32 + i * 4] = v;
            }
            u32* okv = (u32*)g_xkv;
            #pragma unroll
            for (int e = 0; e < 4; ++e) {
                int idx4 = tid + e * 256;
                int r = idx4 >> 4;
                int i = idx4 & 15;
                int colb = (i * 4) ^ ((r & 7) << 2);
                uint4 v = *(uint4*)&sxkv[r][colb];
                *(uint4*)&okv[(rowc + r) * 64 + i * 4] = v;
            }
        }
    }
}

// =====================================================================
// Kernel 2: fused point-transformer. (round-13/14, unchanged)
// =====================================================================
__global__ void __launch_bounds__(128, 8) fused_pt(
    const int*   __restrict__ idx,
    const float* __restrict__ Wp1, const float* __restrict__ bp1,
    const float* __restrict__ pg,  const float* __restrict__ pb,
    const float* __restrict__ pm,  const float* __restrict__ pv,
    const float* __restrict__ Wp2, const float* __restrict__ bp2,
    const float* __restrict__ wg1, const float* __restrict__ wb1,
    const float* __restrict__ wm1, const float* __restrict__ wv1,
    const float* __restrict__ Ww1, const float* __restrict__ bw1,
    const float* __restrict__ wg2, const float* __restrict__ wb2,
    const float* __restrict__ wm2, const float* __restrict__ wv2,
    const float* __restrict__ Ww2, const float* __restrict__ bw2,
    float* __restrict__ out)
{
    __shared__ float  sWp1[9], sbp1v[3], spa[3], spbv[3];
    __shared__ __align__(16) uint4   sBc[32][5];   // per-lane Phase B constants
    __shared__ __align__(16) __half  ssw16 [NBW][16][72];
    __shared__ __align__(16) __half  svpe16[NBW][16][64];
    __shared__ __align__(16) uint4   stvh  [NBW][16];
    __shared__ __align__(16) float   swl   [NBW][16][8];

    const int tid = threadIdx.x;
    if (tid < 9) sWp1[tid] = Wp1[tid];
    if (tid < 3) {
        sbp1v[tid] = bp1[tid];
        float a = pg[tid] * rsqrtf(pv[tid] + EPSV);
        spa[tid] = a; spbv[tid] = pb[tid] - pm[tid] * a;
    }
    if (tid < 32) {
        const int nfr = tid >> 2;
        const int kfr = 2 * (tid & 3);
        u32 bfB[8];
        #pragma unroll
        for (int ch = 0; ch < 4; ++ch) {
            const float* wr = &Ww1[nfr * 64 + ch * 16 + kfr];
            float2 wa = *(const float2*)&wr[0];
            float2 wb = *(const float2*)&wr[8];
            bfB[2 * ch]     = f22h(wa.x, wa.y);
            bfB[2 * ch + 1] = f22h(wb.x, wb.y);
        }
        float2 w2p  = *(const float2*)&Ww2[nfr * 8 + kfr];
        float2 bw1p = *(const float2*)&bw1[kfr];
        float2 g2p  = *(const float2*)&wg2[kfr];
        float2 v2p  = *(const float2*)&wv2[kfr];
        float2 b2p  = *(const float2*)&wb2[kfr];
        float2 m2p  = *(const float2*)&wm2[kfr];
        float2 bb2p = *(const float2*)&bw2[kfr];
        float tA = g2p.x * rsqrtf(v2p.x + EPSV);
        float tB = g2p.y * rsqrtf(v2p.y + EPSV);
        sBc[tid][0] = make_uint4(bfB[0], bfB[1], bfB[2], bfB[3]);
        sBc[tid][1] = make_uint4(bfB[4], bfB[5], bfB[6], bfB[7]);
        sBc[tid][2] = make_uint4(f22h(w2p.x, w2p.y),
                                 __float_as_uint(bw1p.x),
                                 __float_as_uint(bw1p.y),
                                 __float_as_uint(tA));
        sBc[tid][3] = make_uint4(__float_as_uint(tB),
                                 __float_as_uint(b2p.x - m2p.x * tA),
                                 __float_as_uint(b2p.y - m2p.y * tB),
                                 __float_as_uint(bb2p.x));
        sBc[tid][4] = make_uint4(__float_as_uint(bb2p.y), 0u, 0u, 0u);
    }
    __syncthreads();

    const int w    = tid >> 5;
    const int lane = tid & 31;
    const int q    = lane & 15;
    const int sub  = lane >> 4;
    const int c0   = 4 * q;

    float4 wpr0 = *(const float4*)&Wp2[c0 * 3];
    float4 wpr1 = *(const float4*)&Wp2[c0 * 3 + 4];
    float4 wpr2 = *(const float4*)&Wp2[c0 * 3 + 8];
    const u32 wpA0 = f22h(wpr0.x, wpr0.w);
    const u32 wpA1 = f22h(wpr0.y, wpr1.x);
    const u32 wpA2 = f22h(wpr0.z, wpr1.y);
    const u32 wpB0 = f22h(wpr1.z, wpr2.y);
    const u32 wpB1 = f22h(wpr1.w, wpr2.z);
    const u32 wpB2 = f22h(wpr2.x, wpr2.w);
    float4 bpv = *(const float4*)&bp2[c0];
    const u32 bpA = f22h(bpv.x, bpv.y), bpB = f22h(bpv.z, bpv.w);
    float4 g1 = *(const float4*)&wg1[c0];
    float4 b1 = *(const float4*)&wb1[c0];
    float4 m1 = *(const float4*)&wm1[c0];
    float4 v1 = *(const float4*)&wv1[c0];
    float a0f = g1.x * rsqrtf(v1.x + EPSV);
    float a1f = g1.y * rsqrtf(v1.y + EPSV);
    float a2f = g1.z * rsqrtf(v1.z + EPSV);
    float a3f = g1.w * rsqrtf(v1.w + EPSV);
    const u32 a1A = f22h(a0f, a1f), a1B = f22h(a2f, a3f);
    const u32 b1A = f22h(b1.x - m1.x * a0f, b1.y - m1.y * a1f);
    const u32 b1B = f22h(b1.z - m1.z * a2f, b1.w - m1.w * a3f);

    const int nfr = lane >> 2;
    const int kfr = 2 * (lane & 3);
    const int nbase = blockIdx.x * (NBW * PPW) + w * PPW;

    for (int pt = 0; pt < PPW; ++pt) {
        const int n = nbase + pt;

        if (lane < 16) {
            int j = idx[n * 16 + lane];
            float4 pn = g_p4[n];
            float4 pj = g_p4[j];
            float prx = pj.x - pn.x;
            float pry = pj.y - pn.y;
            float prz = pj.z - pn.z;
            float u0 = prx * sWp1[0] + pry * sWp1[1] + prz * sWp1[2] + sbp1v[0];
            float u1 = prx * sWp1[3] + pry * sWp1[4] + prz * sWp1[5] + sbp1v[1];
            float u2 = prx * sWp1[6] + pry * sWp1[7] + prz * sWp1[8] + sbp1v[2];
            float t0 = fmaxf(0.f, fmaf(u0, spa[0], spbv[0]));
            float t1 = fmaxf(0.f, fmaf(u1, spa[1], spbv[1]));
            float t2 = fmaxf(0.f, fmaf(u2, spa[2], spbv[2]));
            stvh[w][lane] = make_uint4(f22h(t0, t0), f22h(t1, t1), f22h(t2, t2), (u32)j);
        }
        __syncwarp();

        {
            u64 xqq = g_xq[n * 16 + q];
            const u32 xqA = (u32)xqq, xqB = (u32)(xqq >> 32);

            #pragma unroll
            for (int hb = 0; hb < 2; ++hb) {
                uint4 tv[4];
                ulonglong2 kv[4];
                #pragma unroll
                for (int i = 0; i < 4; ++i) {
                    const int kk = 8 * hb + 2 * i + sub;
                    tv[i] = stvh[w][kk];
                    kv[i] = g_xkv[(int)tv[i].w * 16 + q];
                }
                #pragma unroll
                for (int i = 0; i < 4; ++i) {
                    const int kk = 8 * hb + 2 * i + sub;
                    u32 kA = (u32)kv[i].x, kB = (u32)(kv[i].x >> 32);
                    u32 vA = (u32)kv[i].y, vB = (u32)(kv[i].y >> 32);
                    u32 peA = hfma2u(wpA0, tv[i].x, hfma2u(wpA1, tv[i].y, hfma2u(wpA2, tv[i].z, bpA)));
                    u32 peB = hfma2u(wpB0, tv[i].x, hfma2u(wpB1, tv[i].y, hfma2u(wpB2, tv[i].z, bpB)));
                    u32 rA  = hadd2u(hsub2u(kA, xqA), peA);
                    u32 rB  = hadd2u(hsub2u(kB, xqB), peB);
                    u32 wA  = hrelu2u(hfma2u(rA, a1A, b1A));
                    u32 wB  = hrelu2u(hfma2u(rB, a1B, b1B));
                    *(u64*)&ssw16[w][kk][c0]  = (u64)wA | ((u64)wB << 32);
                    u32 vpA = hadd2u(vA, peA);
                    u32 vpB = hadd2u(vB, peB);
                    *(u64*)&svpe16[w][kk][c0] = (u64)vpA | ((u64)vpB << 32);
                }
            }
        }
        __syncwarp();

        {
            uint4 cb0 = sBc[lane][0];
            uint4 cb1 = sBc[lane][1];
            uint4 cb2 = sBc[lane][2];
            uint4 cb3 = sBc[lane][3];
            uint4 cb4 = sBc[lane][4];
            const u32 bW2f = cb2.x;
            const float cbw1A = __uint_as_float(cb2.y);
            const float cbw1B = __uint_as_float(cb2.z);
            const float ca2A  = __uint_as_float(cb2.w);
            const float ca2B  = __uint_as_float(cb3.x);
            const float cb2A  = __uint_as_float(cb3.y);
            const float cb2B  = __uint_as_float(cb3.z);
            const float cbw2A = __uint_as_float(cb3.w);
            const float cbw2B = __uint_as_float(cb4.x);

            u32 afr[4][4];
            const int arow = lane & 15;
            const int acol = (lane >> 4) << 3;
            #pragma unroll
            for (int ch = 0; ch < 4; ++ch) {
                u32 ad = smem_u32(&ssw16[w][arow][ch * 16 + acol]);
                asm volatile("ldmatrix.sync.aligned.m8n8.x4.shared.b16 {%0,%1,%2,%3}, [%4];"
                    : "=r"(afr[ch][0]), "=r"(afr[ch][1]), "=r"(afr[ch][2]), "=r"(afr[ch][3])
                    : "r"(ad));
            }
            float d0 = 0.f, d1 = 0.f, d2 = 0.f, d3 = 0.f;
            asm volatile("mma.sync.aligned.m16n8k16.row.col.f32.f16.f16.f32 "
                "{%0,%1,%2,%3}, {%4,%5,%6,%7}, {%8,%9}, {%0,%1,%2,%3};"
                : "+f"(d0), "+f"(d1), "+f"(d2), "+f"(d3)
                : "r"(afr[0][0]), "r"(afr[0][1]), "r"(afr[0][2]), "r"(afr[0][3]),
                  "r"(cb0.x), "r"(cb0.y));
            asm volatile("mma.sync.aligned.m16n8k16.row.col.f32.f16.f16.f32 "
                "{%0,%1,%2,%3}, {%4,%5,%6,%7}, {%8,%9}, {%0,%1,%2,%3};"
                : "+f"(d0), "+f"(d1), "+f"(d2), "+f"(d3)
                : "r"(afr[1][0]), "r"(afr[1][1]), "r"(afr[1][2]), "r"(afr[1][3]),
                  "r"(cb0.z), "r"(cb0.w));
            asm volatile("mma.sync.aligned.m16n8k16.row.col.f32.f16.f16.f32 "
                "{%0,%1,%2,%3}, {%4,%5,%6,%7}, {%8,%9}, {%0,%1,%2,%3};"
                : "+f"(d0), "+f"(d1), "+f"(d2), "+f"(d3)
                : "r"(afr[2][0]), "r"(afr[2][1]), "r"(afr[2][2]), "r"(afr[2][3]),
                  "r"(cb1.x), "r"(cb1.y));
            asm volatile("mma.sync.aligned.m16n8k16.row.col.f32.f16.f16.f32 "
                "{%0,%1,%2,%3}, {%4,%5,%6,%7}, {%8,%9}, {%0,%1,%2,%3};"
                : "+f"(d0), "+f"(d1), "+f"(d2), "+f"(d3)
                : "r"(afr[3][0]), "r"(afr[3][1]), "r"(afr[3][2]), "r"(afr[3][3]),
                  "r"(cb1.z), "r"(cb1.w));

            float h0 = fmaxf(0.f, fmaf(d0 + cbw1A, ca2A, cb2A));
            float h1 = fmaxf(0.f, fmaf(d1 + cbw1B, ca2B, cb2B));
            float h2 = fmaxf(0.f, fmaf(d2 + cbw1A, ca2A, cb2A));
            float h3 = fmaxf(0.f, fmaf(d3 + cbw1B, ca2B, cb2B));
            u32 ha0 = f22h(h0, h1), ha1 = f22h(h2, h3);
            float l0 = 0.f, l1 = 0.f, l2 = 0.f, l3 = 0.f;
            asm volatile("mma.sync.aligned.m16n8k8.row.col.f32.f16.f16.f32 "
                "{%0,%1,%2,%3}, {%4,%5}, {%6}, {%0,%1,%2,%3};"
                : "+f"(l0), "+f"(l1), "+f"(l2), "+f"(l3)
                : "r"(ha0), "r"(ha1), "r"(bW2f));
            l0 += cbw2A; l1 += cbw2B; l2 += cbw2A; l3 += cbw2B;

            float mA = fmaxf(l0, l2), mB = fmaxf(l1, l3);
            #pragma unroll
            for (int dlt = 4; dlt <= 16; dlt <<= 1) {
                mA = fmaxf(mA, __shfl_xor_sync(0xffffffffu, mA, dlt));
                mB = fmaxf(mB, __shfl_xor_sync(0xffffffffu, mB, dlt));
            }
            float e0 = __expf(l0 - mA), e1 = __expf(l1 - mB);
            float e2 = __expf(l2 - mA), e3 = __expf(l3 - mB);
            float sA = e0 + e2, sB = e1 + e3;
            #pragma unroll
            for (int dlt = 4; dlt <= 16; dlt <<= 1) {
                sA += __shfl_xor_sync(0xffffffffu, sA, dlt);
                sB += __shfl_xor_sync(0xffffffffu, sB, dlt);
            }
            float iA = 1.f / sA, iB = 1.f / sB;
            *(u64*)&swl[w][nfr][kfr]     = pk2(e0 * iA, e1 * iB);
            *(u64*)&swl[w][nfr + 8][kfr] = pk2(e2 * iA, e3 * iB);
        }
        __syncwarp();

        {
            const int csq = c0 & 7;

            u64 acc0 = 0ull, acc1 = 0ull;
            #pragma unroll
            for (int it = 0; it < 8; ++it) {
                const int kk = 2 * it + sub;
                u64 vq = *(const u64*)&svpe16[w][kk][c0];
                u64 vA, vB; h4_to_f22(vq, vA, vB);
                ulonglong2 g2 = *(const ulonglong2*)&swl[w][kk][csq];
                acc0 = ffma2(vA, g2.x, acc0);
                acc1 = ffma2(vB, g2.y, acc1);
            }
            float o0, o1, o2, o3;
            upk2(acc0, o0, o1); upk2(acc1, o2, o3);
            o0 += __shfl_xor_sync(0xffffffffu, o0, 16);
            o1 += __shfl_xor_sync(0xffffffffu, o1, 16);
            o2 += __shfl_xor_sync(0xffffffffu, o2, 16);
            o3 += __shfl_xor_sync(0xffffffffu, o3, 16);
            if (sub == 0)
                *(float4*)&out[n * 64 + c0] = make_float4(o0, o1, o2, o3);
        }
        __syncwarp();
    }
}

// =====================================================================
extern "C" void kernel_launch(void* const* d_in, const int* in_sizes, int n_in,
                              void* d_out, int out_size)
{
    const float* p   = (const float*)d_in[0];
    const float* x   = (const float*)d_in[1];
    const int*   idx = (const int*)  d_in[2];
    const float* Wq  = (const float*)d_in[3];
    const float* bq  = (const float*)d_in[4];
    const float* Wk  = (const float*)d_in[5];
    const float* bk  = (const float*)d_in[6];
    const float* Wv  = (const float*)d_in[7];
    const float* bv  = (const float*)d_in[8];
    const float* Wp1 = (const float*)d_in[9];
    const float* bp1 = (const float*)d_in[10];
    const float* pg  = (const float*)d_in[11];
    const float* pb  = (const float*)d_in[12];
    const float* pm  = (const float*)d_in[13];
    const float* pv  = (const float*)d_in[14];
    const float* Wp2 = (const float*)d_in[15];
    const float* bp2 = (const float*)d_in[16];
    const float* wg1 = (const float*)d_in[17];
    const float* wb1 = (const float*)d_in[18];
    const float* wm1 = (const float*)d_in[19];
    const float* wv1 = (const float*)d_in[20];
    const float* Ww1 = (const float*)d_in[21];
    const float* bw1 = (const float*)d_in[22];
    const float* wg2 = (const float*)d_in[23];
    const float* wb2 = (const float*)d_in[24];
    const float* wm2 = (const float*)d_in[25];
    const float* wv2 = (const float*)d_in[26];
    const float* Ww2 = (const float*)d_in[27];
    const float* bw2 = (const float*)d_in[28];
    float* out = (float*)d_out;

    gemm_qkv_mma<<<NPTS / 256, 256>>>(x, p, Wq, bq, Wk, bk, Wv, bv);
    fused_pt<<<NPTS / (NBW * PPW), 128>>>(idx, Wp1, bp1, pg, pb, pm, pv, Wp2, bp2,
                                          wg1, wb1, wm1, wv1, Ww1, bw1,
                                          wg2, wb2, wm2, wv2, Ww2, bw2, out);
}

// round 16
// speedup vs baseline: 3.4192x; 1.0185x over previous
#include <cuda_runtime.h>
#include <cuda_bf16.h>
#include <cuda_fp16.h>

typedef unsigned long long u64;
typedef unsigned int u32;

#define NPTS   65536
#define CCH    64
#define NSMP   16
#define CSW    8
#define EPSV   1e-5f
#define NBW    4   // warps per block in fused kernel
#define PPW    4   // points per warp (looped)

// ---------------- f32x2 helpers ----------------
__device__ __forceinline__ u64 pk2(float a, float b) {
    u64 r; asm("mov.b64 %0, {%1, %2};" : "=l"(r) : "f"(a), "f"(b)); return r;
}
__device__ __forceinline__ void upk2(u64 v, float& a, float& b) {
    asm("mov.b64 {%0, %1}, %2;" : "=f"(a), "=f"(b) : "l"(v));
}
__device__ __forceinline__ u64 ffma2(u64 a, u64 b, u64 c) {
    u64 d; asm("fma.rn.f32x2 %0, %1, %2, %3;" : "=l"(d) : "l"(a), "l"(b), "l"(c)); return d;
}
__device__ __forceinline__ u32 f22h(float a, float b) {
    __half2 h = __floats2half2_rn(a, b);
    return *reinterpret_cast<u32*>(&h);
}
__device__ __forceinline__ u32 smem_u32(const void* p) {
    return (u32)__cvta_generic_to_shared(p);
}
__device__ __forceinline__ void h4_to_f22(u64 h4, u64& loPair, u64& hiPair) {
    u32 lo = (u32)h4, hi = (u32)(h4 >> 32);
    __half2 hlo = *reinterpret_cast<__half2*>(&lo);
    __half2 hhi = *reinterpret_cast<__half2*>(&hi);
    float2 flo = __half22float2(hlo), fhi = __half22float2(hhi);
    loPair = pk2(flo.x, flo.y);
    hiPair = pk2(fhi.x, fhi.y);
}
// ---------------- half2-as-u32 helpers ----------------
__device__ __forceinline__ u32 hfma2u(u32 a, u32 b, u32 c) {
    __half2 r = __hfma2(*(__half2*)&a, *(__half2*)&b, *(__half2*)&c);
    return *(u32*)&r;
}
__device__ __forceinline__ u32 hadd2u(u32 a, u32 b) {
    __half2 r = __hadd2(*(__half2*)&a, *(__half2*)&b);
    return *(u32*)&r;
}
__device__ __forceinline__ u32 hrelu2u(u32 a) {
    __half2 z = __floats2half2_rn(0.f, 0.f);
    __half2 r = __hmax2(*(__half2*)&a, z);
    return *(u32*)&r;
}

// ---------------- scratch tables (fp16, L2-resident) ----------------
__device__ u64        g_xq [NPTS * CCH / 4];   // xq quads
__device__ ulonglong2 g_xkv[NPTS * 16];        // per row: 16 x {xk quad, xv quad}
__device__ float4     g_p4 [NPTS];             // padded coords

// =====================================================================
// Kernel 1: xq/xk/xv = x @ W^T + b via fp16 tensor-core MMA.
// 256 rows/block, 4 chunks, B-fragments once; x loads software-pipelined
// (next chunk's LDGs issued before this chunk's MMA).
// =====================================================================
__global__ __launch_bounds__(256) void gemm_qkv_mma(
    const float* __restrict__ x, const float* __restrict__ p,
    const float* __restrict__ Wq, const float* __restrict__ bq,
    const float* __restrict__ Wk, const float* __restrict__ bk,
    const float* __restrict__ Wv, const float* __restrict__ bv)
{
    __shared__ __align__(16) __half sx[64][72];
    __shared__ __align__(16) u32 sxq [64][32];   // staging, swizzled
    __shared__ __align__(16) u32 sxkv[64][64];   // staging, swizzled

    const int tid  = threadIdx.x;
    const int warp = tid >> 5;
    const int lane = tid & 31;
    const int row0 = blockIdx.x * 256;

    // p4 table slice (256 rows)
    {
        const float* pr = &p[(row0 + tid) * 3];
        g_p4[row0 + tid] = make_float4(pr[0], pr[1], pr[2], 0.f);
    }

    // ---- B fragments + biases: built once per block ----
    const int n0  = warp * 8;
    const int nn  = n0 + (lane >> 2);
    const int kfr = 2 * (lane & 3);

    const float* Ws[3] = {Wq, Wk, Wv};
    const float* Bs[3] = {bq, bk, bv};
    u32 bf[3][4][2];
    float bsx[3], bsy[3];
    #pragma unroll
    for (int m = 0; m < 3; ++m) {
        #pragma unroll
        for (int ks = 0; ks < 4; ++ks) {
            const float* wr = &Ws[m][nn * 64 + ks * 16 + kfr];
            float2 wa = *(const float2*)&wr[0];
            float2 wb = *(const float2*)&wr[8];
            bf[m][ks][0] = f22h(wa.x, wa.y);
            bf[m][ks][1] = f22h(wb.x, wb.y);
        }
        float2 bb = *(const float2*)&Bs[m][n0 + kfr];
        bsx[m] = bb.x; bsy[m] = bb.y;
    }

    const int pp   = (n0 + kfr) >> 1;   // 0..31
    const int qq   = pp >> 1;           // quad 0..15
    const int half = pp & 1;

    const int lr  = tid & 63;           // load row within chunk
    const int lkb = (tid >> 6) * 16;    // load col base

    // prologue: issue chunk-0 loads
    float4 v0, v1, v2, v3;
    {
        const float* xr = &x[(row0 + lr) * 64 + lkb];
        v0 = *(const float4*)&xr[0];
        v1 = *(const float4*)&xr[4];
        v2 = *(const float4*)&xr[8];
        v3 = *(const float4*)&xr[12];
    }

    for (int ck = 0; ck < 4; ++ck) {
        const int rowc = row0 + ck * 64;

        // store current chunk's x (held in regs) into smem
        {
            uint4 h0 = make_uint4(f22h(v0.x, v0.y), f22h(v0.z, v0.w),
                                  f22h(v1.x, v1.y), f22h(v1.z, v1.w));
            uint4 h1 = make_uint4(f22h(v2.x, v2.y), f22h(v2.z, v2.w),
                                  f22h(v3.x, v3.y), f22h(v3.z, v3.w));
            *(uint4*)&sx[lr][lkb]     = h0;
            *(uint4*)&sx[lr][lkb + 8] = h1;
        }
        __syncthreads();

        // issue NEXT chunk's loads now; latency overlaps the MMA below
        if (ck < 3) {
            const float* xr = &x[(rowc + 64 + lr) * 64 + lkb];
            v0 = *(const float4*)&xr[0];
            v1 = *(const float4*)&xr[4];
            v2 = *(const float4*)&xr[8];
            v3 = *(const float4*)&xr[12];
        }

        #pragma unroll
        for (int rt = 0; rt < 4; ++rt) {
            const int r0 = rt * 16;
            u32 afr[4][4];
            const int arow  = r0 + (lane & 15);
            const int acolb = (lane >> 4) << 3;
            #pragma unroll
            for (int ks = 0; ks < 4; ++ks) {
                u32 ad = smem_u32(&sx[arow][ks * 16 + acolb]);
                asm volatile("ldmatrix.sync.aligned.m8n8.x4.shared.b16 {%0,%1,%2,%3}, [%4];"
                    : "=r"(afr[ks][0]), "=r"(afr[ks][1]), "=r"(afr[ks][2]), "=r"(afr[ks][3])
                    : "r"(ad));
            }
            const int rA = r0 + (lane >> 2);   // local rows 0..63
            const int rB = rA + 8;
            #pragma unroll
            for (int m = 0; m < 3; ++m) {
                float d0 = 0.f, d1 = 0.f, d2 = 0.f, d3 = 0.f;
                #pragma unroll
                for (int ks = 0; ks < 4; ++ks) {
                    asm volatile("mma.sync.aligned.m16n8k16.row.col.f32.f16.f16.f32 "
                        "{%0,%1,%2,%3}, {%4,%5,%6,%7}, {%8,%9}, {%0,%1,%2,%3};"
                        : "+f"(d0), "+f"(d1), "+f"(d2), "+f"(d3)
                        : "r"(afr[ks][0]), "r"(afr[ks][1]), "r"(afr[ks][2]), "r"(afr[ks][3]),
                          "r"(bf[m][ks][0]), "r"(bf[m][ks][1]));
                }
                d0 += bsx[m]; d1 += bsy[m]; d2 += bsx[m]; d3 += bsy[m];
                if (m == 0) {
                    sxq[rA][pp ^ ((rA & 7) << 2)] = f22h(d0, d1);
                    sxq[rB][pp ^ ((rB & 7) << 2)] = f22h(d2, d3);
                } else {
                    const int col = qq * 4 + ((m == 1) ? 0 : 2) + half;
                    sxkv[rA][col ^ ((rA & 7) << 2)] = f22h(d0, d1);
                    sxkv[rB][col ^ ((rB & 7) << 2)] = f22h(d2, d3);
                }
            }
        }
        __syncthreads();

        // coalesced writes: xq (512 uint4), xkv (1024 uint4)
        {
            u32* oq = (u32*)g_xq;
            #pragma unroll
            for (int e = 0; e < 2; ++e) {
                int idx4 = tid + e * 256;
                int r = idx4 >> 3;
                int i = idx4 & 7;
                int colb = (i * 4) ^ ((r & 7) << 2);
                uint4 v = *(uint4*)&sxq[r][colb];
                *(uint4*)&oq[(rowc + r) * 32 + i * 4] = v;
            }
            u32* okv = (u32*)g_xkv;
            #pragma unroll
            for (int e = 0; e < 4; ++e) {
                int idx4 = tid + e * 256;
                int r = idx4 >> 4;
                int i = idx4 & 15;
                int colb = (i * 4) ^ ((r & 7) << 2);
                uint4 v = *(uint4*)&sxkv[r][colb];
                *(uint4*)&okv[(rowc + r) * 64 + i * 4] = v;
            }
        }
    }
}

// =====================================================================
// Kernel 2: fused point-transformer. Phase A refolded:
// w = relu(a1*(xk+pe) + (b1 - a1*xq)), nb1 hoisted per point.
// =====================================================================
__global__ void __launch_bounds__(128, 8) fused_pt(
    const int*   __restrict__ idx,
    const float* __restrict__ Wp1, const float* __restrict__ bp1,
    const float* __restrict__ pg,  const float* __restrict__ pb,
    const float* __restrict__ pm,  const float* __restrict__ pv,
    const float* __restrict__ Wp2, const float* __restrict__ bp2,
    const float* __restrict__ wg1, const float* __restrict__ wb1,
    const float* __restrict__ wm1, const float* __restrict__ wv1,
    const float* __restrict__ Ww1, const float* __restrict__ bw1,
    const float* __restrict__ wg2, const float* __restrict__ wb2,
    const float* __restrict__ wm2, const float* __restrict__ wv2,
    const float* __restrict__ Ww2, const float* __restrict__ bw2,
    float* __restrict__ out)
{
    __shared__ float  sWp1[9], sbp1v[3], spa[3], spbv[3];
    __shared__ __align__(16) uint4   sBc[32][5];   // per-lane Phase B constants
    __shared__ __align__(16) __half  ssw16 [NBW][16][72];
    __shared__ __align__(16) __half  svpe16[NBW][16][64];
    __shared__ __align__(16) uint4   stvh  [NBW][16];
    __shared__ __align__(16) float   swl   [NBW][16][8];

    const int tid = threadIdx.x;
    if (tid < 9) sWp1[tid] = Wp1[tid];
    if (tid < 3) {
        sbp1v[tid] = bp1[tid];
        float a = pg[tid] * rsqrtf(pv[tid] + EPSV);
        spa[tid] = a; spbv[tid] = pb[tid] - pm[tid] * a;
    }
    if (tid < 32) {
        const int nfr = tid >> 2;
        const int kfr = 2 * (tid & 3);
        u32 bfB[8];
        #pragma unroll
        for (int ch = 0; ch < 4; ++ch) {
            const float* wr = &Ww1[nfr * 64 + ch * 16 + kfr];
            float2 wa = *(const float2*)&wr[0];
            float2 wb = *(const float2*)&wr[8];
            bfB[2 * ch]     = f22h(wa.x, wa.y);
            bfB[2 * ch + 1] = f22h(wb.x, wb.y);
        }
        float2 w2p  = *(const float2*)&Ww2[nfr * 8 + kfr];
        float2 bw1p = *(const float2*)&bw1[kfr];
        float2 g2p  = *(const float2*)&wg2[kfr];
        float2 v2p  = *(const float2*)&wv2[kfr];
        float2 b2p  = *(const float2*)&wb2[kfr];
        float2 m2p  = *(const float2*)&wm2[kfr];
        float2 bb2p = *(const float2*)&bw2[kfr];
        float tA = g2p.x * rsqrtf(v2p.x + EPSV);
        float tB = g2p.y * rsqrtf(v2p.y + EPSV);
        sBc[tid][0] = make_uint4(bfB[0], bfB[1], bfB[2], bfB[3]);
        sBc[tid][1] = make_uint4(bfB[4], bfB[5], bfB[6], bfB[7]);
        sBc[tid][2] = make_uint4(f22h(w2p.x, w2p.y),
                                 __float_as_uint(bw1p.x),
                                 __float_as_uint(bw1p.y),
                                 __float_as_uint(tA));
        sBc[tid][3] = make_uint4(__float_as_uint(tB),
                                 __float_as_uint(b2p.x - m2p.x * tA),
                                 __float_as_uint(b2p.y - m2p.y * tB),
                                 __float_as_uint(bb2p.x));
        sBc[tid][4] = make_uint4(__float_as_uint(bb2p.y), 0u, 0u, 0u);
    }
    __syncthreads();

    const int w    = tid >> 5;
    const int lane = tid & 31;
    const int q    = lane & 15;
    const int sub  = lane >> 4;
    const int c0   = 4 * q;

    float4 wpr0 = *(const float4*)&Wp2[c0 * 3];
    float4 wpr1 = *(const float4*)&Wp2[c0 * 3 + 4];
    float4 wpr2 = *(const float4*)&Wp2[c0 * 3 + 8];
    const u32 wpA0 = f22h(wpr0.x, wpr0.w);
    const u32 wpA1 = f22h(wpr0.y, wpr1.x);
    const u32 wpA2 = f22h(wpr0.z, wpr1.y);
    const u32 wpB0 = f22h(wpr1.z, wpr2.y);
    const u32 wpB1 = f22h(wpr1.w, wpr2.z);
    const u32 wpB2 = f22h(wpr2.x, wpr2.w);
    float4 bpv = *(const float4*)&bp2[c0];
    const u32 bpA = f22h(bpv.x, bpv.y), bpB = f22h(bpv.z, bpv.w);
    float4 g1 = *(const float4*)&wg1[c0];
    float4 b1 = *(const float4*)&wb1[c0];
    float4 m1 = *(const float4*)&wm1[c0];
    float4 v1 = *(const float4*)&wv1[c0];
    float a0f = g1.x * rsqrtf(v1.x + EPSV);
    float a1f = g1.y * rsqrtf(v1.y + EPSV);
    float a2f = g1.z * rsqrtf(v1.z + EPSV);
    float a3f = g1.w * rsqrtf(v1.w + EPSV);
    const u32 a1A = f22h(a0f, a1f), a1B = f22h(a2f, a3f);
    const u32 b1A = f22h(b1.x - m1.x * a0f, b1.y - m1.y * a1f);
    const u32 b1B = f22h(b1.z - m1.z * a2f, b1.w - m1.w * a3f);
    const u32 na1A = a1A ^ 0x80008000u;   // -a1 (half2 sign flip)
    const u32 na1B = a1B ^ 0x80008000u;

    const int nfr = lane >> 2;
    const int kfr = 2 * (lane & 3);
    const int nbase = blockIdx.x * (NBW * PPW) + w * PPW;

    for (int pt = 0; pt < PPW; ++pt) {
        const int n = nbase + pt;

        if (lane < 16) {
            int j = idx[n * 16 + lane];
            float4 pn = g_p4[n];
            float4 pj = g_p4[j];
            float prx = pj.x - pn.x;
            float pry = pj.y - pn.y;
            float prz = pj.z - pn.z;
            float u0 = prx * sWp1[0] + pry * sWp1[1] + prz * sWp1[2] + sbp1v[0];
            float u1 = prx * sWp1[3] + pry * sWp1[4] + prz * sWp1[5] + sbp1v[1];
            float u2 = prx * sWp1[6] + pry * sWp1[7] + prz * sWp1[8] + sbp1v[2];
            float t0 = fmaxf(0.f, fmaf(u0, spa[0], spbv[0]));
            float t1 = fmaxf(0.f, fmaf(u1, spa[1], spbv[1]));
            float t2 = fmaxf(0.f, fmaf(u2, spa[2], spbv[2]));
            stvh[w][lane] = make_uint4(f22h(t0, t0), f22h(t1, t1), f22h(t2, t2), (u32)j);
        }
        __syncwarp();

        {
            u64 xqq = g_xq[n * 16 + q];
            const u32 xqA = (u32)xqq, xqB = (u32)(xqq >> 32);
            // nb1 = b1 - a1*xq (per point)
            const u32 nb1A = hfma2u(xqA, na1A, b1A);
            const u32 nb1B = hfma2u(xqB, na1B, b1B);

            #pragma unroll
            for (int hb = 0; hb < 2; ++hb) {
                uint4 tv[4];
                ulonglong2 kv[4];
                #pragma unroll
                for (int i = 0; i < 4; ++i) {
                    const int kk = 8 * hb + 2 * i + sub;
                    tv[i] = stvh[w][kk];
                    kv[i] = g_xkv[(int)tv[i].w * 16 + q];
                }
                #pragma unroll
                for (int i = 0; i < 4; ++i) {
                    const int kk = 8 * hb + 2 * i + sub;
                    u32 kA = (u32)kv[i].x, kB = (u32)(kv[i].x >> 32);
                    u32 vA = (u32)kv[i].y, vB = (u32)(kv[i].y >> 32);
                    u32 peA = hfma2u(wpA0, tv[i].x, hfma2u(wpA1, tv[i].y, hfma2u(wpA2, tv[i].z, bpA)));
                    u32 peB = hfma2u(wpB0, tv[i].x, hfma2u(wpB1, tv[i].y, hfma2u(wpB2, tv[i].z, bpB)));
                    u32 sA2 = hadd2u(kA, peA);             // xk + pe
                    u32 sB2 = hadd2u(kB, peB);
                    u32 wA  = hrelu2u(hfma2u(sA2, a1A, nb1A));
                    u32 wB  = hrelu2u(hfma2u(sB2, a1B, nb1B));
                    *(u64*)&ssw16[w][kk][c0]  = (u64)wA | ((u64)wB << 32);
                    u32 vpA = hadd2u(vA, peA);
                    u32 vpB = hadd2u(vB, peB);
                    *(u64*)&svpe16[w][kk][c0] = (u64)vpA | ((u64)vpB << 32);
                }
            }
        }
        __syncwarp();

        {
            uint4 cb0 = sBc[lane][0];
            uint4 cb1 = sBc[lane][1];
            uint4 cb2 = sBc[lane][2];
            uint4 cb3 = sBc[lane][3];
            uint4 cb4 = sBc[lane][4];
            const u32 bW2f = cb2.x;
            const float cbw1A = __uint_as_float(cb2.y);
            const float cbw1B = __uint_as_float(cb2.z);
            const float ca2A  = __uint_as_float(cb2.w);
            const float ca2B  = __uint_as_float(cb3.x);
            const float cb2A  = __uint_as_float(cb3.y);
            const float cb2B  = __uint_as_float(cb3.z);
            const float cbw2A = __uint_as_float(cb3.w);
            const float cbw2B = __uint_as_float(cb4.x);

            u32 afr[4][4];
            const int arow = lane & 15;
            const int acol = (lane >> 4) << 3;
            #pragma unroll
            for (int ch = 0; ch < 4; ++ch) {
                u32 ad = smem_u32(&ssw16[w][arow][ch * 16 + acol]);
                asm volatile("ldmatrix.sync.aligned.m8n8.x4.shared.b16 {%0,%1,%2,%3}, [%4];"
                    : "=r"(afr[ch][0]), "=r"(afr[ch][1]), "=r"(afr[ch][2]), "=r"(afr[ch][3])
                    : "r"(ad));
            }
            float d0 = 0.f, d1 = 0.f, d2 = 0.f, d3 = 0.f;
            asm volatile("mma.sync.aligned.m16n8k16.row.col.f32.f16.f16.f32 "
                "{%0,%1,%2,%3}, {%4,%5,%6,%7}, {%8,%9}, {%0,%1,%2,%3};"
                : "+f"(d0), "+f"(d1), "+f"(d2), "+f"(d3)
                : "r"(afr[0][0]), "r"(afr[0][1]), "r"(afr[0][2]), "r"(afr[0][3]),
                  "r"(cb0.x), "r"(cb0.y));
            asm volatile("mma.sync.aligned.m16n8k16.row.col.f32.f16.f16.f32 "
                "{%0,%1,%2,%3}, {%4,%5,%6,%7}, {%8,%9}, {%0,%1,%2,%3};"
                : "+f"(d0), "+f"(d1), "+f"(d2), "+f"(d3)
                : "r"(afr[1][0]), "r"(afr[1][1]), "r"(afr[1][2]), "r"(afr[1][3]),
                  "r"(cb0.z), "r"(cb0.w));
            asm volatile("mma.sync.aligned.m16n8k16.row.col.f32.f16.f16.f32 "
                "{%0,%1,%2,%3}, {%4,%5,%6,%7}, {%8,%9}, {%0,%1,%2,%3};"
                : "+f"(d0), "+f"(d1), "+f"(d2), "+f"(d3)
                : "r"(afr[2][0]), "r"(afr[2][1]), "r"(afr[2][2]), "r"(afr[2][3]),
                  "r"(cb1.x), "r"(cb1.y));
            asm volatile("mma.sync.aligned.m16n8k16.row.col.f32.f16.f16.f32 "
                "{%0,%1,%2,%3}, {%4,%5,%6,%7}, {%8,%9}, {%0,%1,%2,%3};"
                : "+f"(d0), "+f"(d1), "+f"(d2), "+f"(d3)
                : "r"(afr[3][0]), "r"(afr[3][1]), "r"(afr[3][2]), "r"(afr[3][3]),
                  "r"(cb1.z), "r"(cb1.w));

            float h0 = fmaxf(0.f, fmaf(d0 + cbw1A, ca2A, cb2A));
            float h1 = fmaxf(0.f, fmaf(d1 + cbw1B, ca2B, cb2B));
            float h2 = fmaxf(0.f, fmaf(d2 + cbw1A, ca2A, cb2A));
            float h3 = fmaxf(0.f, fmaf(d3 + cbw1B, ca2B, cb2B));
            u32 ha0 = f22h(h0, h1), ha1 = f22h(h2, h3);
            float l0 = 0.f, l1 = 0.f, l2 = 0.f, l3 = 0.f;
            asm volatile("mma.sync.aligned.m16n8k8.row.col.f32.f16.f16.f32 "
                "{%0,%1,%2,%3}, {%4,%5}, {%6}, {%0,%1,%2,%3};"
                : "+f"(l0), "+f"(l1), "+f"(l2), "+f"(l3)
                : "r"(ha0), "r"(ha1), "r"(bW2f));
            l0 += cbw2A; l1 += cbw2B; l2 += cbw2A; l3 += cbw2B;

            float mA = fmaxf(l0, l2), mB = fmaxf(l1, l3);
            #pragma unroll
            for (int dlt = 4; dlt <= 16; dlt <<= 1) {
                mA = fmaxf(mA, __shfl_xor_sync(0xffffffffu, mA, dlt));
                mB = fmaxf(mB, __shfl_xor_sync(0xffffffffu, mB, dlt));
            }
            float e0 = __expf(l0 - mA), e1 = __expf(l1 - mB);
            float e2 = __expf(l2 - mA), e3 = __expf(l3 - mB);
            float sA = e0 + e2, sB = e1 + e3;
            #pragma unroll
            for (int dlt = 4; dlt <= 16; dlt <<= 1) {
                sA += __shfl_xor_sync(0xffffffffu, sA, dlt);
                sB += __shfl_xor_sync(0xffffffffu, sB, dlt);
            }
            float iA = 1.f / sA, iB = 1.f / sB;
            *(u64*)&swl[w][nfr][kfr]     = pk2(e0 * iA, e1 * iB);
            *(u64*)&swl[w][nfr + 8][kfr] = pk2(e2 * iA, e3 * iB);
        }
        __syncwarp();

        {
            const int csq = c0 & 7;

            u64 acc0 = 0ull, acc1 = 0ull;
            #pragma unroll
            for (int it = 0; it < 8; ++it) {
                const int kk = 2 * it + sub;
                u64 vq = *(const u64*)&svpe16[w][kk][c0];
                u64 vA, vB; h4_to_f22(vq, vA, vB);
                ulonglong2 g2 = *(const ulonglong2*)&swl[w][kk][csq];
                acc0 = ffma2(vA, g2.x, acc0);
                acc1 = ffma2(vB, g2.y, acc1);
            }
            float o0, o1, o2, o3;
            upk2(acc0, o0, o1); upk2(acc1, o2, o3);
            o0 += __shfl_xor_sync(0xffffffffu, o0, 16);
            o1 += __shfl_xor_sync(0xffffffffu, o1, 16);
            o2 += __shfl_xor_sync(0xffffffffu, o2, 16);
            o3 += __shfl_xor_sync(0xffffffffu, o3, 16);
            if (sub == 0)
                *(float4*)&out[n * 64 + c0] = make_float4(o0, o1, o2, o3);
        }
        __syncwarp();
    }
}

// =====================================================================
extern "C" void kernel_launch(void* const* d_in, const int* in_sizes, int n_in,
                              void* d_out, int out_size)
{
    const float* p   = (const float*)d_in[0];
    const float* x   = (const float*)d_in[1];
    const int*   idx = (const int*)  d_in[2];
    const float* Wq  = (const float*)d_in[3];
    const float* bq  = (const float*)d_in[4];
    const float* Wk  = (const float*)d_in[5];
    const float* bk  = (const float*)d_in[6];
    const float* Wv  = (const float*)d_in[7];
    const float* bv  = (const float*)d_in[8];
    const float* Wp1 = (const float*)d_in[9];
    const float* bp1 = (const float*)d_in[10];
    const float* pg  = (const float*)d_in[11];
    const float* pb  = (const float*)d_in[12];
    const float* pm  = (const float*)d_in[13];
    const float* pv  = (const float*)d_in[14];
    const float* Wp2 = (const float*)d_in[15];
    const float* bp2 = (const float*)d_in[16];
    const float* wg1 = (const float*)d_in[17];
    const float* wb1 = (const float*)d_in[18];
    const float* wm1 = (const float*)d_in[19];
    const float* wv1 = (const float*)d_in[20];
    const float* Ww1 = (const float*)d_in[21];
    const float* bw1 = (const float*)d_in[22];
    const float* wg2 = (const float*)d_in[23];
    const float* wb2 = (const float*)d_in[24];
    const float* wm2 = (const float*)d_in[25];
    const float* wv2 = (const float*)d_in[26];
    const float* Ww2 = (const float*)d_in[27];
    const float* bw2 = (const float*)d_in[28];
    float* out = (float*)d_out;

    gemm_qkv_mma<<<NPTS / 256, 256>>>(x, p, Wq, bq, Wk, bk, Wv, bv);
    fused_pt<<<NPTS / (NBW * PPW), 128>>>(idx, Wp1, bp1, pg, pb, pm, pv, Wp2, bp2,
                                          wg1, wb1, wm1, wv1, Ww1, bw1,
                                          wg2, wb2, wm2, wv2, Ww2, bw2, out);
}